// round 2
// baseline (speedup 1.0000x reference)
#include <cuda_runtime.h>
#include <math.h>

// Problem constants
#define T_TOK 2048
#define H_DIM 1024
#define E_NUM 32
#define I_DIM 256
#define O_DIM 512
#define TOPK  4
#define CAP   2048          // worst-case rows per expert
#define TOT_ROWS (T_TOK*TOPK)   // 8192 total (token,slot) rows

// GEMM tiling
#define BM 64
#define BN 64
#define BK 16

// ---------------- scratch (static device globals; no allocation) -------------
__device__ int   g_cnt[E_NUM];
__device__ int   g_off[E_NUM];
__device__ int   g_bucket[E_NUM * CAP];       // token id per (expert,row)
__device__ int   g_slot_e[T_TOK * TOPK];
__device__ int   g_slot_r[T_TOK * TOPK];      // local row within expert bucket
__device__ float g_slot_w[T_TOK * TOPK];
__device__ float g_H[TOT_ROWS * I_DIM];       // 8 MB  (silu(xWg)*xWu)
__device__ float g_Y[TOT_ROWS * O_DIM];       // 16 MB (h Wd)
__device__ float g_pre[T_TOK * H_DIM];        // 8 MB  (combined, pre-Wc)
__device__ float g_logits_scratch[T_TOK * E_NUM];

// ---------------- init -------------------------------------------------------
__global__ void init_kernel() {
    if (threadIdx.x < E_NUM) g_cnt[threadIdx.x] = 0;
}

// ---------------- K1: router logits = X @ Wr  [2048,1024]x[1024,32] ----------
__global__ __launch_bounds__(256) void router_gemm(const float* __restrict__ X,
                                                   const float* __restrict__ Wr,
                                                   float* __restrict__ logits) {
    __shared__ float xs[8][H_DIM];
    int t0 = blockIdx.x * 8;
    for (int i = threadIdx.x; i < 8 * H_DIM; i += 256)
        xs[i >> 10][i & 1023] = X[(size_t)t0 * H_DIM + i];
    __syncthreads();
    int tl = threadIdx.x >> 5;      // token lane (warp = one token)
    int e  = threadIdx.x & 31;      // expert
    const float* xr = xs[tl];
    float acc = 0.f;
#pragma unroll 8
    for (int k = 0; k < H_DIM; k++)
        acc += xr[k] * Wr[k * E_NUM + e];
    logits[(t0 + tl) * E_NUM + e] = acc;
}

// ---------------- K2: routing per token --------------------------------------
__global__ void route_kernel(const float* __restrict__ logits) {
    int t = blockIdx.x * blockDim.x + threadIdx.x;
    if (t >= T_TOK) return;

    float s[E_NUM];
#pragma unroll
    for (int e = 0; e < E_NUM; e++) s[e] = logits[t * E_NUM + e];

    // per-shard (4 shards of 8 experts): sum + top2 (first-max tie semantics)
    float ssum[4]; int top1[4], top2[4]; float v1a[4], v2a[4];
#pragma unroll
    for (int sh = 0; sh < 4; sh++) {
        float sum = 0.f;
#pragma unroll
        for (int j = 0; j < 8; j++) sum += s[sh * 8 + j];
        ssum[sh] = sum;
        int i1 = 0; float v1 = s[sh * 8];
#pragma unroll
        for (int j = 1; j < 8; j++) {
            float v = s[sh * 8 + j];
            if (v > v1) { v1 = v; i1 = j; }
        }
        int i2 = -1; float v2 = -1e30f;
#pragma unroll
        for (int j = 0; j < 8; j++) {
            if (j == i1) continue;
            float v = s[sh * 8 + j];
            if (v > v2) { v2 = v; i2 = j; }
        }
        top1[sh] = i1; top2[sh] = i2; v1a[sh] = v1; v2a[sh] = v2;
    }
    // group 0: shards {0,1}; group 1: shards {2,3}; argmax keeps first max
    int ch0 = (ssum[1] > ssum[0]) ? 1 : 0;
    int ch1 = (ssum[3] > ssum[2]) ? 3 : 2;

    int ce[4]; float cv[4];
    ce[0] = ch0 * 8 + top1[ch0]; cv[0] = v1a[ch0];
    ce[1] = ch0 * 8 + top2[ch0]; cv[1] = v2a[ch0];
    ce[2] = ch1 * 8 + top1[ch1]; cv[2] = v1a[ch1];
    ce[3] = ch1 * 8 + top2[ch1]; cv[3] = v2a[ch1];

    // softmax over the 4 selected scores (order-invariant)
    float m = cv[0];
#pragma unroll
    for (int k = 1; k < 4; k++) m = fmaxf(m, cv[k]);
    float w[4]; float wsum = 0.f;
#pragma unroll
    for (int k = 0; k < 4; k++) { w[k] = expf(cv[k] - m); wsum += w[k]; }
    float inv = 1.f / wsum;
#pragma unroll
    for (int k = 0; k < 4; k++) {
        int e = ce[k];
        int r = atomicAdd(&g_cnt[e], 1);
        g_bucket[e * CAP + r] = t;
        g_slot_e[t * TOPK + k] = e;
        g_slot_r[t * TOPK + k] = r;
        g_slot_w[t * TOPK + k] = w[k] * inv;
    }
}

// ---------------- K2b: exclusive prefix over expert counts -------------------
__global__ void prefix_kernel() {
    if (threadIdx.x == 0) {
        int o = 0;
        for (int e = 0; e < E_NUM; e++) { g_off[e] = o; o += g_cnt[e]; }
    }
}

// ---------------- K3: grouped GEMM1 (gate+up, fused silu) --------------------
// H[base+r, i] = silu(x_r . Wg[e,:,i]) * (x_r . Wu[e,:,i])
__global__ __launch_bounds__(256) void expert_mlp1(const float* __restrict__ X,
                                                   const float* __restrict__ Wg,
                                                   const float* __restrict__ Wu) {
    int e    = blockIdx.z;
    int rows = g_cnt[e];
    int row0 = blockIdx.y * BM;
    if (row0 >= rows) return;
    int base = g_off[e];
    int i0   = blockIdx.x * BN;

    __shared__ float Xs[BK][BM];
    __shared__ float Gs[BK][BN];
    __shared__ float Us[BK][BN];
    __shared__ int   toks[BM];

    int tid = threadIdx.x;
    for (int r = tid; r < BM; r += 256) {
        int rr = row0 + r;
        toks[r] = g_bucket[e * CAP + (rr < rows ? rr : row0)];
    }
    __syncthreads();

    float acg[4][4] = {}, acu[4][4] = {};
    int lr = tid >> 4;     // 0..15 -> rows lr*4..+3
    int lc = tid & 15;     // 0..15 -> cols lc*4..+3
    int xr = tid >> 2;     // 0..63 row loader
    int xq = tid & 3;      // k quad
    int wk = tid >> 4;     // 0..15 k loader
    int wq = tid & 15;     // col quad

    const float* WgE = Wg + (size_t)e * H_DIM * I_DIM;
    const float* WuE = Wu + (size_t)e * H_DIM * I_DIM;

    for (int k0 = 0; k0 < H_DIM; k0 += BK) {
        float4 xv = *(const float4*)(X + (size_t)toks[xr] * H_DIM + k0 + xq * 4);
        float4 gv = *(const float4*)(WgE + (size_t)(k0 + wk) * I_DIM + i0 + wq * 4);
        float4 uv = *(const float4*)(WuE + (size_t)(k0 + wk) * I_DIM + i0 + wq * 4);
        __syncthreads();
        Xs[xq * 4 + 0][xr] = xv.x; Xs[xq * 4 + 1][xr] = xv.y;
        Xs[xq * 4 + 2][xr] = xv.z; Xs[xq * 4 + 3][xr] = xv.w;
        *(float4*)&Gs[wk][wq * 4] = gv;
        *(float4*)&Us[wk][wq * 4] = uv;
        __syncthreads();
#pragma unroll
        for (int kk = 0; kk < BK; kk++) {
            float4 a4 = *(const float4*)&Xs[kk][lr * 4];
            float4 g4 = *(const float4*)&Gs[kk][lc * 4];
            float4 u4 = *(const float4*)&Us[kk][lc * 4];
            float av[4] = {a4.x, a4.y, a4.z, a4.w};
            float gvv[4] = {g4.x, g4.y, g4.z, g4.w};
            float uvv[4] = {u4.x, u4.y, u4.z, u4.w};
#pragma unroll
            for (int i = 0; i < 4; i++)
#pragma unroll
                for (int j = 0; j < 4; j++) {
                    acg[i][j] += av[i] * gvv[j];
                    acu[i][j] += av[i] * uvv[j];
                }
        }
    }
#pragma unroll
    for (int i = 0; i < 4; i++) {
        int rr = row0 + lr * 4 + i;
        if (rr < rows) {
            float4 hv;
            float g0 = acg[i][0], g1 = acg[i][1], g2 = acg[i][2], g3 = acg[i][3];
            hv.x = (g0 / (1.f + expf(-g0))) * acu[i][0];
            hv.y = (g1 / (1.f + expf(-g1))) * acu[i][1];
            hv.z = (g2 / (1.f + expf(-g2))) * acu[i][2];
            hv.w = (g3 / (1.f + expf(-g3))) * acu[i][3];
            *(float4*)(g_H + (size_t)(base + rr) * I_DIM + i0 + lc * 4) = hv;
        }
    }
}

// ---------------- K4: grouped GEMM2 (down proj) ------------------------------
// Y[base+r, o] = H[base+r,:] . Wd[e,:,o]
__global__ __launch_bounds__(256) void expert_mlp2(const float* __restrict__ Wd) {
    int e    = blockIdx.z;
    int rows = g_cnt[e];
    int row0 = blockIdx.y * BM;
    if (row0 >= rows) return;
    int base = g_off[e];
    int o0   = blockIdx.x * BN;

    __shared__ float As[BK][BM];
    __shared__ float Bs[BK][BN];

    int tid = threadIdx.x;
    float acc[4][4] = {};
    int lr = tid >> 4, lc = tid & 15;
    int xr = tid >> 2, xq = tid & 3;
    int wk = tid >> 4, wq = tid & 15;

    const float* WdE = Wd + (size_t)e * I_DIM * O_DIM;
    int rload = row0 + xr; if (rload >= rows) rload = rows - 1;

    for (int k0 = 0; k0 < I_DIM; k0 += BK) {
        float4 av = *(const float4*)(g_H + (size_t)(base + rload) * I_DIM + k0 + xq * 4);
        float4 bv = *(const float4*)(WdE + (size_t)(k0 + wk) * O_DIM + o0 + wq * 4);
        __syncthreads();
        As[xq * 4 + 0][xr] = av.x; As[xq * 4 + 1][xr] = av.y;
        As[xq * 4 + 2][xr] = av.z; As[xq * 4 + 3][xr] = av.w;
        *(float4*)&Bs[wk][wq * 4] = bv;
        __syncthreads();
#pragma unroll
        for (int kk = 0; kk < BK; kk++) {
            float4 a4 = *(const float4*)&As[kk][lr * 4];
            float4 b4 = *(const float4*)&Bs[kk][lc * 4];
            float avr[4] = {a4.x, a4.y, a4.z, a4.w};
            float bvr[4] = {b4.x, b4.y, b4.z, b4.w};
#pragma unroll
            for (int i = 0; i < 4; i++)
#pragma unroll
                for (int j = 0; j < 4; j++) acc[i][j] += avr[i] * bvr[j];
        }
    }
#pragma unroll
    for (int i = 0; i < 4; i++) {
        int rr = row0 + lr * 4 + i;
        if (rr < rows) {
            float4 yv = {acc[i][0], acc[i][1], acc[i][2], acc[i][3]};
            *(float4*)(g_Y + (size_t)(base + rr) * O_DIM + o0 + lc * 4) = yv;
        }
    }
}

// ---------------- K5: combine (gather, deterministic) ------------------------
__global__ void combine_kernel() {
    int t = blockIdx.x;
    __shared__ int   se[TOPK];
    __shared__ int   sr[TOPK];
    __shared__ float sw[TOPK];
    if (threadIdx.x < TOPK) {
        int e = g_slot_e[t * TOPK + threadIdx.x];
        se[threadIdx.x] = e;
        sr[threadIdx.x] = g_off[e] + g_slot_r[t * TOPK + threadIdx.x];
        sw[threadIdx.x] = g_slot_w[t * TOPK + threadIdx.x];
    }
    __syncthreads();
    for (int c = threadIdx.x; c < H_DIM; c += blockDim.x) {
        int g = c >> 9;        // output group (O_DIM = 512)
        int o = c & 511;
        float acc = 0.f;
#pragma unroll
        for (int s = 0; s < TOPK; s++)
            if ((se[s] >> 4) == g)
                acc += sw[s] * g_Y[(size_t)sr[s] * O_DIM + o];
        g_pre[(size_t)t * H_DIM + c] = acc;
    }
}

// ---------------- K6: final GEMM out = pre @ Wc ------------------------------
__global__ __launch_bounds__(256) void final_gemm(const float* __restrict__ Wc,
                                                  float* __restrict__ out) {
    int row0 = blockIdx.y * BM;
    int j0   = blockIdx.x * BN;

    __shared__ float As[BK][BM];
    __shared__ float Bs[BK][BN];

    int tid = threadIdx.x;
    float acc[4][4] = {};
    int lr = tid >> 4, lc = tid & 15;
    int xr = tid >> 2, xq = tid & 3;
    int wk = tid >> 4, wq = tid & 15;

    for (int k0 = 0; k0 < H_DIM; k0 += BK) {
        float4 av = *(const float4*)(g_pre + (size_t)(row0 + xr) * H_DIM + k0 + xq * 4);
        float4 bv = *(const float4*)(Wc + (size_t)(k0 + wk) * H_DIM + j0 + wq * 4);
        __syncthreads();
        As[xq * 4 + 0][xr] = av.x; As[xq * 4 + 1][xr] = av.y;
        As[xq * 4 + 2][xr] = av.z; As[xq * 4 + 3][xr] = av.w;
        *(float4*)&Bs[wk][wq * 4] = bv;
        __syncthreads();
#pragma unroll
        for (int kk = 0; kk < BK; kk++) {
            float4 a4 = *(const float4*)&As[kk][lr * 4];
            float4 b4 = *(const float4*)&Bs[kk][lc * 4];
            float avr[4] = {a4.x, a4.y, a4.z, a4.w};
            float bvr[4] = {b4.x, b4.y, b4.z, b4.w};
#pragma unroll
            for (int i = 0; i < 4; i++)
#pragma unroll
                for (int j = 0; j < 4; j++) acc[i][j] += avr[i] * bvr[j];
        }
    }
#pragma unroll
    for (int i = 0; i < 4; i++) {
        int rr = row0 + lr * 4 + i;
        float4 ov = {acc[i][0], acc[i][1], acc[i][2], acc[i][3]};
        *(float4*)(out + (size_t)rr * H_DIM + j0 + lc * 4) = ov;
    }
}

// ---------------- launch -----------------------------------------------------
extern "C" void kernel_launch(void* const* d_in, const int* in_sizes, int n_in,
                              void* d_out, int out_size) {
    const float* X  = (const float*)d_in[0];
    const float* Wr = (const float*)d_in[1];
    const float* Wg = (const float*)d_in[2];
    const float* Wu = (const float*)d_in[3];
    const float* Wd = (const float*)d_in[4];
    const float* Wc = (const float*)d_in[5];
    float* out = (float*)d_out;

    // outputs concatenated in reference return order: out [T,H], logits [T,E]
    float* logits;
    if (out_size >= T_TOK * H_DIM + T_TOK * E_NUM)
        logits = out + (size_t)T_TOK * H_DIM;
    else {
        // fallback: logits not part of the checked output
        cudaMemcpyToSymbol(g_logits_scratch, &out, 0);  // no-op placeholder
        logits = nullptr;
    }
    float* logit_dst = logits ? logits : nullptr;

    init_kernel<<<1, 32>>>();
    if (logit_dst == nullptr) {
        // use scratch symbol address via a tiny kernel-free path: get pointer
        // (cudaGetSymbolAddress is not an allocation; host-side, capture-safe)
        void* p = nullptr;
        cudaGetSymbolAddress(&p, g_logits_scratch);
        logit_dst = (float*)p;
    }
    router_gemm<<<T_TOK / 8, 256>>>(X, Wr, logit_dst);
    route_kernel<<<T_TOK / 256, 256>>>(logit_dst);
    prefix_kernel<<<1, 32>>>();

    dim3 g1(I_DIM / BN, CAP / BM, E_NUM);   // (4, 32, 32)
    expert_mlp1<<<g1, 256>>>(X, Wg, Wu);

    dim3 g2(O_DIM / BN, CAP / BM, E_NUM);   // (8, 32, 32)
    expert_mlp2<<<g2, 256>>>(Wd);

    combine_kernel<<<T_TOK, 256>>>();

    dim3 g3(H_DIM / BN, T_TOK / BM);        // (16, 32)
    final_gemm<<<g3, 256>>>(Wc, out);
}

// round 5
// speedup vs baseline: 1.1339x; 1.1339x over previous
#include <cuda_runtime.h>
#include <cuda_bf16.h>
#include <math.h>
#include <stdint.h>

// Problem constants
#define T_TOK 2048
#define H_DIM 1024
#define E_NUM 32
#define I_DIM 256
#define O_DIM 512
#define TOPK  4
#define CAP   2048
#define TOT_ROWS (T_TOK*TOPK)   // 8192

// SIMT GEMM tiling (R1, proven)
#define BM 64
#define BN 64
#define BK 16

#define RS 40   // smem row stride (bf16 elems) for mma tiles

// ---------------- scratch (device globals; no allocation) --------------------
__device__ int   g_cnt[E_NUM];
__device__ int   g_off[E_NUM];
__device__ int   g_bucket[E_NUM * CAP];
__device__ int   g_slot_e[T_TOK * TOPK];
__device__ int   g_slot_r[T_TOK * TOPK];
__device__ float g_slot_w[T_TOK * TOPK];
__device__ float g_H[TOT_ROWS * I_DIM];
__device__ float g_Y[TOT_ROWS * O_DIM];
__device__ float g_pre[T_TOK * H_DIM];

__device__ __align__(256) __nv_bfloat16 g_phi[T_TOK * H_DIM];
__device__ __align__(256) __nv_bfloat16 g_plo[T_TOK * H_DIM];
__device__ __align__(256) __nv_bfloat16 g_WcThi[H_DIM * H_DIM];
__device__ __align__(256) __nv_bfloat16 g_WcTlo[H_DIM * H_DIM];

// ---------------- helpers ----------------------------------------------------
__device__ __forceinline__ void split2(float x, __nv_bfloat16& h, __nv_bfloat16& l) {
    h = __float2bfloat16_rn(x);
    l = __float2bfloat16_rn(x - __bfloat162float(h));
}

__device__ __forceinline__ void mma16816(float* c, const uint32_t* a, const uint32_t* b) {
    asm volatile(
        "mma.sync.aligned.m16n8k16.row.col.f32.bf16.bf16.f32 "
        "{%0,%1,%2,%3}, {%4,%5,%6,%7}, {%8,%9}, {%0,%1,%2,%3};"
        : "+f"(c[0]), "+f"(c[1]), "+f"(c[2]), "+f"(c[3])
        : "r"(a[0]), "r"(a[1]), "r"(a[2]), "r"(a[3]), "r"(b[0]), "r"(b[1]));
}

__device__ __forceinline__ void ldfragA(uint32_t* a, const uint16_t* S, int mrow,
                                        int kk, int qr, int qc) {
    const uint16_t* p = S + (mrow + qr) * RS + kk + qc * 2;
    a[0] = *(const uint32_t*)p;
    a[1] = *(const uint32_t*)(p + 8 * RS);
    a[2] = *(const uint32_t*)(p + 8);
    a[3] = *(const uint32_t*)(p + 8 * RS + 8);
}
__device__ __forceinline__ void ldfragB(uint32_t* b, const uint16_t* S, int nrow,
                                        int kk, int qr, int qc) {
    const uint16_t* p = S + (nrow + qr) * RS + kk + qc * 2;
    b[0] = *(const uint32_t*)p;
    b[1] = *(const uint32_t*)(p + 8);
}

// ---------------- init -------------------------------------------------------
__global__ void init_kernel() {
    if (threadIdx.x < E_NUM) g_cnt[threadIdx.x] = 0;
}

// ---------------- K1: router logits (fp32, exact) ----------------------------
__global__ __launch_bounds__(256) void router_gemm(const float* __restrict__ X,
                                                   const float* __restrict__ Wr,
                                                   float* __restrict__ logits) {
    __shared__ float xs[8][H_DIM];
    int t0 = blockIdx.x * 8;
    for (int i = threadIdx.x; i < 8 * H_DIM; i += 256)
        xs[i >> 10][i & 1023] = X[(size_t)t0 * H_DIM + i];
    __syncthreads();
    int tl = threadIdx.x >> 5;
    int e  = threadIdx.x & 31;
    const float* xr = xs[tl];
    float acc = 0.f;
#pragma unroll 8
    for (int k = 0; k < H_DIM; k++)
        acc += xr[k] * Wr[k * E_NUM + e];
    logits[(t0 + tl) * E_NUM + e] = acc;
}

// ---------------- K2: routing ------------------------------------------------
__global__ void route_kernel(const float* __restrict__ logits) {
    int t = blockIdx.x * blockDim.x + threadIdx.x;
    if (t >= T_TOK) return;
    float s[E_NUM];
#pragma unroll
    for (int e = 0; e < E_NUM; e++) s[e] = logits[t * E_NUM + e];
    float ssum[4]; int top1[4], top2[4]; float v1a[4], v2a[4];
#pragma unroll
    for (int sh = 0; sh < 4; sh++) {
        float sum = 0.f;
#pragma unroll
        for (int j = 0; j < 8; j++) sum += s[sh * 8 + j];
        ssum[sh] = sum;
        int i1 = 0; float v1 = s[sh * 8];
#pragma unroll
        for (int j = 1; j < 8; j++) { float v = s[sh * 8 + j]; if (v > v1) { v1 = v; i1 = j; } }
        int i2 = -1; float v2 = -1e30f;
#pragma unroll
        for (int j = 0; j < 8; j++) {
            if (j == i1) continue;
            float v = s[sh * 8 + j];
            if (v > v2) { v2 = v; i2 = j; }
        }
        top1[sh] = i1; top2[sh] = i2; v1a[sh] = v1; v2a[sh] = v2;
    }
    int ch0 = (ssum[1] > ssum[0]) ? 1 : 0;
    int ch1 = (ssum[3] > ssum[2]) ? 3 : 2;
    int ce[4]; float cv[4];
    ce[0] = ch0 * 8 + top1[ch0]; cv[0] = v1a[ch0];
    ce[1] = ch0 * 8 + top2[ch0]; cv[1] = v2a[ch0];
    ce[2] = ch1 * 8 + top1[ch1]; cv[2] = v1a[ch1];
    ce[3] = ch1 * 8 + top2[ch1]; cv[3] = v2a[ch1];
    float m = cv[0];
#pragma unroll
    for (int k = 1; k < 4; k++) m = fmaxf(m, cv[k]);
    float w[4]; float wsum = 0.f;
#pragma unroll
    for (int k = 0; k < 4; k++) { w[k] = expf(cv[k] - m); wsum += w[k]; }
    float inv = 1.f / wsum;
#pragma unroll
    for (int k = 0; k < 4; k++) {
        int e = ce[k];
        int r = atomicAdd(&g_cnt[e], 1);
        g_bucket[e * CAP + r] = t;
        g_slot_e[t * TOPK + k] = e;
        g_slot_r[t * TOPK + k] = r;
        g_slot_w[t * TOPK + k] = w[k] * inv;
    }
}

__global__ void prefix_kernel() {
    if (threadIdx.x == 0) {
        int o = 0;
        for (int e = 0; e < E_NUM; e++) { g_off[e] = o; o += g_cnt[e]; }
    }
}

// ---------------- K3: grouped GEMM1 (fp32 SIMT, proven) ----------------------
__global__ __launch_bounds__(256) void expert_mlp1(const float* __restrict__ X,
                                                   const float* __restrict__ Wg,
                                                   const float* __restrict__ Wu) {
    int e    = blockIdx.z;
    int rows = g_cnt[e];
    int row0 = blockIdx.y * BM;
    if (row0 >= rows) return;
    int base = g_off[e];
    int i0   = blockIdx.x * BN;

    __shared__ float Xs[BK][BM];
    __shared__ float Gs[BK][BN];
    __shared__ float Us[BK][BN];
    __shared__ int   toks[BM];

    int tid = threadIdx.x;
    for (int r = tid; r < BM; r += 256) {
        int rr = row0 + r;
        toks[r] = g_bucket[e * CAP + (rr < rows ? rr : row0)];
    }
    __syncthreads();

    float acg[4][4] = {}, acu[4][4] = {};
    int lr = tid >> 4, lc = tid & 15;
    int xr = tid >> 2, xq = tid & 3;
    int wk = tid >> 4, wq = tid & 15;

    const float* WgE = Wg + (size_t)e * H_DIM * I_DIM;
    const float* WuE = Wu + (size_t)e * H_DIM * I_DIM;

    for (int k0 = 0; k0 < H_DIM; k0 += BK) {
        float4 xv = *(const float4*)(X + (size_t)toks[xr] * H_DIM + k0 + xq * 4);
        float4 gv = *(const float4*)(WgE + (size_t)(k0 + wk) * I_DIM + i0 + wq * 4);
        float4 uv = *(const float4*)(WuE + (size_t)(k0 + wk) * I_DIM + i0 + wq * 4);
        __syncthreads();
        Xs[xq * 4 + 0][xr] = xv.x; Xs[xq * 4 + 1][xr] = xv.y;
        Xs[xq * 4 + 2][xr] = xv.z; Xs[xq * 4 + 3][xr] = xv.w;
        *(float4*)&Gs[wk][wq * 4] = gv;
        *(float4*)&Us[wk][wq * 4] = uv;
        __syncthreads();
#pragma unroll
        for (int kk = 0; kk < BK; kk++) {
            float4 a4 = *(const float4*)&Xs[kk][lr * 4];
            float4 g4 = *(const float4*)&Gs[kk][lc * 4];
            float4 u4 = *(const float4*)&Us[kk][lc * 4];
            float av[4] = {a4.x, a4.y, a4.z, a4.w};
            float gvv[4] = {g4.x, g4.y, g4.z, g4.w};
            float uvv[4] = {u4.x, u4.y, u4.z, u4.w};
#pragma unroll
            for (int i = 0; i < 4; i++)
#pragma unroll
                for (int j = 0; j < 4; j++) {
                    acg[i][j] += av[i] * gvv[j];
                    acu[i][j] += av[i] * uvv[j];
                }
        }
    }
#pragma unroll
    for (int i = 0; i < 4; i++) {
        int rr = row0 + lr * 4 + i;
        if (rr < rows) {
            float4 hv;
            float g0 = acg[i][0], g1 = acg[i][1], g2 = acg[i][2], g3 = acg[i][3];
            hv.x = (g0 / (1.f + expf(-g0))) * acu[i][0];
            hv.y = (g1 / (1.f + expf(-g1))) * acu[i][1];
            hv.z = (g2 / (1.f + expf(-g2))) * acu[i][2];
            hv.w = (g3 / (1.f + expf(-g3))) * acu[i][3];
            *(float4*)(g_H + (size_t)(base + rr) * I_DIM + i0 + lc * 4) = hv;
        }
    }
}

// ---------------- K4: grouped GEMM2 (fp32 SIMT, proven) ----------------------
__global__ __launch_bounds__(256) void expert_mlp2(const float* __restrict__ Wd) {
    int e    = blockIdx.z;
    int rows = g_cnt[e];
    int row0 = blockIdx.y * BM;
    if (row0 >= rows) return;
    int base = g_off[e];
    int o0   = blockIdx.x * BN;

    __shared__ float As[BK][BM];
    __shared__ float Bs[BK][BN];

    int tid = threadIdx.x;
    float acc[4][4] = {};
    int lr = tid >> 4, lc = tid & 15;
    int xr = tid >> 2, xq = tid & 3;
    int wk = tid >> 4, wq = tid & 15;

    const float* WdE = Wd + (size_t)e * I_DIM * O_DIM;
    int rload = row0 + xr; if (rload >= rows) rload = rows - 1;

    for (int k0 = 0; k0 < I_DIM; k0 += BK) {
        float4 av = *(const float4*)(g_H + (size_t)(base + rload) * I_DIM + k0 + xq * 4);
        float4 bv = *(const float4*)(WdE + (size_t)(k0 + wk) * O_DIM + o0 + wq * 4);
        __syncthreads();
        As[xq * 4 + 0][xr] = av.x; As[xq * 4 + 1][xr] = av.y;
        As[xq * 4 + 2][xr] = av.z; As[xq * 4 + 3][xr] = av.w;
        *(float4*)&Bs[wk][wq * 4] = bv;
        __syncthreads();
#pragma unroll
        for (int kk = 0; kk < BK; kk++) {
            float4 a4 = *(const float4*)&As[kk][lr * 4];
            float4 b4 = *(const float4*)&Bs[kk][lc * 4];
            float avr[4] = {a4.x, a4.y, a4.z, a4.w};
            float bvr[4] = {b4.x, b4.y, b4.z, b4.w};
#pragma unroll
            for (int i = 0; i < 4; i++)
#pragma unroll
                for (int j = 0; j < 4; j++) acc[i][j] += avr[i] * bvr[j];
        }
    }
#pragma unroll
    for (int i = 0; i < 4; i++) {
        int rr = row0 + lr * 4 + i;
        if (rr < rows) {
            float4 yv = {acc[i][0], acc[i][1], acc[i][2], acc[i][3]};
            *(float4*)(g_Y + (size_t)(base + rr) * O_DIM + o0 + lc * 4) = yv;
        }
    }
}

// ---------------- K5: combine (proven) ---------------------------------------
__global__ void combine_kernel() {
    int t = blockIdx.x;
    __shared__ int   se[TOPK];
    __shared__ int   sr[TOPK];
    __shared__ float sw[TOPK];
    if (threadIdx.x < TOPK) {
        int e = g_slot_e[t * TOPK + threadIdx.x];
        se[threadIdx.x] = e;
        sr[threadIdx.x] = g_off[e] + g_slot_r[t * TOPK + threadIdx.x];
        sw[threadIdx.x] = g_slot_w[t * TOPK + threadIdx.x];
    }
    __syncthreads();
    for (int c = threadIdx.x; c < H_DIM; c += blockDim.x) {
        int g = c >> 9;
        int o = c & 511;
        float acc = 0.f;
#pragma unroll
        for (int s = 0; s < TOPK; s++)
            if ((se[s] >> 4) == g)
                acc += sw[s] * g_Y[(size_t)sr[s] * O_DIM + o];
        g_pre[(size_t)t * H_DIM + c] = acc;
    }
}

// ---------------- NEW: convert pre -> bf16 hi/lo ------------------------------
__global__ __launch_bounds__(256) void convert_pre() {
    int idx = (blockIdx.x * 256 + threadIdx.x) * 4;
    float4 v = *(const float4*)(g_pre + idx);
    __nv_bfloat16 h0, l0, h1, l1, h2, l2, h3, l3;
    split2(v.x, h0, l0); split2(v.y, h1, l1); split2(v.z, h2, l2); split2(v.w, h3, l3);
    __nv_bfloat162 a, b;
    a.x = h0; a.y = h1; b.x = h2; b.y = h3;
    *(__nv_bfloat162*)(g_phi + idx) = a; *(__nv_bfloat162*)(g_phi + idx + 2) = b;
    a.x = l0; a.y = l1; b.x = l2; b.y = l3;
    *(__nv_bfloat162*)(g_plo + idx) = a; *(__nv_bfloat162*)(g_plo + idx + 2) = b;
}

// ---------------- NEW: Wc transpose+split (dead simple) ----------------------
// WcT[c][r] = Wc[r][c]; coalesced writes.
__global__ __launch_bounds__(256) void transpose_wc(const float* __restrict__ Wc) {
    uint32_t n = blockIdx.x * 256 + threadIdx.x;   // over [H*H)
    uint32_t c = n >> 10;
    uint32_t r = n & 1023;
    float v = Wc[(size_t)r * H_DIM + c];
    __nv_bfloat16 h, l; split2(v, h, l);
    g_WcThi[n] = h; g_WcTlo[n] = l;
}

// ---------------- NEW: GEMM3 via mma.sync (3-term bf16 split) -----------------
__global__ __launch_bounds__(256) void gemm3_kernel(float* __restrict__ out) {
    int row0 = blockIdx.y * 128;
    int j0   = blockIdx.x * 64;

    __shared__ __align__(16) uint16_t Ahi[128 * RS], Alo[128 * RS];
    __shared__ __align__(16) uint16_t Bh[64 * RS], Bl[64 * RS];

    int tid = threadIdx.x;
    int wid = tid >> 5, lane = tid & 31;
    int qr = lane >> 2, qc = lane & 3;
    int wm = wid & 3, wn = wid >> 2;

    const __nv_bfloat16* BHp = g_WcThi + (size_t)j0 * H_DIM;
    const __nv_bfloat16* BLp = g_WcTlo + (size_t)j0 * H_DIM;

    float acc[2][4][4] = {};

    for (int k0 = 0; k0 < H_DIM; k0 += 32) {
#pragma unroll
        for (int u = tid; u < 512; u += 256) {
            int r = u >> 2, sg = u & 3;
            size_t so = (size_t)(row0 + r) * H_DIM + k0 + sg * 8;
            *(int4*)&Ahi[r * RS + sg * 8] = *(const int4*)(g_phi + so);
            *(int4*)&Alo[r * RS + sg * 8] = *(const int4*)(g_plo + so);
        }
        {
            int r = tid >> 2, sg = tid & 3;
            size_t so = (size_t)r * H_DIM + k0 + sg * 8;
            int d = r * RS + sg * 8;
            *(int4*)&Bh[d] = *(const int4*)(BHp + so);
            *(int4*)&Bl[d] = *(const int4*)(BLp + so);
        }
        __syncthreads();

#pragma unroll
        for (int kk = 0; kk < 32; kk += 16) {
            uint32_t ah[2][4], al[2][4];
#pragma unroll
            for (int i = 0; i < 2; i++) {
                ldfragA(ah[i], Ahi, wm * 32 + i * 16, kk, qr, qc);
                ldfragA(al[i], Alo, wm * 32 + i * 16, kk, qr, qc);
            }
            uint32_t bh[4][2], bl[4][2];
#pragma unroll
            for (int j = 0; j < 4; j++) {
                ldfragB(bh[j], Bh, wn * 32 + j * 8, kk, qr, qc);
                ldfragB(bl[j], Bl, wn * 32 + j * 8, kk, qr, qc);
            }
#pragma unroll
            for (int i = 0; i < 2; i++)
#pragma unroll
                for (int j = 0; j < 4; j++) {
                    mma16816(acc[i][j], ah[i], bh[j]);
                    mma16816(acc[i][j], ah[i], bl[j]);
                    mma16816(acc[i][j], al[i], bh[j]);
                }
        }
        __syncthreads();
    }

#pragma unroll
    for (int i = 0; i < 2; i++) {
#pragma unroll
        for (int half = 0; half < 2; half++) {
            int rr = row0 + wm * 32 + i * 16 + qr + half * 8;
            size_t ro = (size_t)rr * H_DIM + j0 + wn * 32;
#pragma unroll
            for (int j = 0; j < 4; j++) {
                float2 v;
                v.x = acc[i][j][half * 2 + 0];
                v.y = acc[i][j][half * 2 + 1];
                *(float2*)(out + ro + j * 8 + qc * 2) = v;
            }
        }
    }
}

// ---------------- launch -----------------------------------------------------
extern "C" void kernel_launch(void* const* d_in, const int* in_sizes, int n_in,
                              void* d_out, int out_size) {
    const float* X  = (const float*)d_in[0];
    const float* Wr = (const float*)d_in[1];
    const float* Wg = (const float*)d_in[2];
    const float* Wu = (const float*)d_in[3];
    const float* Wd = (const float*)d_in[4];
    const float* Wc = (const float*)d_in[5];
    float* out = (float*)d_out;
    float* logits = out + (size_t)T_TOK * H_DIM;

    init_kernel<<<1, 32>>>();
    transpose_wc<<<H_DIM * H_DIM / 256, 256>>>(Wc);

    router_gemm<<<T_TOK / 8, 256>>>(X, Wr, logits);
    route_kernel<<<T_TOK / 256, 256>>>(logits);
    prefix_kernel<<<1, 32>>>();

    dim3 g1(I_DIM / BN, CAP / BM, E_NUM);
    expert_mlp1<<<g1, 256>>>(X, Wg, Wu);

    dim3 g2(O_DIM / BN, CAP / BM, E_NUM);
    expert_mlp2<<<g2, 256>>>(Wd);

    combine_kernel<<<T_TOK, 256>>>();
    convert_pre<<<T_TOK * H_DIM / 1024, 256>>>();

    gemm3_kernel<<<dim3(H_DIM / 64, T_TOK / 128), 256>>>(out);
}

// round 8
// speedup vs baseline: 1.3924x; 1.2279x over previous
#include <cuda_runtime.h>
#include <cuda_bf16.h>
#include <math.h>
#include <stdint.h>

// Problem constants
#define T_TOK 2048
#define H_DIM 1024
#define E_NUM 32
#define I_DIM 256
#define O_DIM 512
#define TOPK  4
#define CAP   2048
#define TOT_ROWS (T_TOK*TOPK)   // 8192

#define RS 40   // smem row stride (bf16 elems) for mma tiles

// ---------------- scratch (device globals; no allocation) --------------------
__device__ int   g_cnt[E_NUM];
__device__ int   g_off[E_NUM];
__device__ int   g_bucket[E_NUM * CAP];
__device__ int   g_slot_e[T_TOK * TOPK];
__device__ int   g_slot_r[T_TOK * TOPK];
__device__ float g_slot_w[T_TOK * TOPK];
__device__ float g_H[TOT_ROWS * I_DIM];
__device__ float g_Y[TOT_ROWS * O_DIM];
__device__ float g_pre[T_TOK * H_DIM];

__device__ __align__(256) __nv_bfloat16 g_phi[T_TOK * H_DIM];
__device__ __align__(256) __nv_bfloat16 g_plo[T_TOK * H_DIM];
__device__ __align__(256) __nv_bfloat16 g_WcThi[H_DIM * H_DIM];
__device__ __align__(256) __nv_bfloat16 g_WcTlo[H_DIM * H_DIM];

// ---------------- helpers ----------------------------------------------------
__device__ __forceinline__ void split2(float x, __nv_bfloat16& h, __nv_bfloat16& l) {
    h = __float2bfloat16_rn(x);
    l = __float2bfloat16_rn(x - __bfloat162float(h));
}

__device__ __forceinline__ void mma16816(float* c, const uint32_t* a, const uint32_t* b) {
    asm volatile(
        "mma.sync.aligned.m16n8k16.row.col.f32.bf16.bf16.f32 "
        "{%0,%1,%2,%3}, {%4,%5,%6,%7}, {%8,%9}, {%0,%1,%2,%3};"
        : "+f"(c[0]), "+f"(c[1]), "+f"(c[2]), "+f"(c[3])
        : "r"(a[0]), "r"(a[1]), "r"(a[2]), "r"(a[3]), "r"(b[0]), "r"(b[1]));
}

__device__ __forceinline__ void ldfragA(uint32_t* a, const uint16_t* S, int mrow,
                                        int kk, int qr, int qc) {
    const uint16_t* p = S + (mrow + qr) * RS + kk + qc * 2;
    a[0] = *(const uint32_t*)p;
    a[1] = *(const uint32_t*)(p + 8 * RS);
    a[2] = *(const uint32_t*)(p + 8);
    a[3] = *(const uint32_t*)(p + 8 * RS + 8);
}
__device__ __forceinline__ void ldfragB(uint32_t* b, const uint16_t* S, int nrow,
                                        int kk, int qr, int qc) {
    const uint16_t* p = S + (nrow + qr) * RS + kk + qc * 2;
    b[0] = *(const uint32_t*)p;
    b[1] = *(const uint32_t*)(p + 8);
}

// split a float4 (4 consecutive k at row r) into Ahi/Alo smem (row-major tiles)
__device__ __forceinline__ void storeA4(uint16_t* Ahi, uint16_t* Alo, int r, int k,
                                        float4 v) {
    __nv_bfloat16 h0, l0, h1, l1, h2, l2, h3, l3;
    split2(v.x, h0, l0); split2(v.y, h1, l1); split2(v.z, h2, l2); split2(v.w, h3, l3);
    ushort4 hh, ll;
    hh.x = *(uint16_t*)&h0; hh.y = *(uint16_t*)&h1; hh.z = *(uint16_t*)&h2; hh.w = *(uint16_t*)&h3;
    ll.x = *(uint16_t*)&l0; ll.y = *(uint16_t*)&l1; ll.z = *(uint16_t*)&l2; ll.w = *(uint16_t*)&l3;
    *(ushort4*)&Ahi[r * RS + k] = hh;
    *(ushort4*)&Alo[r * RS + k] = ll;
}

// split a float4 (4 consecutive n at col k) transposed into Bh/Bl smem [n][k]
__device__ __forceinline__ void storeB4T(uint16_t* Bh, uint16_t* Bl, int n0, int k,
                                         float4 v) {
    __nv_bfloat16 h, l;
    split2(v.x, h, l); Bh[(n0 + 0) * RS + k] = *(uint16_t*)&h; Bl[(n0 + 0) * RS + k] = *(uint16_t*)&l;
    split2(v.y, h, l); Bh[(n0 + 1) * RS + k] = *(uint16_t*)&h; Bl[(n0 + 1) * RS + k] = *(uint16_t*)&l;
    split2(v.z, h, l); Bh[(n0 + 2) * RS + k] = *(uint16_t*)&h; Bl[(n0 + 2) * RS + k] = *(uint16_t*)&l;
    split2(v.w, h, l); Bh[(n0 + 3) * RS + k] = *(uint16_t*)&h; Bl[(n0 + 3) * RS + k] = *(uint16_t*)&l;
}

// ---------------- init -------------------------------------------------------
__global__ void init_kernel() {
    if (threadIdx.x < E_NUM) g_cnt[threadIdx.x] = 0;
}

// ---------------- K1: router logits (fp32, exact) ----------------------------
__global__ __launch_bounds__(256) void router_gemm(const float* __restrict__ X,
                                                   const float* __restrict__ Wr,
                                                   float* __restrict__ logits) {
    __shared__ float xs[8][H_DIM];
    int t0 = blockIdx.x * 8;
    for (int i = threadIdx.x; i < 8 * H_DIM; i += 256)
        xs[i >> 10][i & 1023] = X[(size_t)t0 * H_DIM + i];
    __syncthreads();
    int tl = threadIdx.x >> 5;
    int e  = threadIdx.x & 31;
    const float* xr = xs[tl];
    float acc = 0.f;
#pragma unroll 8
    for (int k = 0; k < H_DIM; k++)
        acc += xr[k] * Wr[k * E_NUM + e];
    logits[(t0 + tl) * E_NUM + e] = acc;
}

// ---------------- K2: routing ------------------------------------------------
__global__ void route_kernel(const float* __restrict__ logits) {
    int t = blockIdx.x * blockDim.x + threadIdx.x;
    if (t >= T_TOK) return;
    float s[E_NUM];
#pragma unroll
    for (int e = 0; e < E_NUM; e++) s[e] = logits[t * E_NUM + e];
    float ssum[4]; int top1[4], top2[4]; float v1a[4], v2a[4];
#pragma unroll
    for (int sh = 0; sh < 4; sh++) {
        float sum = 0.f;
#pragma unroll
        for (int j = 0; j < 8; j++) sum += s[sh * 8 + j];
        ssum[sh] = sum;
        int i1 = 0; float v1 = s[sh * 8];
#pragma unroll
        for (int j = 1; j < 8; j++) { float v = s[sh * 8 + j]; if (v > v1) { v1 = v; i1 = j; } }
        int i2 = -1; float v2 = -1e30f;
#pragma unroll
        for (int j = 0; j < 8; j++) {
            if (j == i1) continue;
            float v = s[sh * 8 + j];
            if (v > v2) { v2 = v; i2 = j; }
        }
        top1[sh] = i1; top2[sh] = i2; v1a[sh] = v1; v2a[sh] = v2;
    }
    int ch0 = (ssum[1] > ssum[0]) ? 1 : 0;
    int ch1 = (ssum[3] > ssum[2]) ? 3 : 2;
    int ce[4]; float cv[4];
    ce[0] = ch0 * 8 + top1[ch0]; cv[0] = v1a[ch0];
    ce[1] = ch0 * 8 + top2[ch0]; cv[1] = v2a[ch0];
    ce[2] = ch1 * 8 + top1[ch1]; cv[2] = v1a[ch1];
    ce[3] = ch1 * 8 + top2[ch1]; cv[3] = v2a[ch1];
    float m = cv[0];
#pragma unroll
    for (int k = 1; k < 4; k++) m = fmaxf(m, cv[k]);
    float w[4]; float wsum = 0.f;
#pragma unroll
    for (int k = 0; k < 4; k++) { w[k] = expf(cv[k] - m); wsum += w[k]; }
    float inv = 1.f / wsum;
#pragma unroll
    for (int k = 0; k < 4; k++) {
        int e = ce[k];
        int r = atomicAdd(&g_cnt[e], 1);
        g_bucket[e * CAP + r] = t;
        g_slot_e[t * TOPK + k] = e;
        g_slot_r[t * TOPK + k] = r;
        g_slot_w[t * TOPK + k] = w[k] * inv;
    }
}

__global__ void prefix_kernel() {
    if (threadIdx.x == 0) {
        int o = 0;
        for (int e = 0; e < E_NUM; e++) { g_off[e] = o; o += g_cnt[e]; }
    }
}

// ---------------- GEMM1: gate+up (mma, on-the-fly split) ---------------------
__global__ __launch_bounds__(256) void gemm1_kernel(const float* __restrict__ X,
                                                    const float* __restrict__ Wg,
                                                    const float* __restrict__ Wu) {
    int e    = blockIdx.z;
    int rows = g_cnt[e];
    int row0 = blockIdx.y * 128;
    if (row0 >= rows) return;
    int base = g_off[e];
    int i0   = blockIdx.x * 64;

    __shared__ __align__(16) uint16_t Ahi[128 * RS], Alo[128 * RS];
    __shared__ __align__(16) uint16_t Gh[64 * RS], Gl[64 * RS];
    __shared__ __align__(16) uint16_t Uh[64 * RS], Ul[64 * RS];
    __shared__ int toks[128];

    int tid = threadIdx.x;
    int wid = tid >> 5, lane = tid & 31;
    int qr = lane >> 2, qc = lane & 3;
    int wm = wid & 3, wn = wid >> 2;

    for (int r = tid; r < 128; r += 256) {
        int rr = row0 + r;
        toks[r] = g_bucket[e * CAP + (rr < rows ? rr : row0)];
    }
    __syncthreads();

    const float* WgE = Wg + (size_t)e * H_DIM * I_DIM;
    const float* WuE = Wu + (size_t)e * H_DIM * I_DIM;

    // loader indices
    int ar = tid >> 1;               // 0..127 A row
    int akq = (tid & 1) * 16;        // k offset 0 or 16 (x4 float4 -> 4 iters)
    int bk = tid >> 3;               // 0..31 B k row
    int bn0 = (tid & 7) * 8;         // B n group of 8

    float accG[2][4][4] = {}, accU[2][4][4] = {};

    for (int k0 = 0; k0 < H_DIM; k0 += 32) {
        // A: 128 rows x 32 k fp32, gathered; each thread 4 float4 (16 k)
        {
            const float* src = X + (size_t)toks[ar] * H_DIM + k0 + akq;
#pragma unroll
            for (int q = 0; q < 4; q++)
                storeA4(Ahi, Alo, ar, akq + q * 4, *(const float4*)(src + q * 4));
        }
        // B: 32 k x 64 n fp32 -> transposed smem; each thread 2 float4 per matrix
        {
            const float* g0p = WgE + (size_t)(k0 + bk) * I_DIM + i0 + bn0;
            const float* u0p = WuE + (size_t)(k0 + bk) * I_DIM + i0 + bn0;
            float4 v0 = *(const float4*)g0p, v1 = *(const float4*)(g0p + 4);
            storeB4T(Gh, Gl, bn0, bk, v0);
            storeB4T(Gh, Gl, bn0 + 4, bk, v1);
            v0 = *(const float4*)u0p; v1 = *(const float4*)(u0p + 4);
            storeB4T(Uh, Ul, bn0, bk, v0);
            storeB4T(Uh, Ul, bn0 + 4, bk, v1);
        }
        __syncthreads();

#pragma unroll
        for (int kk = 0; kk < 32; kk += 16) {
            uint32_t ah[2][4], al[2][4];
#pragma unroll
            for (int i = 0; i < 2; i++) {
                ldfragA(ah[i], Ahi, wm * 32 + i * 16, kk, qr, qc);
                ldfragA(al[i], Alo, wm * 32 + i * 16, kk, qr, qc);
            }
            uint32_t bh[4][2], bl[4][2];
#pragma unroll
            for (int j = 0; j < 4; j++) {
                ldfragB(bh[j], Gh, wn * 32 + j * 8, kk, qr, qc);
                ldfragB(bl[j], Gl, wn * 32 + j * 8, kk, qr, qc);
            }
#pragma unroll
            for (int i = 0; i < 2; i++)
#pragma unroll
                for (int j = 0; j < 4; j++) {
                    mma16816(accG[i][j], ah[i], bh[j]);
                    mma16816(accG[i][j], ah[i], bl[j]);
                    mma16816(accG[i][j], al[i], bh[j]);
                }
#pragma unroll
            for (int j = 0; j < 4; j++) {
                ldfragB(bh[j], Uh, wn * 32 + j * 8, kk, qr, qc);
                ldfragB(bl[j], Ul, wn * 32 + j * 8, kk, qr, qc);
            }
#pragma unroll
            for (int i = 0; i < 2; i++)
#pragma unroll
                for (int j = 0; j < 4; j++) {
                    mma16816(accU[i][j], ah[i], bh[j]);
                    mma16816(accU[i][j], ah[i], bl[j]);
                    mma16816(accU[i][j], al[i], bh[j]);
                }
        }
        __syncthreads();
    }

    // epilogue: silu(gate)*up -> g_H fp32 (same mapping as verified gemm3)
#pragma unroll
    for (int i = 0; i < 2; i++) {
#pragma unroll
        for (int half = 0; half < 2; half++) {
            int rr = row0 + wm * 32 + i * 16 + qr + half * 8;
            if (rr >= rows) continue;
            size_t ro = (size_t)(base + rr) * I_DIM + i0 + wn * 32;
#pragma unroll
            for (int j = 0; j < 4; j++) {
                float g0 = accG[i][j][half * 2 + 0], g1 = accG[i][j][half * 2 + 1];
                float u0 = accU[i][j][half * 2 + 0], u1 = accU[i][j][half * 2 + 1];
                float2 v;
                v.x = g0 / (1.f + expf(-g0)) * u0;
                v.y = g1 / (1.f + expf(-g1)) * u1;
                *(float2*)(g_H + ro + j * 8 + qc * 2) = v;
            }
        }
    }
}

// ---------------- GEMM2: down proj (mma, on-the-fly split) -------------------
__global__ __launch_bounds__(256) void gemm2_kernel(const float* __restrict__ Wd) {
    int e    = blockIdx.z;
    int rows = g_cnt[e];
    int row0 = blockIdx.y * 128;
    if (row0 >= rows) return;
    int base = g_off[e];
    int o0   = blockIdx.x * 64;

    __shared__ __align__(16) uint16_t Ahi[128 * RS], Alo[128 * RS];
    __shared__ __align__(16) uint16_t Bh[64 * RS], Bl[64 * RS];

    int tid = threadIdx.x;
    int wid = tid >> 5, lane = tid & 31;
    int qr = lane >> 2, qc = lane & 3;
    int wm = wid & 3, wn = wid >> 2;

    const float* WdE = Wd + (size_t)e * I_DIM * O_DIM;

    int ar = tid >> 1;
    int akq = (tid & 1) * 16;
    int bk = tid >> 3;
    int bn0 = (tid & 7) * 8;

    int arow = row0 + ar; if (arow >= rows) arow = rows - 1;  // clamp (in-bounds)

    float acc[2][4][4] = {};

    for (int k0 = 0; k0 < I_DIM; k0 += 32) {
        {
            const float* src = g_H + (size_t)(base + arow) * I_DIM + k0 + akq;
#pragma unroll
            for (int q = 0; q < 4; q++)
                storeA4(Ahi, Alo, ar, akq + q * 4, *(const float4*)(src + q * 4));
        }
        {
            const float* bp = WdE + (size_t)(k0 + bk) * O_DIM + o0 + bn0;
            float4 v0 = *(const float4*)bp, v1 = *(const float4*)(bp + 4);
            storeB4T(Bh, Bl, bn0, bk, v0);
            storeB4T(Bh, Bl, bn0 + 4, bk, v1);
        }
        __syncthreads();

#pragma unroll
        for (int kk = 0; kk < 32; kk += 16) {
            uint32_t ah[2][4], al[2][4];
#pragma unroll
            for (int i = 0; i < 2; i++) {
                ldfragA(ah[i], Ahi, wm * 32 + i * 16, kk, qr, qc);
                ldfragA(al[i], Alo, wm * 32 + i * 16, kk, qr, qc);
            }
            uint32_t bh[4][2], bl[4][2];
#pragma unroll
            for (int j = 0; j < 4; j++) {
                ldfragB(bh[j], Bh, wn * 32 + j * 8, kk, qr, qc);
                ldfragB(bl[j], Bl, wn * 32 + j * 8, kk, qr, qc);
            }
#pragma unroll
            for (int i = 0; i < 2; i++)
#pragma unroll
                for (int j = 0; j < 4; j++) {
                    mma16816(acc[i][j], ah[i], bh[j]);
                    mma16816(acc[i][j], ah[i], bl[j]);
                    mma16816(acc[i][j], al[i], bh[j]);
                }
        }
        __syncthreads();
    }

#pragma unroll
    for (int i = 0; i < 2; i++) {
#pragma unroll
        for (int half = 0; half < 2; half++) {
            int rr = row0 + wm * 32 + i * 16 + qr + half * 8;
            if (rr >= rows) continue;
            size_t ro = (size_t)(base + rr) * O_DIM + o0 + wn * 32;
#pragma unroll
            for (int j = 0; j < 4; j++) {
                float2 v;
                v.x = acc[i][j][half * 2 + 0];
                v.y = acc[i][j][half * 2 + 1];
                *(float2*)(g_Y + ro + j * 8 + qc * 2) = v;
            }
        }
    }
}

// ---------------- K5: combine (proven) ---------------------------------------
__global__ void combine_kernel() {
    int t = blockIdx.x;
    __shared__ int   se[TOPK];
    __shared__ int   sr[TOPK];
    __shared__ float sw[TOPK];
    if (threadIdx.x < TOPK) {
        int e = g_slot_e[t * TOPK + threadIdx.x];
        se[threadIdx.x] = e;
        sr[threadIdx.x] = g_off[e] + g_slot_r[t * TOPK + threadIdx.x];
        sw[threadIdx.x] = g_slot_w[t * TOPK + threadIdx.x];
    }
    __syncthreads();
    for (int c = threadIdx.x; c < H_DIM; c += blockDim.x) {
        int g = c >> 9;
        int o = c & 511;
        float acc = 0.f;
#pragma unroll
        for (int s = 0; s < TOPK; s++)
            if ((se[s] >> 4) == g)
                acc += sw[s] * g_Y[(size_t)sr[s] * O_DIM + o];
        g_pre[(size_t)t * H_DIM + c] = acc;
    }
}

// ---------------- convert pre -> bf16 hi/lo (proven) --------------------------
__global__ __launch_bounds__(256) void convert_pre() {
    int idx = (blockIdx.x * 256 + threadIdx.x) * 4;
    float4 v = *(const float4*)(g_pre + idx);
    __nv_bfloat16 h0, l0, h1, l1, h2, l2, h3, l3;
    split2(v.x, h0, l0); split2(v.y, h1, l1); split2(v.z, h2, l2); split2(v.w, h3, l3);
    __nv_bfloat162 a, b;
    a.x = h0; a.y = h1; b.x = h2; b.y = h3;
    *(__nv_bfloat162*)(g_phi + idx) = a; *(__nv_bfloat162*)(g_phi + idx + 2) = b;
    a.x = l0; a.y = l1; b.x = l2; b.y = l3;
    *(__nv_bfloat162*)(g_plo + idx) = a; *(__nv_bfloat162*)(g_plo + idx + 2) = b;
}

// ---------------- Wc transpose+split (proven) ---------------------------------
__global__ __launch_bounds__(256) void transpose_wc(const float* __restrict__ Wc) {
    uint32_t n = blockIdx.x * 256 + threadIdx.x;
    uint32_t c = n >> 10;
    uint32_t r = n & 1023;
    float v = Wc[(size_t)r * H_DIM + c];
    __nv_bfloat16 h, l; split2(v, h, l);
    g_WcThi[n] = h; g_WcTlo[n] = l;
}

// ---------------- GEMM3 via mma.sync (proven) ---------------------------------
__global__ __launch_bounds__(256) void gemm3_kernel(float* __restrict__ out) {
    int row0 = blockIdx.y * 128;
    int j0   = blockIdx.x * 64;

    __shared__ __align__(16) uint16_t Ahi[128 * RS], Alo[128 * RS];
    __shared__ __align__(16) uint16_t Bh[64 * RS], Bl[64 * RS];

    int tid = threadIdx.x;
    int wid = tid >> 5, lane = tid & 31;
    int qr = lane >> 2, qc = lane & 3;
    int wm = wid & 3, wn = wid >> 2;

    const __nv_bfloat16* BHp = g_WcThi + (size_t)j0 * H_DIM;
    const __nv_bfloat16* BLp = g_WcTlo + (size_t)j0 * H_DIM;

    float acc[2][4][4] = {};

    for (int k0 = 0; k0 < H_DIM; k0 += 32) {
#pragma unroll
        for (int u = tid; u < 512; u += 256) {
            int r = u >> 2, sg = u & 3;
            size_t so = (size_t)(row0 + r) * H_DIM + k0 + sg * 8;
            *(int4*)&Ahi[r * RS + sg * 8] = *(const int4*)(g_phi + so);
            *(int4*)&Alo[r * RS + sg * 8] = *(const int4*)(g_plo + so);
        }
        {
            int r = tid >> 2, sg = tid & 3;
            size_t so = (size_t)r * H_DIM + k0 + sg * 8;
            int d = r * RS + sg * 8;
            *(int4*)&Bh[d] = *(const int4*)(BHp + so);
            *(int4*)&Bl[d] = *(const int4*)(BLp + so);
        }
        __syncthreads();

#pragma unroll
        for (int kk = 0; kk < 32; kk += 16) {
            uint32_t ah[2][4], al[2][4];
#pragma unroll
            for (int i = 0; i < 2; i++) {
                ldfragA(ah[i], Ahi, wm * 32 + i * 16, kk, qr, qc);
                ldfragA(al[i], Alo, wm * 32 + i * 16, kk, qr, qc);
            }
            uint32_t bh[4][2], bl[4][2];
#pragma unroll
            for (int j = 0; j < 4; j++) {
                ldfragB(bh[j], Bh, wn * 32 + j * 8, kk, qr, qc);
                ldfragB(bl[j], Bl, wn * 32 + j * 8, kk, qr, qc);
            }
#pragma unroll
            for (int i = 0; i < 2; i++)
#pragma unroll
                for (int j = 0; j < 4; j++) {
                    mma16816(acc[i][j], ah[i], bh[j]);
                    mma16816(acc[i][j], ah[i], bl[j]);
                    mma16816(acc[i][j], al[i], bh[j]);
                }
        }
        __syncthreads();
    }

#pragma unroll
    for (int i = 0; i < 2; i++) {
#pragma unroll
        for (int half = 0; half < 2; half++) {
            int rr = row0 + wm * 32 + i * 16 + qr + half * 8;
            size_t ro = (size_t)rr * H_DIM + j0 + wn * 32;
#pragma unroll
            for (int j = 0; j < 4; j++) {
                float2 v;
                v.x = acc[i][j][half * 2 + 0];
                v.y = acc[i][j][half * 2 + 1];
                *(float2*)(out + ro + j * 8 + qc * 2) = v;
            }
        }
    }
}

// ---------------- launch -----------------------------------------------------
extern "C" void kernel_launch(void* const* d_in, const int* in_sizes, int n_in,
                              void* d_out, int out_size) {
    const float* X  = (const float*)d_in[0];
    const float* Wr = (const float*)d_in[1];
    const float* Wg = (const float*)d_in[2];
    const float* Wu = (const float*)d_in[3];
    const float* Wd = (const float*)d_in[4];
    const float* Wc = (const float*)d_in[5];
    float* out = (float*)d_out;
    float* logits = out + (size_t)T_TOK * H_DIM;

    init_kernel<<<1, 32>>>();
    transpose_wc<<<H_DIM * H_DIM / 256, 256>>>(Wc);

    router_gemm<<<T_TOK / 8, 256>>>(X, Wr, logits);
    route_kernel<<<T_TOK / 256, 256>>>(logits);
    prefix_kernel<<<1, 32>>>();

    gemm1_kernel<<<dim3(I_DIM / 64, CAP / 128, E_NUM), 256>>>(X, Wg, Wu);
    gemm2_kernel<<<dim3(O_DIM / 64, CAP / 128, E_NUM), 256>>>(Wd);

    combine_kernel<<<T_TOK, 256>>>();
    convert_pre<<<T_TOK * H_DIM / 1024, 256>>>();

    gemm3_kernel<<<dim3(H_DIM / 64, T_TOK / 128), 256>>>(out);
}

// round 10
// speedup vs baseline: 1.5185x; 1.0906x over previous
#include <cuda_runtime.h>
#include <cuda_bf16.h>
#include <math.h>
#include <stdint.h>

// Problem constants
#define T_TOK 2048
#define H_DIM 1024
#define E_NUM 32
#define I_DIM 256
#define O_DIM 512
#define TOPK  4
#define CAP   2048
#define TOT_ROWS (T_TOK*TOPK)   // 8192

#define RS 40   // smem row stride (bf16 elems) for mma tiles

// ---------------- scratch (device globals; no allocation) --------------------
__device__ int   g_cnt[E_NUM];
__device__ int   g_off[E_NUM];
__device__ int   g_bucket[E_NUM * CAP];
__device__ int   g_slot_e[T_TOK * TOPK];
__device__ int   g_slot_r[T_TOK * TOPK];
__device__ float g_slot_w[T_TOK * TOPK];
__device__ float g_Y[TOT_ROWS * O_DIM];

__device__ __align__(256) __nv_bfloat16 g_Xhi[T_TOK * H_DIM];
__device__ __align__(256) __nv_bfloat16 g_Xlo[T_TOK * H_DIM];
__device__ __align__(256) __nv_bfloat16 g_Hhi[(TOT_ROWS + 128) * I_DIM];
__device__ __align__(256) __nv_bfloat16 g_Hlo[(TOT_ROWS + 128) * I_DIM];
__device__ __align__(256) __nv_bfloat16 g_phi[T_TOK * H_DIM];
__device__ __align__(256) __nv_bfloat16 g_plo[T_TOK * H_DIM];
__device__ __align__(256) __nv_bfloat16 g_WcThi[H_DIM * H_DIM];
__device__ __align__(256) __nv_bfloat16 g_WcTlo[H_DIM * H_DIM];
// pre-split transposed weights [e][n][k]
__device__ __align__(256) __nv_bfloat16 g_WgThi[E_NUM * I_DIM * H_DIM];
__device__ __align__(256) __nv_bfloat16 g_WgTlo[E_NUM * I_DIM * H_DIM];
__device__ __align__(256) __nv_bfloat16 g_WuThi[E_NUM * I_DIM * H_DIM];
__device__ __align__(256) __nv_bfloat16 g_WuTlo[E_NUM * I_DIM * H_DIM];
__device__ __align__(256) __nv_bfloat16 g_WdThi[E_NUM * O_DIM * I_DIM];
__device__ __align__(256) __nv_bfloat16 g_WdTlo[E_NUM * O_DIM * I_DIM];

// ---------------- helpers ----------------------------------------------------
__device__ __forceinline__ void split2(float x, __nv_bfloat16& h, __nv_bfloat16& l) {
    h = __float2bfloat16_rn(x);
    l = __float2bfloat16_rn(x - __bfloat162float(h));
}

__device__ __forceinline__ void mma16816(float* c, const uint32_t* a, const uint32_t* b) {
    asm volatile(
        "mma.sync.aligned.m16n8k16.row.col.f32.bf16.bf16.f32 "
        "{%0,%1,%2,%3}, {%4,%5,%6,%7}, {%8,%9}, {%0,%1,%2,%3};"
        : "+f"(c[0]), "+f"(c[1]), "+f"(c[2]), "+f"(c[3])
        : "r"(a[0]), "r"(a[1]), "r"(a[2]), "r"(a[3]), "r"(b[0]), "r"(b[1]));
}

__device__ __forceinline__ void ldfragA(uint32_t* a, const uint16_t* S, int mrow,
                                        int kk, int qr, int qc) {
    const uint16_t* p = S + (mrow + qr) * RS + kk + qc * 2;
    a[0] = *(const uint32_t*)p;
    a[1] = *(const uint32_t*)(p + 8 * RS);
    a[2] = *(const uint32_t*)(p + 8);
    a[3] = *(const uint32_t*)(p + 8 * RS + 8);
}
__device__ __forceinline__ void ldfragB(uint32_t* b, const uint16_t* S, int nrow,
                                        int kk, int qr, int qc) {
    const uint16_t* p = S + (nrow + qr) * RS + kk + qc * 2;
    b[0] = *(const uint32_t*)p;
    b[1] = *(const uint32_t*)(p + 8);
}

// ---------------- init -------------------------------------------------------
__global__ void init_kernel() {
    if (threadIdx.x < E_NUM) g_cnt[threadIdx.x] = 0;
}

// ---------------- convert X -> bf16 hi/lo (verified) --------------------------
__global__ __launch_bounds__(256) void convert_x(const float* __restrict__ X) {
    int idx = (blockIdx.x * 256 + threadIdx.x) * 4;
    float4 v = *(const float4*)(X + idx);
    __nv_bfloat16 h0, l0, h1, l1, h2, l2, h3, l3;
    split2(v.x, h0, l0); split2(v.y, h1, l1); split2(v.z, h2, l2); split2(v.w, h3, l3);
    __nv_bfloat162 a, b;
    a.x = h0; a.y = h1; b.x = h2; b.y = h3;
    *(__nv_bfloat162*)(g_Xhi + idx) = a; *(__nv_bfloat162*)(g_Xhi + idx + 2) = b;
    a.x = l0; a.y = l1; b.x = l2; b.y = l3;
    *(__nv_bfloat162*)(g_Xlo + idx) = a; *(__nv_bfloat162*)(g_Xlo + idx + 2) = b;
}

// ---------------- tiled transpose+split: dst[c][r] = src[r][c] ---------------
// dhi/dlo are REAL device pointers (resolved via cudaGetSymbolAddress on host).
__global__ void tsplit(const float* __restrict__ src,
                       __nv_bfloat16* __restrict__ dhi,
                       __nv_bfloat16* __restrict__ dlo,
                       int R, int C) {
    size_t eoff = (size_t)blockIdx.z * R * C;
    __shared__ float t[32][33];
    int c0 = blockIdx.x * 32, r0 = blockIdx.y * 32;
    int tx = threadIdx.x, ty = threadIdx.y;
#pragma unroll
    for (int i = 0; i < 4; i++)
        t[ty + i * 8][tx] = src[eoff + (size_t)(r0 + ty + i * 8) * C + c0 + tx];
    __syncthreads();
#pragma unroll
    for (int i = 0; i < 4; i++) {
        float v = t[tx][ty + i * 8];
        __nv_bfloat16 h, l; split2(v, h, l);
        size_t o = eoff + (size_t)(c0 + ty + i * 8) * R + r0 + tx;
        dhi[o] = h; dlo[o] = l;
    }
}

// ---------------- Wc transpose+split (verified, writes symbols directly) ------
__global__ __launch_bounds__(256) void transpose_wc(const float* __restrict__ Wc) {
    uint32_t n = blockIdx.x * 256 + threadIdx.x;
    uint32_t c = n >> 10;
    uint32_t r = n & 1023;
    float v = Wc[(size_t)r * H_DIM + c];
    __nv_bfloat16 h, l; split2(v, h, l);
    g_WcThi[n] = h; g_WcTlo[n] = l;
}

// ---------------- K1: router logits (fp32, exact) ----------------------------
__global__ __launch_bounds__(256) void router_gemm(const float* __restrict__ X,
                                                   const float* __restrict__ Wr,
                                                   float* __restrict__ logits) {
    __shared__ float xs[8][H_DIM];
    int t0 = blockIdx.x * 8;
    for (int i = threadIdx.x; i < 8 * H_DIM; i += 256)
        xs[i >> 10][i & 1023] = X[(size_t)t0 * H_DIM + i];
    __syncthreads();
    int tl = threadIdx.x >> 5;
    int e  = threadIdx.x & 31;
    const float* xr = xs[tl];
    float acc = 0.f;
#pragma unroll 8
    for (int k = 0; k < H_DIM; k++)
        acc += xr[k] * Wr[k * E_NUM + e];
    logits[(t0 + tl) * E_NUM + e] = acc;
}

// ---------------- K2: routing ------------------------------------------------
__global__ void route_kernel(const float* __restrict__ logits) {
    int t = blockIdx.x * blockDim.x + threadIdx.x;
    if (t >= T_TOK) return;
    float s[E_NUM];
#pragma unroll
    for (int e = 0; e < E_NUM; e++) s[e] = logits[t * E_NUM + e];
    float ssum[4]; int top1[4], top2[4]; float v1a[4], v2a[4];
#pragma unroll
    for (int sh = 0; sh < 4; sh++) {
        float sum = 0.f;
#pragma unroll
        for (int j = 0; j < 8; j++) sum += s[sh * 8 + j];
        ssum[sh] = sum;
        int i1 = 0; float v1 = s[sh * 8];
#pragma unroll
        for (int j = 1; j < 8; j++) { float v = s[sh * 8 + j]; if (v > v1) { v1 = v; i1 = j; } }
        int i2 = -1; float v2 = -1e30f;
#pragma unroll
        for (int j = 0; j < 8; j++) {
            if (j == i1) continue;
            float v = s[sh * 8 + j];
            if (v > v2) { v2 = v; i2 = j; }
        }
        top1[sh] = i1; top2[sh] = i2; v1a[sh] = v1; v2a[sh] = v2;
    }
    int ch0 = (ssum[1] > ssum[0]) ? 1 : 0;
    int ch1 = (ssum[3] > ssum[2]) ? 3 : 2;
    int ce[4]; float cv[4];
    ce[0] = ch0 * 8 + top1[ch0]; cv[0] = v1a[ch0];
    ce[1] = ch0 * 8 + top2[ch0]; cv[1] = v2a[ch0];
    ce[2] = ch1 * 8 + top1[ch1]; cv[2] = v1a[ch1];
    ce[3] = ch1 * 8 + top2[ch1]; cv[3] = v2a[ch1];
    float m = cv[0];
#pragma unroll
    for (int k = 1; k < 4; k++) m = fmaxf(m, cv[k]);
    float w[4]; float wsum = 0.f;
#pragma unroll
    for (int k = 0; k < 4; k++) { w[k] = expf(cv[k] - m); wsum += w[k]; }
    float inv = 1.f / wsum;
#pragma unroll
    for (int k = 0; k < 4; k++) {
        int e = ce[k];
        int r = atomicAdd(&g_cnt[e], 1);
        g_bucket[e * CAP + r] = t;
        g_slot_e[t * TOPK + k] = e;
        g_slot_r[t * TOPK + k] = r;
        g_slot_w[t * TOPK + k] = w[k] * inv;
    }
}

__global__ void prefix_kernel() {
    if (threadIdx.x == 0) {
        int o = 0;
        for (int e = 0; e < E_NUM; e++) { g_off[e] = o; o += g_cnt[e]; }
    }
}

// ---------------- GEMM1: gate+up (mma, pre-split operands) -------------------
__global__ __launch_bounds__(256) void gemm1_kernel() {
    int e    = blockIdx.z;
    int rows = g_cnt[e];
    int row0 = blockIdx.y * 128;
    if (row0 >= rows) return;
    int base = g_off[e];
    int i0   = blockIdx.x * 64;

    __shared__ __align__(16) uint16_t Ahi[128 * RS], Alo[128 * RS];
    __shared__ __align__(16) uint16_t Gh[64 * RS], Gl[64 * RS];
    __shared__ __align__(16) uint16_t Uh[64 * RS], Ul[64 * RS];
    __shared__ int toks[128];

    int tid = threadIdx.x;
    int wid = tid >> 5, lane = tid & 31;
    int qr = lane >> 2, qc = lane & 3;
    int wm = wid & 3, wn = wid >> 2;

    for (int r = tid; r < 128; r += 256) {
        int rr = row0 + r;
        toks[r] = g_bucket[e * CAP + (rr < rows ? rr : row0)];
    }
    __syncthreads();

    const __nv_bfloat16* GHp = g_WgThi + (size_t)e * I_DIM * H_DIM + (size_t)i0 * H_DIM;
    const __nv_bfloat16* GLp = g_WgTlo + (size_t)e * I_DIM * H_DIM + (size_t)i0 * H_DIM;
    const __nv_bfloat16* UHp = g_WuThi + (size_t)e * I_DIM * H_DIM + (size_t)i0 * H_DIM;
    const __nv_bfloat16* ULp = g_WuTlo + (size_t)e * I_DIM * H_DIM + (size_t)i0 * H_DIM;

    float accG[2][4][4] = {}, accU[2][4][4] = {};

    for (int k0 = 0; k0 < H_DIM; k0 += 32) {
#pragma unroll
        for (int u = tid; u < 512; u += 256) {
            int r = u >> 2, sg = u & 3;
            size_t so = (size_t)toks[r] * H_DIM + k0 + sg * 8;
            int d = r * RS + sg * 8;
            *(int4*)&Ahi[d] = *(const int4*)(g_Xhi + so);
            *(int4*)&Alo[d] = *(const int4*)(g_Xlo + so);
        }
        {
            int r = tid >> 2, sg = tid & 3;
            size_t so = (size_t)r * H_DIM + k0 + sg * 8;
            int d = r * RS + sg * 8;
            *(int4*)&Gh[d] = *(const int4*)(GHp + so);
            *(int4*)&Gl[d] = *(const int4*)(GLp + so);
            *(int4*)&Uh[d] = *(const int4*)(UHp + so);
            *(int4*)&Ul[d] = *(const int4*)(ULp + so);
        }
        __syncthreads();

#pragma unroll
        for (int kk = 0; kk < 32; kk += 16) {
            uint32_t ah[2][4], al[2][4];
#pragma unroll
            for (int i = 0; i < 2; i++) {
                ldfragA(ah[i], Ahi, wm * 32 + i * 16, kk, qr, qc);
                ldfragA(al[i], Alo, wm * 32 + i * 16, kk, qr, qc);
            }
            uint32_t bh[4][2], bl[4][2];
#pragma unroll
            for (int j = 0; j < 4; j++) {
                ldfragB(bh[j], Gh, wn * 32 + j * 8, kk, qr, qc);
                ldfragB(bl[j], Gl, wn * 32 + j * 8, kk, qr, qc);
            }
#pragma unroll
            for (int i = 0; i < 2; i++)
#pragma unroll
                for (int j = 0; j < 4; j++) {
                    mma16816(accG[i][j], ah[i], bh[j]);
                    mma16816(accG[i][j], ah[i], bl[j]);
                    mma16816(accG[i][j], al[i], bh[j]);
                }
#pragma unroll
            for (int j = 0; j < 4; j++) {
                ldfragB(bh[j], Uh, wn * 32 + j * 8, kk, qr, qc);
                ldfragB(bl[j], Ul, wn * 32 + j * 8, kk, qr, qc);
            }
#pragma unroll
            for (int i = 0; i < 2; i++)
#pragma unroll
                for (int j = 0; j < 4; j++) {
                    mma16816(accU[i][j], ah[i], bh[j]);
                    mma16816(accU[i][j], ah[i], bl[j]);
                    mma16816(accU[i][j], al[i], bh[j]);
                }
        }
        __syncthreads();
    }

#pragma unroll
    for (int i = 0; i < 2; i++) {
#pragma unroll
        for (int half = 0; half < 2; half++) {
            int rr = row0 + wm * 32 + i * 16 + qr + half * 8;
            if (rr >= rows) continue;
            size_t ro = (size_t)(base + rr) * I_DIM + i0 + wn * 32;
#pragma unroll
            for (int j = 0; j < 4; j++) {
                float g0 = accG[i][j][half * 2 + 0], g1 = accG[i][j][half * 2 + 1];
                float u0 = accU[i][j][half * 2 + 0], u1 = accU[i][j][half * 2 + 1];
                float h0 = g0 / (1.f + expf(-g0)) * u0;
                float h1 = g1 / (1.f + expf(-g1)) * u1;
                __nv_bfloat16 hh0, hl0, hh1, hl1;
                split2(h0, hh0, hl0); split2(h1, hh1, hl1);
                __nv_bfloat162 ph; ph.x = hh0; ph.y = hh1;
                __nv_bfloat162 pl; pl.x = hl0; pl.y = hl1;
                *(__nv_bfloat162*)(g_Hhi + ro + j * 8 + qc * 2) = ph;
                *(__nv_bfloat162*)(g_Hlo + ro + j * 8 + qc * 2) = pl;
            }
        }
    }
}

// ---------------- GEMM2: down proj (mma, pre-split operands) -----------------
__global__ __launch_bounds__(256) void gemm2_kernel() {
    int e    = blockIdx.z;
    int rows = g_cnt[e];
    int row0 = blockIdx.y * 128;
    if (row0 >= rows) return;
    int base = g_off[e];
    int o0   = blockIdx.x * 64;

    __shared__ __align__(16) uint16_t Ahi[128 * RS], Alo[128 * RS];
    __shared__ __align__(16) uint16_t Bh[64 * RS], Bl[64 * RS];

    int tid = threadIdx.x;
    int wid = tid >> 5, lane = tid & 31;
    int qr = lane >> 2, qc = lane & 3;
    int wm = wid & 3, wn = wid >> 2;

    const __nv_bfloat16* BHp = g_WdThi + (size_t)e * O_DIM * I_DIM + (size_t)o0 * I_DIM;
    const __nv_bfloat16* BLp = g_WdTlo + (size_t)e * O_DIM * I_DIM + (size_t)o0 * I_DIM;

    float acc[2][4][4] = {};

    for (int k0 = 0; k0 < I_DIM; k0 += 32) {
#pragma unroll
        for (int u = tid; u < 512; u += 256) {
            int r = u >> 2, sg = u & 3;
            int ar = row0 + r; if (ar >= rows) ar = rows - 1;
            size_t so = (size_t)(base + ar) * I_DIM + k0 + sg * 8;
            int d = r * RS + sg * 8;
            *(int4*)&Ahi[d] = *(const int4*)(g_Hhi + so);
            *(int4*)&Alo[d] = *(const int4*)(g_Hlo + so);
        }
        {
            int r = tid >> 2, sg = tid & 3;
            size_t so = (size_t)r * I_DIM + k0 + sg * 8;
            int d = r * RS + sg * 8;
            *(int4*)&Bh[d] = *(const int4*)(BHp + so);
            *(int4*)&Bl[d] = *(const int4*)(BLp + so);
        }
        __syncthreads();

#pragma unroll
        for (int kk = 0; kk < 32; kk += 16) {
            uint32_t ah[2][4], al[2][4];
#pragma unroll
            for (int i = 0; i < 2; i++) {
                ldfragA(ah[i], Ahi, wm * 32 + i * 16, kk, qr, qc);
                ldfragA(al[i], Alo, wm * 32 + i * 16, kk, qr, qc);
            }
            uint32_t bh[4][2], bl[4][2];
#pragma unroll
            for (int j = 0; j < 4; j++) {
                ldfragB(bh[j], Bh, wn * 32 + j * 8, kk, qr, qc);
                ldfragB(bl[j], Bl, wn * 32 + j * 8, kk, qr, qc);
            }
#pragma unroll
            for (int i = 0; i < 2; i++)
#pragma unroll
                for (int j = 0; j < 4; j++) {
                    mma16816(acc[i][j], ah[i], bh[j]);
                    mma16816(acc[i][j], ah[i], bl[j]);
                    mma16816(acc[i][j], al[i], bh[j]);
                }
        }
        __syncthreads();
    }

#pragma unroll
    for (int i = 0; i < 2; i++) {
#pragma unroll
        for (int half = 0; half < 2; half++) {
            int rr = row0 + wm * 32 + i * 16 + qr + half * 8;
            if (rr >= rows) continue;
            size_t ro = (size_t)(base + rr) * O_DIM + o0 + wn * 32;
#pragma unroll
            for (int j = 0; j < 4; j++) {
                float2 v;
                v.x = acc[i][j][half * 2 + 0];
                v.y = acc[i][j][half * 2 + 1];
                *(float2*)(g_Y + ro + j * 8 + qc * 2) = v;
            }
        }
    }
}

// ---------------- K5: combine + split (fused) --------------------------------
__global__ void combine_kernel() {
    int t = blockIdx.x;
    __shared__ int   se[TOPK];
    __shared__ int   sr[TOPK];
    __shared__ float sw[TOPK];
    if (threadIdx.x < TOPK) {
        int e = g_slot_e[t * TOPK + threadIdx.x];
        se[threadIdx.x] = e;
        sr[threadIdx.x] = g_off[e] + g_slot_r[t * TOPK + threadIdx.x];
        sw[threadIdx.x] = g_slot_w[t * TOPK + threadIdx.x];
    }
    __syncthreads();
    for (int c = threadIdx.x; c < H_DIM; c += blockDim.x) {
        int g = c >> 9;
        int o = c & 511;
        float acc = 0.f;
#pragma unroll
        for (int s = 0; s < TOPK; s++)
            if ((se[s] >> 4) == g)
                acc += sw[s] * g_Y[(size_t)sr[s] * O_DIM + o];
        __nv_bfloat16 h, l; split2(acc, h, l);
        g_phi[(size_t)t * H_DIM + c] = h;
        g_plo[(size_t)t * H_DIM + c] = l;
    }
}

// ---------------- GEMM3 via mma.sync (proven) ---------------------------------
__global__ __launch_bounds__(256) void gemm3_kernel(float* __restrict__ out) {
    int row0 = blockIdx.y * 128;
    int j0   = blockIdx.x * 64;

    __shared__ __align__(16) uint16_t Ahi[128 * RS], Alo[128 * RS];
    __shared__ __align__(16) uint16_t Bh[64 * RS], Bl[64 * RS];

    int tid = threadIdx.x;
    int wid = tid >> 5, lane = tid & 31;
    int qr = lane >> 2, qc = lane & 3;
    int wm = wid & 3, wn = wid >> 2;

    const __nv_bfloat16* BHp = g_WcThi + (size_t)j0 * H_DIM;
    const __nv_bfloat16* BLp = g_WcTlo + (size_t)j0 * H_DIM;

    float acc[2][4][4] = {};

    for (int k0 = 0; k0 < H_DIM; k0 += 32) {
#pragma unroll
        for (int u = tid; u < 512; u += 256) {
            int r = u >> 2, sg = u & 3;
            size_t so = (size_t)(row0 + r) * H_DIM + k0 + sg * 8;
            int d = r * RS + sg * 8;
            *(int4*)&Ahi[d] = *(const int4*)(g_phi + so);
            *(int4*)&Alo[d] = *(const int4*)(g_plo + so);
        }
        {
            int r = tid >> 2, sg = tid & 3;
            size_t so = (size_t)r * H_DIM + k0 + sg * 8;
            int d = r * RS + sg * 8;
            *(int4*)&Bh[d] = *(const int4*)(BHp + so);
            *(int4*)&Bl[d] = *(const int4*)(BLp + so);
        }
        __syncthreads();

#pragma unroll
        for (int kk = 0; kk < 32; kk += 16) {
            uint32_t ah[2][4], al[2][4];
#pragma unroll
            for (int i = 0; i < 2; i++) {
                ldfragA(ah[i], Ahi, wm * 32 + i * 16, kk, qr, qc);
                ldfragA(al[i], Alo, wm * 32 + i * 16, kk, qr, qc);
            }
            uint32_t bh[4][2], bl[4][2];
#pragma unroll
            for (int j = 0; j < 4; j++) {
                ldfragB(bh[j], Bh, wn * 32 + j * 8, kk, qr, qc);
                ldfragB(bl[j], Bl, wn * 32 + j * 8, kk, qr, qc);
            }
#pragma unroll
            for (int i = 0; i < 2; i++)
#pragma unroll
                for (int j = 0; j < 4; j++) {
                    mma16816(acc[i][j], ah[i], bh[j]);
                    mma16816(acc[i][j], ah[i], bl[j]);
                    mma16816(acc[i][j], al[i], bh[j]);
                }
        }
        __syncthreads();
    }

#pragma unroll
    for (int i = 0; i < 2; i++) {
#pragma unroll
        for (int half = 0; half < 2; half++) {
            int rr = row0 + wm * 32 + i * 16 + qr + half * 8;
            size_t ro = (size_t)rr * H_DIM + j0 + wn * 32;
#pragma unroll
            for (int j = 0; j < 4; j++) {
                float2 v;
                v.x = acc[i][j][half * 2 + 0];
                v.y = acc[i][j][half * 2 + 1];
                *(float2*)(out + ro + j * 8 + qc * 2) = v;
            }
        }
    }
}

// ---------------- launch -----------------------------------------------------
extern "C" void kernel_launch(void* const* d_in, const int* in_sizes, int n_in,
                              void* d_out, int out_size) {
    const float* X  = (const float*)d_in[0];
    const float* Wr = (const float*)d_in[1];
    const float* Wg = (const float*)d_in[2];
    const float* Wu = (const float*)d_in[3];
    const float* Wd = (const float*)d_in[4];
    const float* Wc = (const float*)d_in[5];
    float* out = (float*)d_out;
    float* logits = out + (size_t)T_TOK * H_DIM;

    // Resolve REAL device addresses of the destination symbols.
    // (Passing a __device__ symbol directly as a kernel arg passes the host
    //  shadow address — on GB300 ATS that silently writes HOST memory. This
    //  was the R4/R9 zero-output bug.)
    void *pGh, *pGl, *pUh, *pUl, *pDh, *pDl;
    cudaGetSymbolAddress(&pGh, g_WgThi);
    cudaGetSymbolAddress(&pGl, g_WgTlo);
    cudaGetSymbolAddress(&pUh, g_WuThi);
    cudaGetSymbolAddress(&pUl, g_WuTlo);
    cudaGetSymbolAddress(&pDh, g_WdThi);
    cudaGetSymbolAddress(&pDl, g_WdTlo);

    init_kernel<<<1, 32>>>();
    convert_x<<<T_TOK * H_DIM / 1024, 256>>>(X);
    transpose_wc<<<H_DIM * H_DIM / 256, 256>>>(Wc);

    {
        dim3 blk(32, 8);
        // Wg/Wu: [e][H][I] -> [e][I][H]
        tsplit<<<dim3(I_DIM / 32, H_DIM / 32, E_NUM), blk>>>(
            Wg, (__nv_bfloat16*)pGh, (__nv_bfloat16*)pGl, H_DIM, I_DIM);
        tsplit<<<dim3(I_DIM / 32, H_DIM / 32, E_NUM), blk>>>(
            Wu, (__nv_bfloat16*)pUh, (__nv_bfloat16*)pUl, H_DIM, I_DIM);
        // Wd: [e][I][O] -> [e][O][I]
        tsplit<<<dim3(O_DIM / 32, I_DIM / 32, E_NUM), blk>>>(
            Wd, (__nv_bfloat16*)pDh, (__nv_bfloat16*)pDl, I_DIM, O_DIM);
    }

    router_gemm<<<T_TOK / 8, 256>>>(X, Wr, logits);
    route_kernel<<<T_TOK / 256, 256>>>(logits);
    prefix_kernel<<<1, 32>>>();

    gemm1_kernel<<<dim3(I_DIM / 64, CAP / 128, E_NUM), 256>>>();
    gemm2_kernel<<<dim3(O_DIM / 64, CAP / 128, E_NUM), 256>>>();

    combine_kernel<<<T_TOK, 256>>>();
    gemm3_kernel<<<dim3(H_DIM / 64, T_TOK / 128), 256>>>(out);
}

// round 11
// speedup vs baseline: 1.7922x; 1.1802x over previous
#include <cuda_runtime.h>
#include <cuda_bf16.h>
#include <math.h>
#include <stdint.h>

// Problem constants
#define T_TOK 2048
#define H_DIM 1024
#define E_NUM 32
#define I_DIM 256
#define O_DIM 512
#define TOPK  4
#define CAP   2048
#define TOT_ROWS (T_TOK*TOPK)   // 8192

#define RS 40   // smem row stride (bf16 elems) for mma tiles

// dynamic smem stage sizes (bytes)
#define G1_STG 40960            // A(hi+lo) 2*10240 + B(Gh,Gl,Uh,Ul) 4*5120
#define G1_SMEM (2*G1_STG + 512)
#define G2_STG 30720            // A(hi+lo) 2*10240 + B(hi,lo) 2*5120
#define G2_SMEM (2*G2_STG)
#define G3_STG 30720
#define G3_SMEM (2*G3_STG)

// ---------------- scratch (device globals; no allocation) --------------------
__device__ int   g_cnt[E_NUM];
__device__ int   g_off[E_NUM];
__device__ int   g_bucket[E_NUM * CAP];
__device__ int   g_slot_e[T_TOK * TOPK];
__device__ int   g_slot_r[T_TOK * TOPK];
__device__ float g_slot_w[T_TOK * TOPK];
__device__ float g_Y[TOT_ROWS * O_DIM];

__device__ __align__(256) __nv_bfloat16 g_Xhi[T_TOK * H_DIM];
__device__ __align__(256) __nv_bfloat16 g_Xlo[T_TOK * H_DIM];
__device__ __align__(256) __nv_bfloat16 g_Hhi[(TOT_ROWS + 128) * I_DIM];
__device__ __align__(256) __nv_bfloat16 g_Hlo[(TOT_ROWS + 128) * I_DIM];
__device__ __align__(256) __nv_bfloat16 g_phi[T_TOK * H_DIM];
__device__ __align__(256) __nv_bfloat16 g_plo[T_TOK * H_DIM];
__device__ __align__(256) __nv_bfloat16 g_WcThi[H_DIM * H_DIM];
__device__ __align__(256) __nv_bfloat16 g_WcTlo[H_DIM * H_DIM];
// pre-split transposed weights [e][n][k]
__device__ __align__(256) __nv_bfloat16 g_WgThi[E_NUM * I_DIM * H_DIM];
__device__ __align__(256) __nv_bfloat16 g_WgTlo[E_NUM * I_DIM * H_DIM];
__device__ __align__(256) __nv_bfloat16 g_WuThi[E_NUM * I_DIM * H_DIM];
__device__ __align__(256) __nv_bfloat16 g_WuTlo[E_NUM * I_DIM * H_DIM];
__device__ __align__(256) __nv_bfloat16 g_WdThi[E_NUM * O_DIM * I_DIM];
__device__ __align__(256) __nv_bfloat16 g_WdTlo[E_NUM * O_DIM * I_DIM];

// ---------------- helpers ----------------------------------------------------
__device__ __forceinline__ void split2(float x, __nv_bfloat16& h, __nv_bfloat16& l) {
    h = __float2bfloat16_rn(x);
    l = __float2bfloat16_rn(x - __bfloat162float(h));
}

__device__ __forceinline__ void mma16816(float* c, const uint32_t* a, const uint32_t* b) {
    asm volatile(
        "mma.sync.aligned.m16n8k16.row.col.f32.bf16.bf16.f32 "
        "{%0,%1,%2,%3}, {%4,%5,%6,%7}, {%8,%9}, {%0,%1,%2,%3};"
        : "+f"(c[0]), "+f"(c[1]), "+f"(c[2]), "+f"(c[3])
        : "r"(a[0]), "r"(a[1]), "r"(a[2]), "r"(a[3]), "r"(b[0]), "r"(b[1]));
}

__device__ __forceinline__ void ldfragA(uint32_t* a, const uint16_t* S, int mrow,
                                        int kk, int qr, int qc) {
    const uint16_t* p = S + (mrow + qr) * RS + kk + qc * 2;
    a[0] = *(const uint32_t*)p;
    a[1] = *(const uint32_t*)(p + 8 * RS);
    a[2] = *(const uint32_t*)(p + 8);
    a[3] = *(const uint32_t*)(p + 8 * RS + 8);
}
__device__ __forceinline__ void ldfragB(uint32_t* b, const uint16_t* S, int nrow,
                                        int kk, int qr, int qc) {
    const uint16_t* p = S + (nrow + qr) * RS + kk + qc * 2;
    b[0] = *(const uint32_t*)p;
    b[1] = *(const uint32_t*)(p + 8);
}

__device__ __forceinline__ void cpa16(uint32_t s, const void* g) {
    asm volatile("cp.async.ca.shared.global [%0], [%1], 16;" :: "r"(s), "l"(g));
}
#define CP_COMMIT() asm volatile("cp.async.commit_group;")
#define CP_WAIT1()  asm volatile("cp.async.wait_group 1;")
#define CP_WAIT0()  asm volatile("cp.async.wait_group 0;")

// ---------------- init -------------------------------------------------------
__global__ void init_kernel() {
    if (threadIdx.x < E_NUM) g_cnt[threadIdx.x] = 0;
}

// ---------------- convert X -> bf16 hi/lo (verified) --------------------------
__global__ __launch_bounds__(256) void convert_x(const float* __restrict__ X) {
    int idx = (blockIdx.x * 256 + threadIdx.x) * 4;
    float4 v = *(const float4*)(X + idx);
    __nv_bfloat16 h0, l0, h1, l1, h2, l2, h3, l3;
    split2(v.x, h0, l0); split2(v.y, h1, l1); split2(v.z, h2, l2); split2(v.w, h3, l3);
    __nv_bfloat162 a, b;
    a.x = h0; a.y = h1; b.x = h2; b.y = h3;
    *(__nv_bfloat162*)(g_Xhi + idx) = a; *(__nv_bfloat162*)(g_Xhi + idx + 2) = b;
    a.x = l0; a.y = l1; b.x = l2; b.y = l3;
    *(__nv_bfloat162*)(g_Xlo + idx) = a; *(__nv_bfloat162*)(g_Xlo + idx + 2) = b;
}

// ---------------- tiled transpose+split (verified): dst[c][r] = src[r][c] ----
__global__ void tsplit(const float* __restrict__ src,
                       __nv_bfloat16* __restrict__ dhi,
                       __nv_bfloat16* __restrict__ dlo,
                       int R, int C) {
    size_t eoff = (size_t)blockIdx.z * R * C;
    __shared__ float t[32][33];
    int c0 = blockIdx.x * 32, r0 = blockIdx.y * 32;
    int tx = threadIdx.x, ty = threadIdx.y;
#pragma unroll
    for (int i = 0; i < 4; i++)
        t[ty + i * 8][tx] = src[eoff + (size_t)(r0 + ty + i * 8) * C + c0 + tx];
    __syncthreads();
#pragma unroll
    for (int i = 0; i < 4; i++) {
        float v = t[tx][ty + i * 8];
        __nv_bfloat16 h, l; split2(v, h, l);
        size_t o = eoff + (size_t)(c0 + ty + i * 8) * R + r0 + tx;
        dhi[o] = h; dlo[o] = l;
    }
}

// ---------------- K1: router logits (fp32, exact) ----------------------------
__global__ __launch_bounds__(256) void router_gemm(const float* __restrict__ X,
                                                   const float* __restrict__ Wr,
                                                   float* __restrict__ logits) {
    __shared__ float xs[8][H_DIM];
    int t0 = blockIdx.x * 8;
    for (int i = threadIdx.x; i < 8 * H_DIM; i += 256)
        xs[i >> 10][i & 1023] = X[(size_t)t0 * H_DIM + i];
    __syncthreads();
    int tl = threadIdx.x >> 5;
    int e  = threadIdx.x & 31;
    const float* xr = xs[tl];
    float acc = 0.f;
#pragma unroll 8
    for (int k = 0; k < H_DIM; k++)
        acc += xr[k] * Wr[k * E_NUM + e];
    logits[(t0 + tl) * E_NUM + e] = acc;
}

// ---------------- K2: routing ------------------------------------------------
__global__ void route_kernel(const float* __restrict__ logits) {
    int t = blockIdx.x * blockDim.x + threadIdx.x;
    if (t >= T_TOK) return;
    float s[E_NUM];
#pragma unroll
    for (int e = 0; e < E_NUM; e++) s[e] = logits[t * E_NUM + e];
    float ssum[4]; int top1[4], top2[4]; float v1a[4], v2a[4];
#pragma unroll
    for (int sh = 0; sh < 4; sh++) {
        float sum = 0.f;
#pragma unroll
        for (int j = 0; j < 8; j++) sum += s[sh * 8 + j];
        ssum[sh] = sum;
        int i1 = 0; float v1 = s[sh * 8];
#pragma unroll
        for (int j = 1; j < 8; j++) { float v = s[sh * 8 + j]; if (v > v1) { v1 = v; i1 = j; } }
        int i2 = -1; float v2 = -1e30f;
#pragma unroll
        for (int j = 0; j < 8; j++) {
            if (j == i1) continue;
            float v = s[sh * 8 + j];
            if (v > v2) { v2 = v; i2 = j; }
        }
        top1[sh] = i1; top2[sh] = i2; v1a[sh] = v1; v2a[sh] = v2;
    }
    int ch0 = (ssum[1] > ssum[0]) ? 1 : 0;
    int ch1 = (ssum[3] > ssum[2]) ? 3 : 2;
    int ce[4]; float cv[4];
    ce[0] = ch0 * 8 + top1[ch0]; cv[0] = v1a[ch0];
    ce[1] = ch0 * 8 + top2[ch0]; cv[1] = v2a[ch0];
    ce[2] = ch1 * 8 + top1[ch1]; cv[2] = v1a[ch1];
    ce[3] = ch1 * 8 + top2[ch1]; cv[3] = v2a[ch1];
    float m = cv[0];
#pragma unroll
    for (int k = 1; k < 4; k++) m = fmaxf(m, cv[k]);
    float w[4]; float wsum = 0.f;
#pragma unroll
    for (int k = 0; k < 4; k++) { w[k] = expf(cv[k] - m); wsum += w[k]; }
    float inv = 1.f / wsum;
#pragma unroll
    for (int k = 0; k < 4; k++) {
        int e = ce[k];
        int r = atomicAdd(&g_cnt[e], 1);
        g_bucket[e * CAP + r] = t;
        g_slot_e[t * TOPK + k] = e;
        g_slot_r[t * TOPK + k] = r;
        g_slot_w[t * TOPK + k] = w[k] * inv;
    }
}

__global__ void prefix_kernel() {
    if (threadIdx.x == 0) {
        int o = 0;
        for (int e = 0; e < E_NUM; e++) { g_off[e] = o; o += g_cnt[e]; }
    }
}

// ---------------- GEMM1: gate+up (mma, cp.async double-buffered) -------------
__global__ __launch_bounds__(256) void gemm1_kernel() {
    int e    = blockIdx.z;
    int rows = g_cnt[e];
    int row0 = blockIdx.y * 128;
    if (row0 >= rows) return;
    int base = g_off[e];
    int i0   = blockIdx.x * 64;

    extern __shared__ __align__(16) char sm[];
    int* toks = (int*)(sm + 2 * G1_STG);
    uint32_t sb = (uint32_t)__cvta_generic_to_shared(sm);

    int tid = threadIdx.x;
    int wid = tid >> 5, lane = tid & 31;
    int qr = lane >> 2, qc = lane & 3;
    int wm = wid & 3, wn = wid >> 2;

    for (int r = tid; r < 128; r += 256) {
        int rr = row0 + r;
        toks[r] = g_bucket[e * CAP + (rr < rows ? rr : row0)];
    }
    __syncthreads();

    const __nv_bfloat16* GHp = g_WgThi + (size_t)e * I_DIM * H_DIM + (size_t)i0 * H_DIM;
    const __nv_bfloat16* GLp = g_WgTlo + (size_t)e * I_DIM * H_DIM + (size_t)i0 * H_DIM;
    const __nv_bfloat16* UHp = g_WuThi + (size_t)e * I_DIM * H_DIM + (size_t)i0 * H_DIM;
    const __nv_bfloat16* ULp = g_WuTlo + (size_t)e * I_DIM * H_DIM + (size_t)i0 * H_DIM;

    // per-thread loader indices
    int r0a = tid >> 2, sga = tid & 3;            // A: rows tid>>2 and +64
    int rb = tid >> 2, sgb = tid & 3;             // B

    // issue loads for chunk ch into stage st
    auto issue = [&](int ch, int st) {
        int k0 = ch * 32;
        uint32_t s = sb + st * G1_STG;
#pragma unroll
        for (int h = 0; h < 2; h++) {
            int r = r0a + h * 64;
            size_t so = (size_t)toks[r] * H_DIM + k0 + sga * 8;
            uint32_t d = (uint32_t)(r * RS + sga * 8) * 2;
            cpa16(s + d, g_Xhi + so);
            cpa16(s + 10240 + d, g_Xlo + so);
        }
        {
            size_t so = (size_t)rb * H_DIM + k0 + sgb * 8;
            uint32_t d = (uint32_t)(rb * RS + sgb * 8) * 2;
            cpa16(s + 20480 + d, GHp + so);
            cpa16(s + 25600 + d, GLp + so);
            cpa16(s + 30720 + d, UHp + so);
            cpa16(s + 35840 + d, ULp + so);
        }
        CP_COMMIT();
    };

    float accG[2][4][4] = {}, accU[2][4][4] = {};

    issue(0, 0);
    for (int ch = 0; ch < 32; ch++) {
        int st = ch & 1;
        if (ch + 1 < 32) { issue(ch + 1, st ^ 1); CP_WAIT1(); }
        else             { CP_WAIT0(); }
        __syncthreads();

        const uint16_t* Ahi = (const uint16_t*)(sm + st * G1_STG);
        const uint16_t* Alo = (const uint16_t*)(sm + st * G1_STG + 10240);
        const uint16_t* Gh  = (const uint16_t*)(sm + st * G1_STG + 20480);
        const uint16_t* Gl  = (const uint16_t*)(sm + st * G1_STG + 25600);
        const uint16_t* Uh  = (const uint16_t*)(sm + st * G1_STG + 30720);
        const uint16_t* Ul  = (const uint16_t*)(sm + st * G1_STG + 35840);

#pragma unroll
        for (int kk = 0; kk < 32; kk += 16) {
            uint32_t ah[2][4], al[2][4];
#pragma unroll
            for (int i = 0; i < 2; i++) {
                ldfragA(ah[i], Ahi, wm * 32 + i * 16, kk, qr, qc);
                ldfragA(al[i], Alo, wm * 32 + i * 16, kk, qr, qc);
            }
            uint32_t bh[4][2], bl[4][2];
#pragma unroll
            for (int j = 0; j < 4; j++) {
                ldfragB(bh[j], Gh, wn * 32 + j * 8, kk, qr, qc);
                ldfragB(bl[j], Gl, wn * 32 + j * 8, kk, qr, qc);
            }
#pragma unroll
            for (int i = 0; i < 2; i++)
#pragma unroll
                for (int j = 0; j < 4; j++) {
                    mma16816(accG[i][j], ah[i], bh[j]);
                    mma16816(accG[i][j], ah[i], bl[j]);
                    mma16816(accG[i][j], al[i], bh[j]);
                }
#pragma unroll
            for (int j = 0; j < 4; j++) {
                ldfragB(bh[j], Uh, wn * 32 + j * 8, kk, qr, qc);
                ldfragB(bl[j], Ul, wn * 32 + j * 8, kk, qr, qc);
            }
#pragma unroll
            for (int i = 0; i < 2; i++)
#pragma unroll
                for (int j = 0; j < 4; j++) {
                    mma16816(accU[i][j], ah[i], bh[j]);
                    mma16816(accU[i][j], ah[i], bl[j]);
                    mma16816(accU[i][j], al[i], bh[j]);
                }
        }
        __syncthreads();
    }

#pragma unroll
    for (int i = 0; i < 2; i++) {
#pragma unroll
        for (int half = 0; half < 2; half++) {
            int rr = row0 + wm * 32 + i * 16 + qr + half * 8;
            if (rr >= rows) continue;
            size_t ro = (size_t)(base + rr) * I_DIM + i0 + wn * 32;
#pragma unroll
            for (int j = 0; j < 4; j++) {
                float g0 = accG[i][j][half * 2 + 0], g1 = accG[i][j][half * 2 + 1];
                float u0 = accU[i][j][half * 2 + 0], u1 = accU[i][j][half * 2 + 1];
                float h0 = g0 / (1.f + expf(-g0)) * u0;
                float h1 = g1 / (1.f + expf(-g1)) * u1;
                __nv_bfloat16 hh0, hl0, hh1, hl1;
                split2(h0, hh0, hl0); split2(h1, hh1, hl1);
                __nv_bfloat162 ph; ph.x = hh0; ph.y = hh1;
                __nv_bfloat162 pl; pl.x = hl0; pl.y = hl1;
                *(__nv_bfloat162*)(g_Hhi + ro + j * 8 + qc * 2) = ph;
                *(__nv_bfloat162*)(g_Hlo + ro + j * 8 + qc * 2) = pl;
            }
        }
    }
}

// ---------------- GEMM2: down proj (mma, cp.async double-buffered) -----------
__global__ __launch_bounds__(256) void gemm2_kernel() {
    int e    = blockIdx.z;
    int rows = g_cnt[e];
    int row0 = blockIdx.y * 128;
    if (row0 >= rows) return;
    int base = g_off[e];
    int o0   = blockIdx.x * 64;

    extern __shared__ __align__(16) char sm[];
    uint32_t sb = (uint32_t)__cvta_generic_to_shared(sm);

    int tid = threadIdx.x;
    int wid = tid >> 5, lane = tid & 31;
    int qr = lane >> 2, qc = lane & 3;
    int wm = wid & 3, wn = wid >> 2;

    const __nv_bfloat16* BHp = g_WdThi + (size_t)e * O_DIM * I_DIM + (size_t)o0 * I_DIM;
    const __nv_bfloat16* BLp = g_WdTlo + (size_t)e * O_DIM * I_DIM + (size_t)o0 * I_DIM;

    int r0a = tid >> 2, sga = tid & 3;
    int rb = tid >> 2, sgb = tid & 3;
    int arow0 = row0 + r0a;      if (arow0 >= rows) arow0 = rows - 1;
    int arow1 = row0 + r0a + 64; if (arow1 >= rows) arow1 = rows - 1;

    auto issue = [&](int ch, int st) {
        int k0 = ch * 32;
        uint32_t s = sb + st * G2_STG;
        {
            size_t so = (size_t)(base + arow0) * I_DIM + k0 + sga * 8;
            uint32_t d = (uint32_t)(r0a * RS + sga * 8) * 2;
            cpa16(s + d, g_Hhi + so);
            cpa16(s + 10240 + d, g_Hlo + so);
            so = (size_t)(base + arow1) * I_DIM + k0 + sga * 8;
            d = (uint32_t)((r0a + 64) * RS + sga * 8) * 2;
            cpa16(s + d, g_Hhi + so);
            cpa16(s + 10240 + d, g_Hlo + so);
        }
        {
            size_t so = (size_t)rb * I_DIM + k0 + sgb * 8;
            uint32_t d = (uint32_t)(rb * RS + sgb * 8) * 2;
            cpa16(s + 20480 + d, BHp + so);
            cpa16(s + 25600 + d, BLp + so);
        }
        CP_COMMIT();
    };

    float acc[2][4][4] = {};

    issue(0, 0);
    for (int ch = 0; ch < 8; ch++) {
        int st = ch & 1;
        if (ch + 1 < 8) { issue(ch + 1, st ^ 1); CP_WAIT1(); }
        else            { CP_WAIT0(); }
        __syncthreads();

        const uint16_t* Ahi = (const uint16_t*)(sm + st * G2_STG);
        const uint16_t* Alo = (const uint16_t*)(sm + st * G2_STG + 10240);
        const uint16_t* Bh  = (const uint16_t*)(sm + st * G2_STG + 20480);
        const uint16_t* Bl  = (const uint16_t*)(sm + st * G2_STG + 25600);

#pragma unroll
        for (int kk = 0; kk < 32; kk += 16) {
            uint32_t ah[2][4], al[2][4];
#pragma unroll
            for (int i = 0; i < 2; i++) {
                ldfragA(ah[i], Ahi, wm * 32 + i * 16, kk, qr, qc);
                ldfragA(al[i], Alo, wm * 32 + i * 16, kk, qr, qc);
            }
            uint32_t bh[4][2], bl[4][2];
#pragma unroll
            for (int j = 0; j < 4; j++) {
                ldfragB(bh[j], Bh, wn * 32 + j * 8, kk, qr, qc);
                ldfragB(bl[j], Bl, wn * 32 + j * 8, kk, qr, qc);
            }
#pragma unroll
            for (int i = 0; i < 2; i++)
#pragma unroll
                for (int j = 0; j < 4; j++) {
                    mma16816(acc[i][j], ah[i], bh[j]);
                    mma16816(acc[i][j], ah[i], bl[j]);
                    mma16816(acc[i][j], al[i], bh[j]);
                }
        }
        __syncthreads();
    }

#pragma unroll
    for (int i = 0; i < 2; i++) {
#pragma unroll
        for (int half = 0; half < 2; half++) {
            int rr = row0 + wm * 32 + i * 16 + qr + half * 8;
            if (rr >= rows) continue;
            size_t ro = (size_t)(base + rr) * O_DIM + o0 + wn * 32;
#pragma unroll
            for (int j = 0; j < 4; j++) {
                float2 v;
                v.x = acc[i][j][half * 2 + 0];
                v.y = acc[i][j][half * 2 + 1];
                *(float2*)(g_Y + ro + j * 8 + qc * 2) = v;
            }
        }
    }
}

// ---------------- K5: combine + split (fused, verified) ----------------------
__global__ void combine_kernel() {
    int t = blockIdx.x;
    __shared__ int   se[TOPK];
    __shared__ int   sr[TOPK];
    __shared__ float sw[TOPK];
    if (threadIdx.x < TOPK) {
        int e = g_slot_e[t * TOPK + threadIdx.x];
        se[threadIdx.x] = e;
        sr[threadIdx.x] = g_off[e] + g_slot_r[t * TOPK + threadIdx.x];
        sw[threadIdx.x] = g_slot_w[t * TOPK + threadIdx.x];
    }
    __syncthreads();
    for (int c = threadIdx.x; c < H_DIM; c += blockDim.x) {
        int g = c >> 9;
        int o = c & 511;
        float acc = 0.f;
#pragma unroll
        for (int s = 0; s < TOPK; s++)
            if ((se[s] >> 4) == g)
                acc += sw[s] * g_Y[(size_t)sr[s] * O_DIM + o];
        __nv_bfloat16 h, l; split2(acc, h, l);
        g_phi[(size_t)t * H_DIM + c] = h;
        g_plo[(size_t)t * H_DIM + c] = l;
    }
}

// ---------------- GEMM3 (mma, cp.async double-buffered) ----------------------
__global__ __launch_bounds__(256) void gemm3_kernel(float* __restrict__ out) {
    int row0 = blockIdx.y * 128;
    int j0   = blockIdx.x * 64;

    extern __shared__ __align__(16) char sm[];
    uint32_t sb = (uint32_t)__cvta_generic_to_shared(sm);

    int tid = threadIdx.x;
    int wid = tid >> 5, lane = tid & 31;
    int qr = lane >> 2, qc = lane & 3;
    int wm = wid & 3, wn = wid >> 2;

    const __nv_bfloat16* BHp = g_WcThi + (size_t)j0 * H_DIM;
    const __nv_bfloat16* BLp = g_WcTlo + (size_t)j0 * H_DIM;

    int r0a = tid >> 2, sga = tid & 3;
    int rb = tid >> 2, sgb = tid & 3;

    auto issue = [&](int ch, int st) {
        int k0 = ch * 32;
        uint32_t s = sb + st * G3_STG;
#pragma unroll
        for (int h = 0; h < 2; h++) {
            int r = r0a + h * 64;
            size_t so = (size_t)(row0 + r) * H_DIM + k0 + sga * 8;
            uint32_t d = (uint32_t)(r * RS + sga * 8) * 2;
            cpa16(s + d, g_phi + so);
            cpa16(s + 10240 + d, g_plo + so);
        }
        {
            size_t so = (size_t)rb * H_DIM + k0 + sgb * 8;
            uint32_t d = (uint32_t)(rb * RS + sgb * 8) * 2;
            cpa16(s + 20480 + d, BHp + so);
            cpa16(s + 25600 + d, BLp + so);
        }
        CP_COMMIT();
    };

    float acc[2][4][4] = {};

    issue(0, 0);
    for (int ch = 0; ch < 32; ch++) {
        int st = ch & 1;
        if (ch + 1 < 32) { issue(ch + 1, st ^ 1); CP_WAIT1(); }
        else             { CP_WAIT0(); }
        __syncthreads();

        const uint16_t* Ahi = (const uint16_t*)(sm + st * G3_STG);
        const uint16_t* Alo = (const uint16_t*)(sm + st * G3_STG + 10240);
        const uint16_t* Bh  = (const uint16_t*)(sm + st * G3_STG + 20480);
        const uint16_t* Bl  = (const uint16_t*)(sm + st * G3_STG + 25600);

#pragma unroll
        for (int kk = 0; kk < 32; kk += 16) {
            uint32_t ah[2][4], al[2][4];
#pragma unroll
            for (int i = 0; i < 2; i++) {
                ldfragA(ah[i], Ahi, wm * 32 + i * 16, kk, qr, qc);
                ldfragA(al[i], Alo, wm * 32 + i * 16, kk, qr, qc);
            }
            uint32_t bh[4][2], bl[4][2];
#pragma unroll
            for (int j = 0; j < 4; j++) {
                ldfragB(bh[j], Bh, wn * 32 + j * 8, kk, qr, qc);
                ldfragB(bl[j], Bl, wn * 32 + j * 8, kk, qr, qc);
            }
#pragma unroll
            for (int i = 0; i < 2; i++)
#pragma unroll
                for (int j = 0; j < 4; j++) {
                    mma16816(acc[i][j], ah[i], bh[j]);
                    mma16816(acc[i][j], ah[i], bl[j]);
                    mma16816(acc[i][j], al[i], bh[j]);
                }
        }
        __syncthreads();
    }

#pragma unroll
    for (int i = 0; i < 2; i++) {
#pragma unroll
        for (int half = 0; half < 2; half++) {
            int rr = row0 + wm * 32 + i * 16 + qr + half * 8;
            size_t ro = (size_t)rr * H_DIM + j0 + wn * 32;
#pragma unroll
            for (int j = 0; j < 4; j++) {
                float2 v;
                v.x = acc[i][j][half * 2 + 0];
                v.y = acc[i][j][half * 2 + 1];
                *(float2*)(out + ro + j * 8 + qc * 2) = v;
            }
        }
    }
}

// ---------------- launch -----------------------------------------------------
extern "C" void kernel_launch(void* const* d_in, const int* in_sizes, int n_in,
                              void* d_out, int out_size) {
    const float* X  = (const float*)d_in[0];
    const float* Wr = (const float*)d_in[1];
    const float* Wg = (const float*)d_in[2];
    const float* Wu = (const float*)d_in[3];
    const float* Wd = (const float*)d_in[4];
    const float* Wc = (const float*)d_in[5];
    float* out = (float*)d_out;
    float* logits = out + (size_t)T_TOK * H_DIM;

    // Resolve REAL device addresses (symbol-as-arg = host shadow addr = silent
    // ATS write to host memory on GB300; the R4/R9 bug).
    void *pGh, *pGl, *pUh, *pUl, *pDh, *pDl, *pCh, *pCl;
    cudaGetSymbolAddress(&pGh, g_WgThi);
    cudaGetSymbolAddress(&pGl, g_WgTlo);
    cudaGetSymbolAddress(&pUh, g_WuThi);
    cudaGetSymbolAddress(&pUl, g_WuTlo);
    cudaGetSymbolAddress(&pDh, g_WdThi);
    cudaGetSymbolAddress(&pDl, g_WdTlo);
    cudaGetSymbolAddress(&pCh, g_WcThi);
    cudaGetSymbolAddress(&pCl, g_WcTlo);

    cudaFuncSetAttribute(gemm1_kernel, cudaFuncAttributeMaxDynamicSharedMemorySize, G1_SMEM);
    cudaFuncSetAttribute(gemm2_kernel, cudaFuncAttributeMaxDynamicSharedMemorySize, G2_SMEM);
    cudaFuncSetAttribute(gemm3_kernel, cudaFuncAttributeMaxDynamicSharedMemorySize, G3_SMEM);

    init_kernel<<<1, 32>>>();
    convert_x<<<T_TOK * H_DIM / 1024, 256>>>(X);

    {
        dim3 blk(32, 8);
        tsplit<<<dim3(I_DIM / 32, H_DIM / 32, E_NUM), blk>>>(
            Wg, (__nv_bfloat16*)pGh, (__nv_bfloat16*)pGl, H_DIM, I_DIM);
        tsplit<<<dim3(I_DIM / 32, H_DIM / 32, E_NUM), blk>>>(
            Wu, (__nv_bfloat16*)pUh, (__nv_bfloat16*)pUl, H_DIM, I_DIM);
        tsplit<<<dim3(O_DIM / 32, I_DIM / 32, E_NUM), blk>>>(
            Wd, (__nv_bfloat16*)pDh, (__nv_bfloat16*)pDl, I_DIM, O_DIM);
        tsplit<<<dim3(H_DIM / 32, H_DIM / 32, 1), blk>>>(
            Wc, (__nv_bfloat16*)pCh, (__nv_bfloat16*)pCl, H_DIM, H_DIM);
    }

    router_gemm<<<T_TOK / 8, 256>>>(X, Wr, logits);
    route_kernel<<<T_TOK / 256, 256>>>(logits);
    prefix_kernel<<<1, 32>>>();

    gemm1_kernel<<<dim3(I_DIM / 64, CAP / 128, E_NUM), 256, G1_SMEM>>>();
    gemm2_kernel<<<dim3(O_DIM / 64, CAP / 128, E_NUM), 256, G2_SMEM>>>();

    combine_kernel<<<T_TOK, 256>>>();
    gemm3_kernel<<<dim3(H_DIM / 64, T_TOK / 128), 256, G3_SMEM>>>(out);
}

// round 12
// speedup vs baseline: 2.2166x; 1.2368x over previous
#include <cuda_runtime.h>
#include <cuda_fp16.h>
#include <math.h>
#include <stdint.h>

// Problem constants
#define T_TOK 2048
#define H_DIM 1024
#define E_NUM 32
#define I_DIM 256
#define O_DIM 512
#define TOPK  4
#define CAP   2048
#define TOT_ROWS (T_TOK*TOPK)   // 8192

#define RS 40   // smem row stride (fp16 elems) for mma tiles

// dynamic smem stage sizes (bytes)
#define G1_STG 30720            // A(hi+lo) 2*10240 + B(Gh,Uh) 2*5120
#define G1_SMEM (2*G1_STG + 512)
#define G2_STG 25600            // A(hi+lo) 2*10240 + Bh 5120
#define G2_SMEM (2*G2_STG)
#define G3_STG 25600
#define G3_SMEM (2*G3_STG)

// ---------------- scratch (device globals; no allocation) --------------------
__device__ int   g_cnt[E_NUM];
__device__ int   g_off[E_NUM];
__device__ int   g_bucket[E_NUM * CAP];
__device__ int   g_slot_e[T_TOK * TOPK];
__device__ int   g_slot_r[T_TOK * TOPK];
__device__ float g_slot_w[T_TOK * TOPK];
__device__ float g_Y[TOT_ROWS * O_DIM];

__device__ __align__(256) __half g_Xhi[T_TOK * H_DIM];
__device__ __align__(256) __half g_Xlo[T_TOK * H_DIM];
__device__ __align__(256) __half g_Hhi[(TOT_ROWS + 128) * I_DIM];
__device__ __align__(256) __half g_Hlo[(TOT_ROWS + 128) * I_DIM];
__device__ __align__(256) __half g_phi[T_TOK * H_DIM];
__device__ __align__(256) __half g_plo[T_TOK * H_DIM];
__device__ __align__(256) __half g_WcT[H_DIM * H_DIM];
// pre-split transposed weights [e][n][k], fp16 hi only
__device__ __align__(256) __half g_WgT[E_NUM * I_DIM * H_DIM];
__device__ __align__(256) __half g_WuT[E_NUM * I_DIM * H_DIM];
__device__ __align__(256) __half g_WdT[E_NUM * O_DIM * I_DIM];

// ---------------- helpers ----------------------------------------------------
__device__ __forceinline__ void split2h(float x, __half& h, __half& l) {
    h = __float2half_rn(x);
    l = __float2half_rn(x - __half2float(h));
}

__device__ __forceinline__ void mma16816(float* c, const uint32_t* a, const uint32_t* b) {
    asm volatile(
        "mma.sync.aligned.m16n8k16.row.col.f32.f16.f16.f32 "
        "{%0,%1,%2,%3}, {%4,%5,%6,%7}, {%8,%9}, {%0,%1,%2,%3};"
        : "+f"(c[0]), "+f"(c[1]), "+f"(c[2]), "+f"(c[3])
        : "r"(a[0]), "r"(a[1]), "r"(a[2]), "r"(a[3]), "r"(b[0]), "r"(b[1]));
}

__device__ __forceinline__ void ldfragA(uint32_t* a, const uint16_t* S, int mrow,
                                        int kk, int qr, int qc) {
    const uint16_t* p = S + (mrow + qr) * RS + kk + qc * 2;
    a[0] = *(const uint32_t*)p;
    a[1] = *(const uint32_t*)(p + 8 * RS);
    a[2] = *(const uint32_t*)(p + 8);
    a[3] = *(const uint32_t*)(p + 8 * RS + 8);
}
__device__ __forceinline__ void ldfragB(uint32_t* b, const uint16_t* S, int nrow,
                                        int kk, int qr, int qc) {
    const uint16_t* p = S + (nrow + qr) * RS + kk + qc * 2;
    b[0] = *(const uint32_t*)p;
    b[1] = *(const uint32_t*)(p + 8);
}

__device__ __forceinline__ void cpa16(uint32_t s, const void* g) {
    asm volatile("cp.async.ca.shared.global [%0], [%1], 16;" :: "r"(s), "l"(g));
}
#define CP_COMMIT() asm volatile("cp.async.commit_group;")
#define CP_WAIT1()  asm volatile("cp.async.wait_group 1;")
#define CP_WAIT0()  asm volatile("cp.async.wait_group 0;")

// ---------------- init -------------------------------------------------------
__global__ void init_kernel() {
    if (threadIdx.x < E_NUM) g_cnt[threadIdx.x] = 0;
}

// ---------------- convert X -> fp16 hi/lo (verified pattern) ------------------
__global__ __launch_bounds__(256) void convert_x(const float* __restrict__ X) {
    int idx = (blockIdx.x * 256 + threadIdx.x) * 4;
    float4 v = *(const float4*)(X + idx);
    __half h0, l0, h1, l1, h2, l2, h3, l3;
    split2h(v.x, h0, l0); split2h(v.y, h1, l1); split2h(v.z, h2, l2); split2h(v.w, h3, l3);
    __half2 a, b;
    a.x = h0; a.y = h1; b.x = h2; b.y = h3;
    *(__half2*)(g_Xhi + idx) = a; *(__half2*)(g_Xhi + idx + 2) = b;
    a.x = l0; a.y = l1; b.x = l2; b.y = l3;
    *(__half2*)(g_Xlo + idx) = a; *(__half2*)(g_Xlo + idx + 2) = b;
}

// ---------------- tiled transpose (verified structure): dst[c][r] = fp16(src[r][c])
__global__ void tsplit(const float* __restrict__ src,
                       __half* __restrict__ dhi,
                       int R, int C) {
    size_t eoff = (size_t)blockIdx.z * R * C;
    __shared__ float t[32][33];
    int c0 = blockIdx.x * 32, r0 = blockIdx.y * 32;
    int tx = threadIdx.x, ty = threadIdx.y;
#pragma unroll
    for (int i = 0; i < 4; i++)
        t[ty + i * 8][tx] = src[eoff + (size_t)(r0 + ty + i * 8) * C + c0 + tx];
    __syncthreads();
#pragma unroll
    for (int i = 0; i < 4; i++) {
        float v = t[tx][ty + i * 8];
        size_t o = eoff + (size_t)(c0 + ty + i * 8) * R + r0 + tx;
        dhi[o] = __float2half_rn(v);
    }
}

// ---------------- K1: router logits (fp32, exact) ----------------------------
__global__ __launch_bounds__(256) void router_gemm(const float* __restrict__ X,
                                                   const float* __restrict__ Wr,
                                                   float* __restrict__ logits) {
    __shared__ float xs[8][H_DIM];
    int t0 = blockIdx.x * 8;
    for (int i = threadIdx.x; i < 8 * H_DIM; i += 256)
        xs[i >> 10][i & 1023] = X[(size_t)t0 * H_DIM + i];
    __syncthreads();
    int tl = threadIdx.x >> 5;
    int e  = threadIdx.x & 31;
    const float* xr = xs[tl];
    float acc = 0.f;
#pragma unroll 8
    for (int k = 0; k < H_DIM; k++)
        acc += xr[k] * Wr[k * E_NUM + e];
    logits[(t0 + tl) * E_NUM + e] = acc;
}

// ---------------- K2: routing ------------------------------------------------
__global__ void route_kernel(const float* __restrict__ logits) {
    int t = blockIdx.x * blockDim.x + threadIdx.x;
    if (t >= T_TOK) return;
    float s[E_NUM];
#pragma unroll
    for (int e = 0; e < E_NUM; e++) s[e] = logits[t * E_NUM + e];
    float ssum[4]; int top1[4], top2[4]; float v1a[4], v2a[4];
#pragma unroll
    for (int sh = 0; sh < 4; sh++) {
        float sum = 0.f;
#pragma unroll
        for (int j = 0; j < 8; j++) sum += s[sh * 8 + j];
        ssum[sh] = sum;
        int i1 = 0; float v1 = s[sh * 8];
#pragma unroll
        for (int j = 1; j < 8; j++) { float v = s[sh * 8 + j]; if (v > v1) { v1 = v; i1 = j; } }
        int i2 = -1; float v2 = -1e30f;
#pragma unroll
        for (int j = 0; j < 8; j++) {
            if (j == i1) continue;
            float v = s[sh * 8 + j];
            if (v > v2) { v2 = v; i2 = j; }
        }
        top1[sh] = i1; top2[sh] = i2; v1a[sh] = v1; v2a[sh] = v2;
    }
    int ch0 = (ssum[1] > ssum[0]) ? 1 : 0;
    int ch1 = (ssum[3] > ssum[2]) ? 3 : 2;
    int ce[4]; float cv[4];
    ce[0] = ch0 * 8 + top1[ch0]; cv[0] = v1a[ch0];
    ce[1] = ch0 * 8 + top2[ch0]; cv[1] = v2a[ch0];
    ce[2] = ch1 * 8 + top1[ch1]; cv[2] = v1a[ch1];
    ce[3] = ch1 * 8 + top2[ch1]; cv[3] = v2a[ch1];
    float m = cv[0];
#pragma unroll
    for (int k = 1; k < 4; k++) m = fmaxf(m, cv[k]);
    float w[4]; float wsum = 0.f;
#pragma unroll
    for (int k = 0; k < 4; k++) { w[k] = expf(cv[k] - m); wsum += w[k]; }
    float inv = 1.f / wsum;
#pragma unroll
    for (int k = 0; k < 4; k++) {
        int e = ce[k];
        int r = atomicAdd(&g_cnt[e], 1);
        g_bucket[e * CAP + r] = t;
        g_slot_e[t * TOPK + k] = e;
        g_slot_r[t * TOPK + k] = r;
        g_slot_w[t * TOPK + k] = w[k] * inv;
    }
}

__global__ void prefix_kernel() {
    if (threadIdx.x == 0) {
        int o = 0;
        for (int e = 0; e < E_NUM; e++) { g_off[e] = o; o += g_cnt[e]; }
    }
}

// ---------------- GEMM1: gate+up (fp16 2-term, cp.async pipelined) -----------
__global__ __launch_bounds__(256) void gemm1_kernel() {
    int e    = blockIdx.z;
    int rows = g_cnt[e];
    int row0 = blockIdx.y * 128;
    if (row0 >= rows) return;
    int base = g_off[e];
    int i0   = blockIdx.x * 64;

    extern __shared__ __align__(16) char sm[];
    int* toks = (int*)(sm + 2 * G1_STG);
    uint32_t sb = (uint32_t)__cvta_generic_to_shared(sm);

    int tid = threadIdx.x;
    int wid = tid >> 5, lane = tid & 31;
    int qr = lane >> 2, qc = lane & 3;
    int wm = wid & 3, wn = wid >> 2;

    for (int r = tid; r < 128; r += 256) {
        int rr = row0 + r;
        toks[r] = g_bucket[e * CAP + (rr < rows ? rr : row0)];
    }
    __syncthreads();

    const __half* GHp = g_WgT + (size_t)e * I_DIM * H_DIM + (size_t)i0 * H_DIM;
    const __half* UHp = g_WuT + (size_t)e * I_DIM * H_DIM + (size_t)i0 * H_DIM;

    int r0a = tid >> 2, sga = tid & 3;
    int rb = tid >> 2, sgb = tid & 3;

    auto issue = [&](int ch, int st) {
        int k0 = ch * 32;
        uint32_t s = sb + st * G1_STG;
#pragma unroll
        for (int h = 0; h < 2; h++) {
            int r = r0a + h * 64;
            size_t so = (size_t)toks[r] * H_DIM + k0 + sga * 8;
            uint32_t d = (uint32_t)(r * RS + sga * 8) * 2;
            cpa16(s + d, g_Xhi + so);
            cpa16(s + 10240 + d, g_Xlo + so);
        }
        {
            size_t so = (size_t)rb * H_DIM + k0 + sgb * 8;
            uint32_t d = (uint32_t)(rb * RS + sgb * 8) * 2;
            cpa16(s + 20480 + d, GHp + so);
            cpa16(s + 25600 + d, UHp + so);
        }
        CP_COMMIT();
    };

    float accG[2][4][4] = {}, accU[2][4][4] = {};

    issue(0, 0);
    for (int ch = 0; ch < 32; ch++) {
        int st = ch & 1;
        if (ch + 1 < 32) { issue(ch + 1, st ^ 1); CP_WAIT1(); }
        else             { CP_WAIT0(); }
        __syncthreads();

        const uint16_t* Ahi = (const uint16_t*)(sm + st * G1_STG);
        const uint16_t* Alo = (const uint16_t*)(sm + st * G1_STG + 10240);
        const uint16_t* Gh  = (const uint16_t*)(sm + st * G1_STG + 20480);
        const uint16_t* Uh  = (const uint16_t*)(sm + st * G1_STG + 25600);

#pragma unroll
        for (int kk = 0; kk < 32; kk += 16) {
            uint32_t ah[2][4], al[2][4];
#pragma unroll
            for (int i = 0; i < 2; i++) {
                ldfragA(ah[i], Ahi, wm * 32 + i * 16, kk, qr, qc);
                ldfragA(al[i], Alo, wm * 32 + i * 16, kk, qr, qc);
            }
            uint32_t bh[4][2];
#pragma unroll
            for (int j = 0; j < 4; j++)
                ldfragB(bh[j], Gh, wn * 32 + j * 8, kk, qr, qc);
#pragma unroll
            for (int i = 0; i < 2; i++)
#pragma unroll
                for (int j = 0; j < 4; j++) {
                    mma16816(accG[i][j], ah[i], bh[j]);
                    mma16816(accG[i][j], al[i], bh[j]);
                }
#pragma unroll
            for (int j = 0; j < 4; j++)
                ldfragB(bh[j], Uh, wn * 32 + j * 8, kk, qr, qc);
#pragma unroll
            for (int i = 0; i < 2; i++)
#pragma unroll
                for (int j = 0; j < 4; j++) {
                    mma16816(accU[i][j], ah[i], bh[j]);
                    mma16816(accU[i][j], al[i], bh[j]);
                }
        }
        __syncthreads();
    }

    // epilogue: silu(gate)*up -> fp16 hi/lo
#pragma unroll
    for (int i = 0; i < 2; i++) {
#pragma unroll
        for (int half = 0; half < 2; half++) {
            int rr = row0 + wm * 32 + i * 16 + qr + half * 8;
            if (rr >= rows) continue;
            size_t ro = (size_t)(base + rr) * I_DIM + i0 + wn * 32;
#pragma unroll
            for (int j = 0; j < 4; j++) {
                float g0 = accG[i][j][half * 2 + 0], g1 = accG[i][j][half * 2 + 1];
                float u0 = accU[i][j][half * 2 + 0], u1 = accU[i][j][half * 2 + 1];
                float h0 = g0 / (1.f + expf(-g0)) * u0;
                float h1 = g1 / (1.f + expf(-g1)) * u1;
                __half hh0, hl0, hh1, hl1;
                split2h(h0, hh0, hl0); split2h(h1, hh1, hl1);
                __half2 ph; ph.x = hh0; ph.y = hh1;
                __half2 pl; pl.x = hl0; pl.y = hl1;
                *(__half2*)(g_Hhi + ro + j * 8 + qc * 2) = ph;
                *(__half2*)(g_Hlo + ro + j * 8 + qc * 2) = pl;
            }
        }
    }
}

// ---------------- GEMM2: down proj (fp16 2-term, cp.async pipelined) ---------
__global__ __launch_bounds__(256) void gemm2_kernel() {
    int e    = blockIdx.z;
    int rows = g_cnt[e];
    int row0 = blockIdx.y * 128;
    if (row0 >= rows) return;
    int base = g_off[e];
    int o0   = blockIdx.x * 64;

    extern __shared__ __align__(16) char sm[];
    uint32_t sb = (uint32_t)__cvta_generic_to_shared(sm);

    int tid = threadIdx.x;
    int wid = tid >> 5, lane = tid & 31;
    int qr = lane >> 2, qc = lane & 3;
    int wm = wid & 3, wn = wid >> 2;

    const __half* BHp = g_WdT + (size_t)e * O_DIM * I_DIM + (size_t)o0 * I_DIM;

    int r0a = tid >> 2, sga = tid & 3;
    int rb = tid >> 2, sgb = tid & 3;
    int arow0 = row0 + r0a;      if (arow0 >= rows) arow0 = rows - 1;
    int arow1 = row0 + r0a + 64; if (arow1 >= rows) arow1 = rows - 1;

    auto issue = [&](int ch, int st) {
        int k0 = ch * 32;
        uint32_t s = sb + st * G2_STG;
        {
            size_t so = (size_t)(base + arow0) * I_DIM + k0 + sga * 8;
            uint32_t d = (uint32_t)(r0a * RS + sga * 8) * 2;
            cpa16(s + d, g_Hhi + so);
            cpa16(s + 10240 + d, g_Hlo + so);
            so = (size_t)(base + arow1) * I_DIM + k0 + sga * 8;
            d = (uint32_t)((r0a + 64) * RS + sga * 8) * 2;
            cpa16(s + d, g_Hhi + so);
            cpa16(s + 10240 + d, g_Hlo + so);
        }
        {
            size_t so = (size_t)rb * I_DIM + k0 + sgb * 8;
            uint32_t d = (uint32_t)(rb * RS + sgb * 8) * 2;
            cpa16(s + 20480 + d, BHp + so);
        }
        CP_COMMIT();
    };

    float acc[2][4][4] = {};

    issue(0, 0);
    for (int ch = 0; ch < 8; ch++) {
        int st = ch & 1;
        if (ch + 1 < 8) { issue(ch + 1, st ^ 1); CP_WAIT1(); }
        else            { CP_WAIT0(); }
        __syncthreads();

        const uint16_t* Ahi = (const uint16_t*)(sm + st * G2_STG);
        const uint16_t* Alo = (const uint16_t*)(sm + st * G2_STG + 10240);
        const uint16_t* Bh  = (const uint16_t*)(sm + st * G2_STG + 20480);

#pragma unroll
        for (int kk = 0; kk < 32; kk += 16) {
            uint32_t ah[2][4], al[2][4];
#pragma unroll
            for (int i = 0; i < 2; i++) {
                ldfragA(ah[i], Ahi, wm * 32 + i * 16, kk, qr, qc);
                ldfragA(al[i], Alo, wm * 32 + i * 16, kk, qr, qc);
            }
            uint32_t bh[4][2];
#pragma unroll
            for (int j = 0; j < 4; j++)
                ldfragB(bh[j], Bh, wn * 32 + j * 8, kk, qr, qc);
#pragma unroll
            for (int i = 0; i < 2; i++)
#pragma unroll
                for (int j = 0; j < 4; j++) {
                    mma16816(acc[i][j], ah[i], bh[j]);
                    mma16816(acc[i][j], al[i], bh[j]);
                }
        }
        __syncthreads();
    }

#pragma unroll
    for (int i = 0; i < 2; i++) {
#pragma unroll
        for (int half = 0; half < 2; half++) {
            int rr = row0 + wm * 32 + i * 16 + qr + half * 8;
            if (rr >= rows) continue;
            size_t ro = (size_t)(base + rr) * O_DIM + o0 + wn * 32;
#pragma unroll
            for (int j = 0; j < 4; j++) {
                float2 v;
                v.x = acc[i][j][half * 2 + 0];
                v.y = acc[i][j][half * 2 + 1];
                *(float2*)(g_Y + ro + j * 8 + qc * 2) = v;
            }
        }
    }
}

// ---------------- K5: combine + split (fused, verified) ----------------------
__global__ void combine_kernel() {
    int t = blockIdx.x;
    __shared__ int   se[TOPK];
    __shared__ int   sr[TOPK];
    __shared__ float sw[TOPK];
    if (threadIdx.x < TOPK) {
        int e = g_slot_e[t * TOPK + threadIdx.x];
        se[threadIdx.x] = e;
        sr[threadIdx.x] = g_off[e] + g_slot_r[t * TOPK + threadIdx.x];
        sw[threadIdx.x] = g_slot_w[t * TOPK + threadIdx.x];
    }
    __syncthreads();
    for (int c = threadIdx.x; c < H_DIM; c += blockDim.x) {
        int g = c >> 9;
        int o = c & 511;
        float acc = 0.f;
#pragma unroll
        for (int s = 0; s < TOPK; s++)
            if ((se[s] >> 4) == g)
                acc += sw[s] * g_Y[(size_t)sr[s] * O_DIM + o];
        __half h, l; split2h(acc, h, l);
        g_phi[(size_t)t * H_DIM + c] = h;
        g_plo[(size_t)t * H_DIM + c] = l;
    }
}

// ---------------- GEMM3 (fp16 2-term, cp.async pipelined) --------------------
__global__ __launch_bounds__(256) void gemm3_kernel(float* __restrict__ out) {
    int row0 = blockIdx.y * 128;
    int j0   = blockIdx.x * 64;

    extern __shared__ __align__(16) char sm[];
    uint32_t sb = (uint32_t)__cvta_generic_to_shared(sm);

    int tid = threadIdx.x;
    int wid = tid >> 5, lane = tid & 31;
    int qr = lane >> 2, qc = lane & 3;
    int wm = wid & 3, wn = wid >> 2;

    const __half* BHp = g_WcT + (size_t)j0 * H_DIM;

    int r0a = tid >> 2, sga = tid & 3;
    int rb = tid >> 2, sgb = tid & 3;

    auto issue = [&](int ch, int st) {
        int k0 = ch * 32;
        uint32_t s = sb + st * G3_STG;
#pragma unroll
        for (int h = 0; h < 2; h++) {
            int r = r0a + h * 64;
            size_t so = (size_t)(row0 + r) * H_DIM + k0 + sga * 8;
            uint32_t d = (uint32_t)(r * RS + sga * 8) * 2;
            cpa16(s + d, g_phi + so);
            cpa16(s + 10240 + d, g_plo + so);
        }
        {
            size_t so = (size_t)rb * H_DIM + k0 + sgb * 8;
            uint32_t d = (uint32_t)(rb * RS + sgb * 8) * 2;
            cpa16(s + 20480 + d, BHp + so);
        }
        CP_COMMIT();
    };

    float acc[2][4][4] = {};

    issue(0, 0);
    for (int ch = 0; ch < 32; ch++) {
        int st = ch & 1;
        if (ch + 1 < 32) { issue(ch + 1, st ^ 1); CP_WAIT1(); }
        else             { CP_WAIT0(); }
        __syncthreads();

        const uint16_t* Ahi = (const uint16_t*)(sm + st * G3_STG);
        const uint16_t* Alo = (const uint16_t*)(sm + st * G3_STG + 10240);
        const uint16_t* Bh  = (const uint16_t*)(sm + st * G3_STG + 20480);

#pragma unroll
        for (int kk = 0; kk < 32; kk += 16) {
            uint32_t ah[2][4], al[2][4];
#pragma unroll
            for (int i = 0; i < 2; i++) {
                ldfragA(ah[i], Ahi, wm * 32 + i * 16, kk, qr, qc);
                ldfragA(al[i], Alo, wm * 32 + i * 16, kk, qr, qc);
            }
            uint32_t bh[4][2];
#pragma unroll
            for (int j = 0; j < 4; j++)
                ldfragB(bh[j], Bh, wn * 32 + j * 8, kk, qr, qc);
#pragma unroll
            for (int i = 0; i < 2; i++)
#pragma unroll
                for (int j = 0; j < 4; j++) {
                    mma16816(acc[i][j], ah[i], bh[j]);
                    mma16816(acc[i][j], al[i], bh[j]);
                }
        }
        __syncthreads();
    }

#pragma unroll
    for (int i = 0; i < 2; i++) {
#pragma unroll
        for (int half = 0; half < 2; half++) {
            int rr = row0 + wm * 32 + i * 16 + qr + half * 8;
            size_t ro = (size_t)rr * H_DIM + j0 + wn * 32;
#pragma unroll
            for (int j = 0; j < 4; j++) {
                float2 v;
                v.x = acc[i][j][half * 2 + 0];
                v.y = acc[i][j][half * 2 + 1];
                *(float2*)(out + ro + j * 8 + qc * 2) = v;
            }
        }
    }
}

// ---------------- launch -----------------------------------------------------
extern "C" void kernel_launch(void* const* d_in, const int* in_sizes, int n_in,
                              void* d_out, int out_size) {
    const float* X  = (const float*)d_in[0];
    const float* Wr = (const float*)d_in[1];
    const float* Wg = (const float*)d_in[2];
    const float* Wu = (const float*)d_in[3];
    const float* Wd = (const float*)d_in[4];
    const float* Wc = (const float*)d_in[5];
    float* out = (float*)d_out;
    float* logits = out + (size_t)T_TOK * H_DIM;

    // Resolve REAL device addresses (symbol-as-arg = host shadow addr = silent
    // ATS write to host memory on GB300; the R4/R9 bug).
    void *pG, *pU, *pD, *pC;
    cudaGetSymbolAddress(&pG, g_WgT);
    cudaGetSymbolAddress(&pU, g_WuT);
    cudaGetSymbolAddress(&pD, g_WdT);
    cudaGetSymbolAddress(&pC, g_WcT);

    cudaFuncSetAttribute(gemm1_kernel, cudaFuncAttributeMaxDynamicSharedMemorySize, G1_SMEM);
    cudaFuncSetAttribute(gemm2_kernel, cudaFuncAttributeMaxDynamicSharedMemorySize, G2_SMEM);
    cudaFuncSetAttribute(gemm3_kernel, cudaFuncAttributeMaxDynamicSharedMemorySize, G3_SMEM);

    init_kernel<<<1, 32>>>();
    convert_x<<<T_TOK * H_DIM / 1024, 256>>>(X);

    {
        dim3 blk(32, 8);
        tsplit<<<dim3(I_DIM / 32, H_DIM / 32, E_NUM), blk>>>(Wg, (__half*)pG, H_DIM, I_DIM);
        tsplit<<<dim3(I_DIM / 32, H_DIM / 32, E_NUM), blk>>>(Wu, (__half*)pU, H_DIM, I_DIM);
        tsplit<<<dim3(O_DIM / 32, I_DIM / 32, E_NUM), blk>>>(Wd, (__half*)pD, I_DIM, O_DIM);
        tsplit<<<dim3(H_DIM / 32, H_DIM / 32, 1), blk>>>(Wc, (__half*)pC, H_DIM, H_DIM);
    }

    router_gemm<<<T_TOK / 8, 256>>>(X, Wr, logits);
    route_kernel<<<T_TOK / 256, 256>>>(logits);
    prefix_kernel<<<1, 32>>>();

    gemm1_kernel<<<dim3(I_DIM / 64, CAP / 128, E_NUM), 256, G1_SMEM>>>();
    gemm2_kernel<<<dim3(O_DIM / 64, CAP / 128, E_NUM), 256, G2_SMEM>>>();

    combine_kernel<<<T_TOK, 256>>>();
    gemm3_kernel<<<dim3(H_DIM / 64, T_TOK / 128), 256, G3_SMEM>>>(out);
}

// round 14
// speedup vs baseline: 2.5064x; 1.1308x over previous
#include <cuda_runtime.h>
#include <cuda_fp16.h>
#include <math.h>
#include <stdint.h>

// Problem constants
#define T_TOK 2048
#define H_DIM 1024
#define E_NUM 32
#define I_DIM 256
#define O_DIM 512
#define TOPK  4
#define CAP   2048
#define EROWS (E_NUM*CAP)       // fixed-stride bucket rows (65536)

#define RS 40   // smem row stride (fp16 elems) -> 80B, ldmatrix conflict-free

// dynamic smem stage sizes (bytes)
#define G1_STG 30720            // Ahi 10240 | Alo 10240 | Gh 5120 | Uh 5120
#define G1_SMEM (2*G1_STG + 512)
#define G2_STG 25600            // Ahi | Alo | Bh
#define G2_SMEM (2*G2_STG)
#define G3_STG 25600
#define G3_SMEM (2*G3_STG)

// ---------------- scratch (device globals; no allocation) --------------------
__device__ int   g_cnt[E_NUM];
__device__ int   g_slot_e[T_TOK * TOPK];
__device__ int   g_slot_r[T_TOK * TOPK];
__device__ float g_slot_w[T_TOK * TOPK];
__device__ int   g_bucket[E_NUM * CAP];
__device__ float g_Y[(size_t)EROWS * O_DIM];          // 128 MB, fixed stride

__device__ __align__(256) __half g_Xhi[T_TOK * H_DIM];
__device__ __align__(256) __half g_Xlo[T_TOK * H_DIM];
__device__ __align__(256) __half g_Hhi[(size_t)EROWS * I_DIM];
__device__ __align__(256) __half g_Hlo[(size_t)EROWS * I_DIM];
__device__ __align__(256) __half g_phi[T_TOK * H_DIM];
__device__ __align__(256) __half g_plo[T_TOK * H_DIM];
__device__ __align__(256) __half g_WcT[H_DIM * H_DIM];
__device__ __align__(256) __half g_WgT[E_NUM * I_DIM * H_DIM];
__device__ __align__(256) __half g_WuT[E_NUM * I_DIM * H_DIM];
__device__ __align__(256) __half g_WdT[E_NUM * O_DIM * I_DIM];

// ---------------- helpers ----------------------------------------------------
__device__ __forceinline__ void split2h(float x, __half& h, __half& l) {
    h = __float2half_rn(x);
    l = __float2half_rn(x - __half2float(h));
}

__device__ __forceinline__ void mma16816(float* c, const uint32_t* a, const uint32_t* b) {
    asm volatile(
        "mma.sync.aligned.m16n8k16.row.col.f32.f16.f16.f32 "
        "{%0,%1,%2,%3}, {%4,%5,%6,%7}, {%8,%9}, {%0,%1,%2,%3};"
        : "+f"(c[0]), "+f"(c[1]), "+f"(c[2]), "+f"(c[3])
        : "r"(a[0]), "r"(a[1]), "r"(a[2]), "r"(a[3]), "r"(b[0]), "r"(b[1]));
}

// one warp inst: 4x m8n8 b16 matrices
__device__ __forceinline__ void ldsm4(uint32_t* r, uint32_t addr) {
    asm volatile("ldmatrix.sync.aligned.m8n8.x4.shared.b16 {%0,%1,%2,%3}, [%4];"
                 : "=r"(r[0]), "=r"(r[1]), "=r"(r[2]), "=r"(r[3]) : "r"(addr));
}

__device__ __forceinline__ void cpa16(uint32_t s, const void* g) {
    asm volatile("cp.async.ca.shared.global [%0], [%1], 16;" :: "r"(s), "l"(g));
}
#define CP_COMMIT() asm volatile("cp.async.commit_group;")
#define CP_WAIT1()  asm volatile("cp.async.wait_group 1;")
#define CP_WAIT0()  asm volatile("cp.async.wait_group 0;")

// ---------------- convert X -> fp16 hi/lo (+ init counts) --------------------
__global__ __launch_bounds__(256) void convert_x(const float* __restrict__ X) {
    if (blockIdx.x == 0 && threadIdx.x < E_NUM) g_cnt[threadIdx.x] = 0;
    int idx = (blockIdx.x * 256 + threadIdx.x) * 4;
    float4 v = *(const float4*)(X + idx);
    __half h0, l0, h1, l1, h2, l2, h3, l3;
    split2h(v.x, h0, l0); split2h(v.y, h1, l1); split2h(v.z, h2, l2); split2h(v.w, h3, l3);
    __half2 a, b;
    a.x = h0; a.y = h1; b.x = h2; b.y = h3;
    *(__half2*)(g_Xhi + idx) = a; *(__half2*)(g_Xhi + idx + 2) = b;
    a.x = l0; a.y = l1; b.x = l2; b.y = l3;
    *(__half2*)(g_Xlo + idx) = a; *(__half2*)(g_Xlo + idx + 2) = b;
}

// ---------------- fused transpose of all 4 weight tensors --------------------
// verified tsplit body, parameterized; one launch for Wg/Wu/Wd/Wc
__device__ __forceinline__ void tile_transpose(const float* src, __half* dst,
                                               int R, int C, int bx, int by, int bz) {
    size_t eoff = (size_t)bz * R * C;
    __shared__ float t[32][33];
    int c0 = bx * 32, r0 = by * 32;
    int tx = threadIdx.x, ty = threadIdx.y;
#pragma unroll
    for (int i = 0; i < 4; i++)
        t[ty + i * 8][tx] = src[eoff + (size_t)(r0 + ty + i * 8) * C + c0 + tx];
    __syncthreads();
#pragma unroll
    for (int i = 0; i < 4; i++) {
        float v = t[tx][ty + i * 8];
        size_t o = eoff + (size_t)(c0 + ty + i * 8) * R + r0 + tx;
        dst[o] = __float2half_rn(v);
    }
}

#define NG 8192   // Wg tiles: 8*32*32
#define NU 8192
#define ND 4096   // 16*8*32
#define NC 1024   // 32*32

__global__ void tsplit_all(const float* __restrict__ Wg, const float* __restrict__ Wu,
                           const float* __restrict__ Wd, const float* __restrict__ Wc,
                           __half* dG, __half* dU, __half* dD, __half* dC) {
    int id = blockIdx.x;
    if (id < NG) {
        int bx = id & 7, by = (id >> 3) & 31, bz = id >> 8;
        tile_transpose(Wg, dG, H_DIM, I_DIM, bx, by, bz);
    } else if (id < NG + NU) {
        id -= NG;
        int bx = id & 7, by = (id >> 3) & 31, bz = id >> 8;
        tile_transpose(Wu, dU, H_DIM, I_DIM, bx, by, bz);
    } else if (id < NG + NU + ND) {
        id -= NG + NU;
        int bx = id & 15, by = (id >> 4) & 7, bz = id >> 7;
        tile_transpose(Wd, dD, I_DIM, O_DIM, bx, by, bz);
    } else {
        id -= NG + NU + ND;
        int bx = id & 31, by = id >> 5;
        tile_transpose(Wc, dC, H_DIM, H_DIM, bx, by, 0);
    }
}

// ---------------- K1: router logits (fp32, exact) ----------------------------
__global__ __launch_bounds__(256) void router_gemm(const float* __restrict__ X,
                                                   const float* __restrict__ Wr,
                                                   float* __restrict__ logits) {
    __shared__ float xs[8][H_DIM];
    int t0 = blockIdx.x * 8;
    for (int i = threadIdx.x; i < 8 * H_DIM; i += 256)
        xs[i >> 10][i & 1023] = X[(size_t)t0 * H_DIM + i];
    __syncthreads();
    int tl = threadIdx.x >> 5;
    int e  = threadIdx.x & 31;
    const float* xr = xs[tl];
    float acc = 0.f;
#pragma unroll 8
    for (int k = 0; k < H_DIM; k++)
        acc += xr[k] * Wr[k * E_NUM + e];
    logits[(t0 + tl) * E_NUM + e] = acc;
}

// ---------------- K2: routing ------------------------------------------------
__global__ void route_kernel(const float* __restrict__ logits) {
    int t = blockIdx.x * blockDim.x + threadIdx.x;
    if (t >= T_TOK) return;
    float s[E_NUM];
#pragma unroll
    for (int e = 0; e < E_NUM; e++) s[e] = logits[t * E_NUM + e];
    float ssum[4]; int top1[4], top2[4]; float v1a[4], v2a[4];
#pragma unroll
    for (int sh = 0; sh < 4; sh++) {
        float sum = 0.f;
#pragma unroll
        for (int j = 0; j < 8; j++) sum += s[sh * 8 + j];
        ssum[sh] = sum;
        int i1 = 0; float v1 = s[sh * 8];
#pragma unroll
        for (int j = 1; j < 8; j++) { float v = s[sh * 8 + j]; if (v > v1) { v1 = v; i1 = j; } }
        int i2 = -1; float v2 = -1e30f;
#pragma unroll
        for (int j = 0; j < 8; j++) {
            if (j == i1) continue;
            float v = s[sh * 8 + j];
            if (v > v2) { v2 = v; i2 = j; }
        }
        top1[sh] = i1; top2[sh] = i2; v1a[sh] = v1; v2a[sh] = v2;
    }
    int ch0 = (ssum[1] > ssum[0]) ? 1 : 0;
    int ch1 = (ssum[3] > ssum[2]) ? 3 : 2;
    int ce[4]; float cv[4];
    ce[0] = ch0 * 8 + top1[ch0]; cv[0] = v1a[ch0];
    ce[1] = ch0 * 8 + top2[ch0]; cv[1] = v2a[ch0];
    ce[2] = ch1 * 8 + top1[ch1]; cv[2] = v1a[ch1];
    ce[3] = ch1 * 8 + top2[ch1]; cv[3] = v2a[ch1];
    float m = cv[0];
#pragma unroll
    for (int k = 1; k < 4; k++) m = fmaxf(m, cv[k]);
    float w[4]; float wsum = 0.f;
#pragma unroll
    for (int k = 0; k < 4; k++) { w[k] = expf(cv[k] - m); wsum += w[k]; }
    float inv = 1.f / wsum;
#pragma unroll
    for (int k = 0; k < 4; k++) {
        int e = ce[k];
        int r = atomicAdd(&g_cnt[e], 1);
        g_bucket[e * CAP + r] = t;
        g_slot_e[t * TOPK + k] = e;
        g_slot_r[t * TOPK + k] = r;
        g_slot_w[t * TOPK + k] = w[k] * inv;
    }
}

// ---------------- GEMM1: gate+up (fp16 2-term, ldmatrix, pipelined) ----------
__global__ __launch_bounds__(256) void gemm1_kernel() {
    int e    = blockIdx.z;
    int rows = g_cnt[e];
    int row0 = blockIdx.y * 128;
    if (row0 >= rows) return;
    int base = e * CAP;                     // fixed-stride bucketing
    int i0   = blockIdx.x * 64;

    extern __shared__ __align__(16) char sm[];
    int* toks = (int*)(sm + 2 * G1_STG);
    uint32_t sb = (uint32_t)__cvta_generic_to_shared(sm);

    int tid = threadIdx.x;
    int wid = tid >> 5, lane = tid & 31;
    int qr = lane >> 2, qc = lane & 3;
    int wm = wid & 3, wn = wid >> 2;

    // ldmatrix per-lane half-offsets
    int la = (lane & 15) * RS + (lane >> 4) * 8;                       // A x4
    int lb = (((lane >> 4) << 3) + (lane & 7)) * RS + ((lane >> 3) & 1) * 8; // B x4 (2 n-tiles)

    for (int r = tid; r < 128; r += 256) {
        int rr = row0 + r;
        toks[r] = g_bucket[e * CAP + (rr < rows ? rr : row0)];
    }
    __syncthreads();

    const __half* GHp = g_WgT + (size_t)e * I_DIM * H_DIM + (size_t)i0 * H_DIM;
    const __half* UHp = g_WuT + (size_t)e * I_DIM * H_DIM + (size_t)i0 * H_DIM;

    int r0a = tid >> 2, sga = tid & 3;
    int rb = tid >> 2, sgb = tid & 3;

    auto issue = [&](int ch, int st) {
        int k0 = ch * 32;
        uint32_t s = sb + st * G1_STG;
#pragma unroll
        for (int h = 0; h < 2; h++) {
            int r = r0a + h * 64;
            size_t so = (size_t)toks[r] * H_DIM + k0 + sga * 8;
            uint32_t d = (uint32_t)(r * RS + sga * 8) * 2;
            cpa16(s + d, g_Xhi + so);
            cpa16(s + 10240 + d, g_Xlo + so);
        }
        {
            size_t so = (size_t)rb * H_DIM + k0 + sgb * 8;
            uint32_t d = (uint32_t)(rb * RS + sgb * 8) * 2;
            cpa16(s + 20480 + d, GHp + so);
            cpa16(s + 25600 + d, UHp + so);
        }
        CP_COMMIT();
    };

    float accG[2][4][4] = {}, accU[2][4][4] = {};

    issue(0, 0);
    for (int ch = 0; ch < 32; ch++) {
        int st = ch & 1;
        if (ch + 1 < 32) { issue(ch + 1, st ^ 1); CP_WAIT1(); }
        else             { CP_WAIT0(); }
        __syncthreads();

        uint32_t sA  = sb + st * G1_STG;
        uint32_t sAl = sA + 10240;
        uint32_t sG  = sA + 20480;
        uint32_t sU  = sA + 25600;

#pragma unroll
        for (int kk = 0; kk < 32; kk += 16) {
            uint32_t ah[2][4], al[2][4];
#pragma unroll
            for (int i = 0; i < 2; i++) {
                uint32_t off = 2u * ((wm * 32 + i * 16) * RS + kk + la);
                ldsm4(ah[i], sA + off);
                ldsm4(al[i], sAl + off);
            }
            uint32_t bg[2][4];
#pragma unroll
            for (int jp = 0; jp < 2; jp++)
                ldsm4(bg[jp], sG + 2u * ((wn * 32 + jp * 16) * RS + kk + lb));
#pragma unroll
            for (int i = 0; i < 2; i++)
#pragma unroll
                for (int j = 0; j < 4; j++) {
                    const uint32_t* bf = &bg[j >> 1][(j & 1) * 2];
                    mma16816(accG[i][j], ah[i], bf);
                    mma16816(accG[i][j], al[i], bf);
                }
#pragma unroll
            for (int jp = 0; jp < 2; jp++)
                ldsm4(bg[jp], sU + 2u * ((wn * 32 + jp * 16) * RS + kk + lb));
#pragma unroll
            for (int i = 0; i < 2; i++)
#pragma unroll
                for (int j = 0; j < 4; j++) {
                    const uint32_t* bf = &bg[j >> 1][(j & 1) * 2];
                    mma16816(accU[i][j], ah[i], bf);
                    mma16816(accU[i][j], al[i], bf);
                }
        }
        __syncthreads();
    }

    // epilogue: silu(gate)*up -> fp16 hi/lo
#pragma unroll
    for (int i = 0; i < 2; i++) {
#pragma unroll
        for (int half = 0; half < 2; half++) {
            int rr = row0 + wm * 32 + i * 16 + qr + half * 8;
            if (rr >= rows) continue;
            size_t ro = (size_t)(base + rr) * I_DIM + i0 + wn * 32;
#pragma unroll
            for (int j = 0; j < 4; j++) {
                float g0 = accG[i][j][half * 2 + 0], g1 = accG[i][j][half * 2 + 1];
                float u0 = accU[i][j][half * 2 + 0], u1 = accU[i][j][half * 2 + 1];
                float h0 = g0 / (1.f + expf(-g0)) * u0;
                float h1 = g1 / (1.f + expf(-g1)) * u1;
                __half hh0, hl0, hh1, hl1;
                split2h(h0, hh0, hl0); split2h(h1, hh1, hl1);
                __half2 ph; ph.x = hh0; ph.y = hh1;
                __half2 pl; pl.x = hl0; pl.y = hl1;
                *(__half2*)(g_Hhi + ro + j * 8 + qc * 2) = ph;
                *(__half2*)(g_Hlo + ro + j * 8 + qc * 2) = pl;
            }
        }
    }
}

// ---------------- GEMM2: down proj (fp16 2-term, ldmatrix, pipelined) --------
__global__ __launch_bounds__(256) void gemm2_kernel() {
    int e    = blockIdx.z;
    int rows = g_cnt[e];
    int row0 = blockIdx.y * 128;
    if (row0 >= rows) return;
    int base = e * CAP;
    int o0   = blockIdx.x * 64;

    extern __shared__ __align__(16) char sm[];
    uint32_t sb = (uint32_t)__cvta_generic_to_shared(sm);

    int tid = threadIdx.x;
    int wid = tid >> 5, lane = tid & 31;
    int qr = lane >> 2, qc = lane & 3;
    int wm = wid & 3, wn = wid >> 2;

    int la = (lane & 15) * RS + (lane >> 4) * 8;
    int lb = (((lane >> 4) << 3) + (lane & 7)) * RS + ((lane >> 3) & 1) * 8;

    const __half* BHp = g_WdT + (size_t)e * O_DIM * I_DIM + (size_t)o0 * I_DIM;

    int r0a = tid >> 2, sga = tid & 3;
    int rb = tid >> 2, sgb = tid & 3;
    int arow0 = row0 + r0a;      if (arow0 >= rows) arow0 = rows - 1;
    int arow1 = row0 + r0a + 64; if (arow1 >= rows) arow1 = rows - 1;

    auto issue = [&](int ch, int st) {
        int k0 = ch * 32;
        uint32_t s = sb + st * G2_STG;
        {
            size_t so = (size_t)(base + arow0) * I_DIM + k0 + sga * 8;
            uint32_t d = (uint32_t)(r0a * RS + sga * 8) * 2;
            cpa16(s + d, g_Hhi + so);
            cpa16(s + 10240 + d, g_Hlo + so);
            so = (size_t)(base + arow1) * I_DIM + k0 + sga * 8;
            d = (uint32_t)((r0a + 64) * RS + sga * 8) * 2;
            cpa16(s + d, g_Hhi + so);
            cpa16(s + 10240 + d, g_Hlo + so);
        }
        {
            size_t so = (size_t)rb * I_DIM + k0 + sgb * 8;
            uint32_t d = (uint32_t)(rb * RS + sgb * 8) * 2;
            cpa16(s + 20480 + d, BHp + so);
        }
        CP_COMMIT();
    };

    float acc[2][4][4] = {};

    issue(0, 0);
    for (int ch = 0; ch < 8; ch++) {
        int st = ch & 1;
        if (ch + 1 < 8) { issue(ch + 1, st ^ 1); CP_WAIT1(); }
        else            { CP_WAIT0(); }
        __syncthreads();

        uint32_t sA  = sb + st * G2_STG;
        uint32_t sAl = sA + 10240;
        uint32_t sB  = sA + 20480;

#pragma unroll
        for (int kk = 0; kk < 32; kk += 16) {
            uint32_t ah[2][4], al[2][4];
#pragma unroll
            for (int i = 0; i < 2; i++) {
                uint32_t off = 2u * ((wm * 32 + i * 16) * RS + kk + la);
                ldsm4(ah[i], sA + off);
                ldsm4(al[i], sAl + off);
            }
            uint32_t bg[2][4];
#pragma unroll
            for (int jp = 0; jp < 2; jp++)
                ldsm4(bg[jp], sB + 2u * ((wn * 32 + jp * 16) * RS + kk + lb));
#pragma unroll
            for (int i = 0; i < 2; i++)
#pragma unroll
                for (int j = 0; j < 4; j++) {
                    const uint32_t* bf = &bg[j >> 1][(j & 1) * 2];
                    mma16816(acc[i][j], ah[i], bf);
                    mma16816(acc[i][j], al[i], bf);
                }
        }
        __syncthreads();
    }

#pragma unroll
    for (int i = 0; i < 2; i++) {
#pragma unroll
        for (int half = 0; half < 2; half++) {
            int rr = row0 + wm * 32 + i * 16 + qr + half * 8;
            if (rr >= rows) continue;
            size_t ro = (size_t)(base + rr) * O_DIM + o0 + wn * 32;
#pragma unroll
            for (int j = 0; j < 4; j++) {
                float2 v;
                v.x = acc[i][j][half * 2 + 0];
                v.y = acc[i][j][half * 2 + 1];
                *(float2*)(g_Y + ro + j * 8 + qc * 2) = v;
            }
        }
    }
}

// ---------------- combine + split (fused, verified) --------------------------
__global__ void combine_kernel() {
    int t = blockIdx.x;
    __shared__ int   se[TOPK];
    __shared__ int   sr[TOPK];
    __shared__ float sw[TOPK];
    if (threadIdx.x < TOPK) {
        int e = g_slot_e[t * TOPK + threadIdx.x];
        se[threadIdx.x] = e;
        sr[threadIdx.x] = e * CAP + g_slot_r[t * TOPK + threadIdx.x];
        sw[threadIdx.x] = g_slot_w[t * TOPK + threadIdx.x];
    }
    __syncthreads();
    for (int c = threadIdx.x; c < H_DIM; c += blockDim.x) {
        int g = c >> 9;
        int o = c & 511;
        float acc = 0.f;
#pragma unroll
        for (int s = 0; s < TOPK; s++)
            if ((se[s] >> 4) == g)
                acc += sw[s] * g_Y[(size_t)sr[s] * O_DIM + o];
        __half h, l; split2h(acc, h, l);
        g_phi[(size_t)t * H_DIM + c] = h;
        g_plo[(size_t)t * H_DIM + c] = l;
    }
}

// ---------------- GEMM3 (fp16 2-term, ldmatrix, pipelined) -------------------
__global__ __launch_bounds__(256) void gemm3_kernel(float* __restrict__ out) {
    int row0 = blockIdx.y * 128;
    int j0   = blockIdx.x * 64;

    extern __shared__ __align__(16) char sm[];
    uint32_t sb = (uint32_t)__cvta_generic_to_shared(sm);

    int tid = threadIdx.x;
    int wid = tid >> 5, lane = tid & 31;
    int qr = lane >> 2, qc = lane & 3;
    int wm = wid & 3, wn = wid >> 2;

    int la = (lane & 15) * RS + (lane >> 4) * 8;
    int lb = (((lane >> 4) << 3) + (lane & 7)) * RS + ((lane >> 3) & 1) * 8;

    const __half* BHp = g_WcT + (size_t)j0 * H_DIM;

    int r0a = tid >> 2, sga = tid & 3;
    int rb = tid >> 2, sgb = tid & 3;

    auto issue = [&](int ch, int st) {
        int k0 = ch * 32;
        uint32_t s = sb + st * G3_STG;
#pragma unroll
        for (int h = 0; h < 2; h++) {
            int r = r0a + h * 64;
            size_t so = (size_t)(row0 + r) * H_DIM + k0 + sga * 8;
            uint32_t d = (uint32_t)(r * RS + sga * 8) * 2;
            cpa16(s + d, g_phi + so);
            cpa16(s + 10240 + d, g_plo + so);
        }
        {
            size_t so = (size_t)rb * H_DIM + k0 + sgb * 8;
            uint32_t d = (uint32_t)(rb * RS + sgb * 8) * 2;
            cpa16(s + 20480 + d, BHp + so);
        }
        CP_COMMIT();
    };

    float acc[2][4][4] = {};

    issue(0, 0);
    for (int ch = 0; ch < 32; ch++) {
        int st = ch & 1;
        if (ch + 1 < 32) { issue(ch + 1, st ^ 1); CP_WAIT1(); }
        else             { CP_WAIT0(); }
        __syncthreads();

        uint32_t sA  = sb + st * G3_STG;
        uint32_t sAl = sA + 10240;
        uint32_t sB  = sA + 20480;

#pragma unroll
        for (int kk = 0; kk < 32; kk += 16) {
            uint32_t ah[2][4], al[2][4];
#pragma unroll
            for (int i = 0; i < 2; i++) {
                uint32_t off = 2u * ((wm * 32 + i * 16) * RS + kk + la);
                ldsm4(ah[i], sA + off);
                ldsm4(al[i], sAl + off);
            }
            uint32_t bg[2][4];
#pragma unroll
            for (int jp = 0; jp < 2; jp++)
                ldsm4(bg[jp], sB + 2u * ((wn * 32 + jp * 16) * RS + kk + lb));
#pragma unroll
            for (int i = 0; i < 2; i++)
#pragma unroll
                for (int j = 0; j < 4; j++) {
                    const uint32_t* bf = &bg[j >> 1][(j & 1) * 2];
                    mma16816(acc[i][j], ah[i], bf);
                    mma16816(acc[i][j], al[i], bf);
                }
        }
        __syncthreads();
    }

#pragma unroll
    for (int i = 0; i < 2; i++) {
#pragma unroll
        for (int half = 0; half < 2; half++) {
            int rr = row0 + wm * 32 + i * 16 + qr + half * 8;
            size_t ro = (size_t)rr * H_DIM + j0 + wn * 32;
#pragma unroll
            for (int j = 0; j < 4; j++) {
                float2 v;
                v.x = acc[i][j][half * 2 + 0];
                v.y = acc[i][j][half * 2 + 1];
                *(float2*)(out + ro + j * 8 + qc * 2) = v;
            }
        }
    }
}

// ---------------- launch -----------------------------------------------------
extern "C" void kernel_launch(void* const* d_in, const int* in_sizes, int n_in,
                              void* d_out, int out_size) {
    const float* X  = (const float*)d_in[0];
    const float* Wr = (const float*)d_in[1];
    const float* Wg = (const float*)d_in[2];
    const float* Wu = (const float*)d_in[3];
    const float* Wd = (const float*)d_in[4];
    const float* Wc = (const float*)d_in[5];
    float* out = (float*)d_out;
    float* logits = out + (size_t)T_TOK * H_DIM;

    // Resolve REAL device addresses (symbol-as-arg = host shadow addr = silent
    // ATS write to host memory on GB300; the R4/R9 bug).
    void *pG, *pU, *pD, *pC;
    cudaGetSymbolAddress(&pG, g_WgT);
    cudaGetSymbolAddress(&pU, g_WuT);
    cudaGetSymbolAddress(&pD, g_WdT);
    cudaGetSymbolAddress(&pC, g_WcT);

    cudaFuncSetAttribute(gemm1_kernel, cudaFuncAttributeMaxDynamicSharedMemorySize, G1_SMEM);
    cudaFuncSetAttribute(gemm2_kernel, cudaFuncAttributeMaxDynamicSharedMemorySize, G2_SMEM);
    cudaFuncSetAttribute(gemm3_kernel, cudaFuncAttributeMaxDynamicSharedMemorySize, G3_SMEM);

    convert_x<<<T_TOK * H_DIM / 1024, 256>>>(X);

    tsplit_all<<<NG + NU + ND + NC, dim3(32, 8)>>>(
        Wg, Wu, Wd, Wc, (__half*)pG, (__half*)pU, (__half*)pD, (__half*)pC);

    router_gemm<<<T_TOK / 8, 256>>>(X, Wr, logits);
    route_kernel<<<T_TOK / 256, 256>>>(logits);

    gemm1_kernel<<<dim3(I_DIM / 64, CAP / 128, E_NUM), 256, G1_SMEM>>>();
    gemm2_kernel<<<dim3(O_DIM / 64, CAP / 128, E_NUM), 256, G2_SMEM>>>();

    combine_kernel<<<T_TOK, 256>>>();
    gemm3_kernel<<<dim3(H_DIM / 64, T_TOK / 128), 256, G3_SMEM>>>(out);
}

// round 15
// speedup vs baseline: 3.0114x; 1.2015x over previous
#include <cuda_runtime.h>
#include <cuda_fp16.h>
#include <math.h>
#include <stdint.h>

// Problem constants
#define T_TOK 2048
#define H_DIM 1024
#define E_NUM 32
#define I_DIM 256
#define O_DIM 512
#define TOPK  4
#define CAP   2048
#define EROWS (E_NUM*CAP)       // fixed-stride bucket rows (65536)

#define RS 40   // smem row stride (fp16 elems) -> 80B, ldmatrix conflict-free

// dynamic smem stage sizes (bytes)
#define G1_STG 20480            // Ahi 10240 | Gh 5120 | Uh 5120
#define G1_SMEM (2*G1_STG + 512)
#define G2_STG 15360            // Ahi 10240 | Bh 5120
#define G2_SMEM (2*G2_STG)
#define G3_STG 15360
#define G3_SMEM (2*G3_STG)

// ---------------- scratch (device globals; no allocation) --------------------
__device__ int   g_cnt[E_NUM];
__device__ int   g_slot_e[T_TOK * TOPK];
__device__ int   g_slot_r[T_TOK * TOPK];
__device__ float g_slot_w[T_TOK * TOPK];
__device__ int   g_bucket[E_NUM * CAP];
__device__ float g_Y[(size_t)EROWS * O_DIM];          // fixed stride

__device__ __align__(256) __half g_Xhi[T_TOK * H_DIM];
__device__ __align__(256) __half g_Hhi[(size_t)EROWS * I_DIM];
__device__ __align__(256) __half g_phi[T_TOK * H_DIM];
__device__ __align__(256) __half g_WcT[H_DIM * H_DIM];
__device__ __align__(256) __half g_WgT[E_NUM * I_DIM * H_DIM];
__device__ __align__(256) __half g_WuT[E_NUM * I_DIM * H_DIM];
__device__ __align__(256) __half g_WdT[E_NUM * O_DIM * I_DIM];

// ---------------- helpers ----------------------------------------------------
__device__ __forceinline__ void mma16816(float* c, const uint32_t* a, const uint32_t* b) {
    asm volatile(
        "mma.sync.aligned.m16n8k16.row.col.f32.f16.f16.f32 "
        "{%0,%1,%2,%3}, {%4,%5,%6,%7}, {%8,%9}, {%0,%1,%2,%3};"
        : "+f"(c[0]), "+f"(c[1]), "+f"(c[2]), "+f"(c[3])
        : "r"(a[0]), "r"(a[1]), "r"(a[2]), "r"(a[3]), "r"(b[0]), "r"(b[1]));
}

__device__ __forceinline__ void ldsm4(uint32_t* r, uint32_t addr) {
    asm volatile("ldmatrix.sync.aligned.m8n8.x4.shared.b16 {%0,%1,%2,%3}, [%4];"
                 : "=r"(r[0]), "=r"(r[1]), "=r"(r[2]), "=r"(r[3]) : "r"(addr));
}

__device__ __forceinline__ void cpa16(uint32_t s, const void* g) {
    asm volatile("cp.async.ca.shared.global [%0], [%1], 16;" :: "r"(s), "l"(g));
}
#define CP_COMMIT() asm volatile("cp.async.commit_group;")
#define CP_WAIT1()  asm volatile("cp.async.wait_group 1;")
#define CP_WAIT0()  asm volatile("cp.async.wait_group 0;")

// ---------------- convert X -> fp16 (+ init counts) --------------------------
__global__ __launch_bounds__(256) void convert_x(const float* __restrict__ X) {
    if (blockIdx.x == 0 && threadIdx.x < E_NUM) g_cnt[threadIdx.x] = 0;
    int idx = (blockIdx.x * 256 + threadIdx.x) * 4;
    float4 v = *(const float4*)(X + idx);
    __half2 a, b;
    a.x = __float2half_rn(v.x); a.y = __float2half_rn(v.y);
    b.x = __float2half_rn(v.z); b.y = __float2half_rn(v.w);
    *(__half2*)(g_Xhi + idx) = a;
    *(__half2*)(g_Xhi + idx + 2) = b;
}

// ---------------- fused transpose of all 4 weight tensors --------------------
__device__ __forceinline__ void tile_transpose(const float* src, __half* dst,
                                               int R, int C, int bx, int by, int bz) {
    size_t eoff = (size_t)bz * R * C;
    __shared__ float t[32][33];
    int c0 = bx * 32, r0 = by * 32;
    int tx = threadIdx.x, ty = threadIdx.y;
#pragma unroll
    for (int i = 0; i < 4; i++)
        t[ty + i * 8][tx] = src[eoff + (size_t)(r0 + ty + i * 8) * C + c0 + tx];
    __syncthreads();
#pragma unroll
    for (int i = 0; i < 4; i++) {
        float v = t[tx][ty + i * 8];
        size_t o = eoff + (size_t)(c0 + ty + i * 8) * R + r0 + tx;
        dst[o] = __float2half_rn(v);
    }
}

#define NG 8192
#define NU 8192
#define ND 4096
#define NC 1024

__global__ void tsplit_all(const float* __restrict__ Wg, const float* __restrict__ Wu,
                           const float* __restrict__ Wd, const float* __restrict__ Wc,
                           __half* dG, __half* dU, __half* dD, __half* dC) {
    int id = blockIdx.x;
    if (id < NG) {
        int bx = id & 7, by = (id >> 3) & 31, bz = id >> 8;
        tile_transpose(Wg, dG, H_DIM, I_DIM, bx, by, bz);
    } else if (id < NG + NU) {
        id -= NG;
        int bx = id & 7, by = (id >> 3) & 31, bz = id >> 8;
        tile_transpose(Wu, dU, H_DIM, I_DIM, bx, by, bz);
    } else if (id < NG + NU + ND) {
        id -= NG + NU;
        int bx = id & 15, by = (id >> 4) & 7, bz = id >> 7;
        tile_transpose(Wd, dD, I_DIM, O_DIM, bx, by, bz);
    } else {
        id -= NG + NU + ND;
        int bx = id & 31, by = id >> 5;
        tile_transpose(Wc, dC, H_DIM, H_DIM, bx, by, 0);
    }
}

// ---------------- K1: router logits (fp32, exact) ----------------------------
__global__ __launch_bounds__(256) void router_gemm(const float* __restrict__ X,
                                                   const float* __restrict__ Wr,
                                                   float* __restrict__ logits) {
    __shared__ float xs[8][H_DIM];
    int t0 = blockIdx.x * 8;
    for (int i = threadIdx.x; i < 8 * H_DIM; i += 256)
        xs[i >> 10][i & 1023] = X[(size_t)t0 * H_DIM + i];
    __syncthreads();
    int tl = threadIdx.x >> 5;
    int e  = threadIdx.x & 31;
    const float* xr = xs[tl];
    float acc = 0.f;
#pragma unroll 8
    for (int k = 0; k < H_DIM; k++)
        acc += xr[k] * Wr[k * E_NUM + e];
    logits[(t0 + tl) * E_NUM + e] = acc;
}

// ---------------- K2: routing ------------------------------------------------
__global__ void route_kernel(const float* __restrict__ logits) {
    int t = blockIdx.x * blockDim.x + threadIdx.x;
    if (t >= T_TOK) return;
    float s[E_NUM];
#pragma unroll
    for (int e = 0; e < E_NUM; e++) s[e] = logits[t * E_NUM + e];
    float ssum[4]; int top1[4], top2[4]; float v1a[4], v2a[4];
#pragma unroll
    for (int sh = 0; sh < 4; sh++) {
        float sum = 0.f;
#pragma unroll
        for (int j = 0; j < 8; j++) sum += s[sh * 8 + j];
        ssum[sh] = sum;
        int i1 = 0; float v1 = s[sh * 8];
#pragma unroll
        for (int j = 1; j < 8; j++) { float v = s[sh * 8 + j]; if (v > v1) { v1 = v; i1 = j; } }
        int i2 = -1; float v2 = -1e30f;
#pragma unroll
        for (int j = 0; j < 8; j++) {
            if (j == i1) continue;
            float v = s[sh * 8 + j];
            if (v > v2) { v2 = v; i2 = j; }
        }
        top1[sh] = i1; top2[sh] = i2; v1a[sh] = v1; v2a[sh] = v2;
    }
    int ch0 = (ssum[1] > ssum[0]) ? 1 : 0;
    int ch1 = (ssum[3] > ssum[2]) ? 3 : 2;
    int ce[4]; float cv[4];
    ce[0] = ch0 * 8 + top1[ch0]; cv[0] = v1a[ch0];
    ce[1] = ch0 * 8 + top2[ch0]; cv[1] = v2a[ch0];
    ce[2] = ch1 * 8 + top1[ch1]; cv[2] = v1a[ch1];
    ce[3] = ch1 * 8 + top2[ch1]; cv[3] = v2a[ch1];
    float m = cv[0];
#pragma unroll
    for (int k = 1; k < 4; k++) m = fmaxf(m, cv[k]);
    float w[4]; float wsum = 0.f;
#pragma unroll
    for (int k = 0; k < 4; k++) { w[k] = expf(cv[k] - m); wsum += w[k]; }
    float inv = 1.f / wsum;
#pragma unroll
    for (int k = 0; k < 4; k++) {
        int e = ce[k];
        int r = atomicAdd(&g_cnt[e], 1);
        g_bucket[e * CAP + r] = t;
        g_slot_e[t * TOPK + k] = e;
        g_slot_r[t * TOPK + k] = r;
        g_slot_w[t * TOPK + k] = w[k] * inv;
    }
}

// ---------------- GEMM1: gate+up (fp16 1-term, ldmatrix, pipelined) ----------
__global__ __launch_bounds__(256) void gemm1_kernel() {
    int e    = blockIdx.z;
    int rows = g_cnt[e];
    int row0 = blockIdx.y * 128;
    if (row0 >= rows) return;
    int base = e * CAP;
    int i0   = blockIdx.x * 64;

    extern __shared__ __align__(16) char sm[];
    int* toks = (int*)(sm + 2 * G1_STG);
    uint32_t sb = (uint32_t)__cvta_generic_to_shared(sm);

    int tid = threadIdx.x;
    int wid = tid >> 5, lane = tid & 31;
    int qr = lane >> 2, qc = lane & 3;
    int wm = wid & 3, wn = wid >> 2;

    int la = (lane & 15) * RS + (lane >> 4) * 8;
    int lb = (((lane >> 4) << 3) + (lane & 7)) * RS + ((lane >> 3) & 1) * 8;

    for (int r = tid; r < 128; r += 256) {
        int rr = row0 + r;
        toks[r] = g_bucket[e * CAP + (rr < rows ? rr : row0)];
    }
    __syncthreads();

    const __half* GHp = g_WgT + (size_t)e * I_DIM * H_DIM + (size_t)i0 * H_DIM;
    const __half* UHp = g_WuT + (size_t)e * I_DIM * H_DIM + (size_t)i0 * H_DIM;

    int r0a = tid >> 2, sga = tid & 3;
    int rb = tid >> 2, sgb = tid & 3;

    auto issue = [&](int ch, int st) {
        int k0 = ch * 32;
        uint32_t s = sb + st * G1_STG;
#pragma unroll
        for (int h = 0; h < 2; h++) {
            int r = r0a + h * 64;
            size_t so = (size_t)toks[r] * H_DIM + k0 + sga * 8;
            cpa16(s + (uint32_t)(r * RS + sga * 8) * 2, g_Xhi + so);
        }
        {
            size_t so = (size_t)rb * H_DIM + k0 + sgb * 8;
            uint32_t d = (uint32_t)(rb * RS + sgb * 8) * 2;
            cpa16(s + 10240 + d, GHp + so);
            cpa16(s + 15360 + d, UHp + so);
        }
        CP_COMMIT();
    };

    float accG[2][4][4] = {}, accU[2][4][4] = {};

    issue(0, 0);
    for (int ch = 0; ch < 32; ch++) {
        int st = ch & 1;
        if (ch + 1 < 32) { issue(ch + 1, st ^ 1); CP_WAIT1(); }
        else             { CP_WAIT0(); }
        __syncthreads();

        uint32_t sA = sb + st * G1_STG;
        uint32_t sG = sA + 10240;
        uint32_t sU = sA + 15360;

#pragma unroll
        for (int kk = 0; kk < 32; kk += 16) {
            uint32_t ah[2][4];
#pragma unroll
            for (int i = 0; i < 2; i++)
                ldsm4(ah[i], sA + 2u * ((wm * 32 + i * 16) * RS + kk + la));
            uint32_t bg[2][4];
#pragma unroll
            for (int jp = 0; jp < 2; jp++)
                ldsm4(bg[jp], sG + 2u * ((wn * 32 + jp * 16) * RS + kk + lb));
#pragma unroll
            for (int i = 0; i < 2; i++)
#pragma unroll
                for (int j = 0; j < 4; j++)
                    mma16816(accG[i][j], ah[i], &bg[j >> 1][(j & 1) * 2]);
#pragma unroll
            for (int jp = 0; jp < 2; jp++)
                ldsm4(bg[jp], sU + 2u * ((wn * 32 + jp * 16) * RS + kk + lb));
#pragma unroll
            for (int i = 0; i < 2; i++)
#pragma unroll
                for (int j = 0; j < 4; j++)
                    mma16816(accU[i][j], ah[i], &bg[j >> 1][(j & 1) * 2]);
        }
        __syncthreads();
    }

    // epilogue: silu(gate)*up -> fp16
#pragma unroll
    for (int i = 0; i < 2; i++) {
#pragma unroll
        for (int half = 0; half < 2; half++) {
            int rr = row0 + wm * 32 + i * 16 + qr + half * 8;
            if (rr >= rows) continue;
            size_t ro = (size_t)(base + rr) * I_DIM + i0 + wn * 32;
#pragma unroll
            for (int j = 0; j < 4; j++) {
                float g0 = accG[i][j][half * 2 + 0], g1 = accG[i][j][half * 2 + 1];
                float u0 = accU[i][j][half * 2 + 0], u1 = accU[i][j][half * 2 + 1];
                float h0 = g0 / (1.f + expf(-g0)) * u0;
                float h1 = g1 / (1.f + expf(-g1)) * u1;
                __half2 ph;
                ph.x = __float2half_rn(h0); ph.y = __float2half_rn(h1);
                *(__half2*)(g_Hhi + ro + j * 8 + qc * 2) = ph;
            }
        }
    }
}

// ---------------- GEMM2: down proj (fp16 1-term, ldmatrix, pipelined) --------
__global__ __launch_bounds__(256) void gemm2_kernel() {
    int e    = blockIdx.z;
    int rows = g_cnt[e];
    int row0 = blockIdx.y * 128;
    if (row0 >= rows) return;
    int base = e * CAP;
    int o0   = blockIdx.x * 64;

    extern __shared__ __align__(16) char sm[];
    uint32_t sb = (uint32_t)__cvta_generic_to_shared(sm);

    int tid = threadIdx.x;
    int wid = tid >> 5, lane = tid & 31;
    int qr = lane >> 2, qc = lane & 3;
    int wm = wid & 3, wn = wid >> 2;

    int la = (lane & 15) * RS + (lane >> 4) * 8;
    int lb = (((lane >> 4) << 3) + (lane & 7)) * RS + ((lane >> 3) & 1) * 8;

    const __half* BHp = g_WdT + (size_t)e * O_DIM * I_DIM + (size_t)o0 * I_DIM;

    int r0a = tid >> 2, sga = tid & 3;
    int rb = tid >> 2, sgb = tid & 3;
    int arow0 = row0 + r0a;      if (arow0 >= rows) arow0 = rows - 1;
    int arow1 = row0 + r0a + 64; if (arow1 >= rows) arow1 = rows - 1;

    auto issue = [&](int ch, int st) {
        int k0 = ch * 32;
        uint32_t s = sb + st * G2_STG;
        {
            size_t so = (size_t)(base + arow0) * I_DIM + k0 + sga * 8;
            cpa16(s + (uint32_t)(r0a * RS + sga * 8) * 2, g_Hhi + so);
            so = (size_t)(base + arow1) * I_DIM + k0 + sga * 8;
            cpa16(s + (uint32_t)((r0a + 64) * RS + sga * 8) * 2, g_Hhi + so);
        }
        {
            size_t so = (size_t)rb * I_DIM + k0 + sgb * 8;
            cpa16(s + 10240 + (uint32_t)(rb * RS + sgb * 8) * 2, BHp + so);
        }
        CP_COMMIT();
    };

    float acc[2][4][4] = {};

    issue(0, 0);
    for (int ch = 0; ch < 8; ch++) {
        int st = ch & 1;
        if (ch + 1 < 8) { issue(ch + 1, st ^ 1); CP_WAIT1(); }
        else            { CP_WAIT0(); }
        __syncthreads();

        uint32_t sA = sb + st * G2_STG;
        uint32_t sB = sA + 10240;

#pragma unroll
        for (int kk = 0; kk < 32; kk += 16) {
            uint32_t ah[2][4];
#pragma unroll
            for (int i = 0; i < 2; i++)
                ldsm4(ah[i], sA + 2u * ((wm * 32 + i * 16) * RS + kk + la));
            uint32_t bg[2][4];
#pragma unroll
            for (int jp = 0; jp < 2; jp++)
                ldsm4(bg[jp], sB + 2u * ((wn * 32 + jp * 16) * RS + kk + lb));
#pragma unroll
            for (int i = 0; i < 2; i++)
#pragma unroll
                for (int j = 0; j < 4; j++)
                    mma16816(acc[i][j], ah[i], &bg[j >> 1][(j & 1) * 2]);
        }
        __syncthreads();
    }

#pragma unroll
    for (int i = 0; i < 2; i++) {
#pragma unroll
        for (int half = 0; half < 2; half++) {
            int rr = row0 + wm * 32 + i * 16 + qr + half * 8;
            if (rr >= rows) continue;
            size_t ro = (size_t)(base + rr) * O_DIM + o0 + wn * 32;
#pragma unroll
            for (int j = 0; j < 4; j++) {
                float2 v;
                v.x = acc[i][j][half * 2 + 0];
                v.y = acc[i][j][half * 2 + 1];
                *(float2*)(g_Y + ro + j * 8 + qc * 2) = v;
            }
        }
    }
}

// ---------------- combine (gather, fused fp16 store) --------------------------
__global__ void combine_kernel() {
    int t = blockIdx.x;
    __shared__ int   se[TOPK];
    __shared__ int   sr[TOPK];
    __shared__ float sw[TOPK];
    if (threadIdx.x < TOPK) {
        int e = g_slot_e[t * TOPK + threadIdx.x];
        se[threadIdx.x] = e;
        sr[threadIdx.x] = e * CAP + g_slot_r[t * TOPK + threadIdx.x];
        sw[threadIdx.x] = g_slot_w[t * TOPK + threadIdx.x];
    }
    __syncthreads();
    for (int c = threadIdx.x; c < H_DIM; c += blockDim.x) {
        int g = c >> 9;
        int o = c & 511;
        float acc = 0.f;
#pragma unroll
        for (int s = 0; s < TOPK; s++)
            if ((se[s] >> 4) == g)
                acc += sw[s] * g_Y[(size_t)sr[s] * O_DIM + o];
        g_phi[(size_t)t * H_DIM + c] = __float2half_rn(acc);
    }
}

// ---------------- GEMM3 (fp16 1-term, ldmatrix, pipelined) -------------------
__global__ __launch_bounds__(256) void gemm3_kernel(float* __restrict__ out) {
    int row0 = blockIdx.y * 128;
    int j0   = blockIdx.x * 64;

    extern __shared__ __align__(16) char sm[];
    uint32_t sb = (uint32_t)__cvta_generic_to_shared(sm);

    int tid = threadIdx.x;
    int wid = tid >> 5, lane = tid & 31;
    int qr = lane >> 2, qc = lane & 3;
    int wm = wid & 3, wn = wid >> 2;

    int la = (lane & 15) * RS + (lane >> 4) * 8;
    int lb = (((lane >> 4) << 3) + (lane & 7)) * RS + ((lane >> 3) & 1) * 8;

    const __half* BHp = g_WcT + (size_t)j0 * H_DIM;

    int r0a = tid >> 2, sga = tid & 3;
    int rb = tid >> 2, sgb = tid & 3;

    auto issue = [&](int ch, int st) {
        int k0 = ch * 32;
        uint32_t s = sb + st * G3_STG;
#pragma unroll
        for (int h = 0; h < 2; h++) {
            int r = r0a + h * 64;
            size_t so = (size_t)(row0 + r) * H_DIM + k0 + sga * 8;
            cpa16(s + (uint32_t)(r * RS + sga * 8) * 2, g_phi + so);
        }
        {
            size_t so = (size_t)rb * H_DIM + k0 + sgb * 8;
            cpa16(s + 10240 + (uint32_t)(rb * RS + sgb * 8) * 2, BHp + so);
        }
        CP_COMMIT();
    };

    float acc[2][4][4] = {};

    issue(0, 0);
    for (int ch = 0; ch < 32; ch++) {
        int st = ch & 1;
        if (ch + 1 < 32) { issue(ch + 1, st ^ 1); CP_WAIT1(); }
        else             { CP_WAIT0(); }
        __syncthreads();

        uint32_t sA = sb + st * G3_STG;
        uint32_t sB = sA + 10240;

#pragma unroll
        for (int kk = 0; kk < 32; kk += 16) {
            uint32_t ah[2][4];
#pragma unroll
            for (int i = 0; i < 2; i++)
                ldsm4(ah[i], sA + 2u * ((wm * 32 + i * 16) * RS + kk + la));
            uint32_t bg[2][4];
#pragma unroll
            for (int jp = 0; jp < 2; jp++)
                ldsm4(bg[jp], sB + 2u * ((wn * 32 + jp * 16) * RS + kk + lb));
#pragma unroll
            for (int i = 0; i < 2; i++)
#pragma unroll
                for (int j = 0; j < 4; j++)
                    mma16816(acc[i][j], ah[i], &bg[j >> 1][(j & 1) * 2]);
        }
        __syncthreads();
    }

#pragma unroll
    for (int i = 0; i < 2; i++) {
#pragma unroll
        for (int half = 0; half < 2; half++) {
            int rr = row0 + wm * 32 + i * 16 + qr + half * 8;
            size_t ro = (size_t)rr * H_DIM + j0 + wn * 32;
#pragma unroll
            for (int j = 0; j < 4; j++) {
                float2 v;
                v.x = acc[i][j][half * 2 + 0];
                v.y = acc[i][j][half * 2 + 1];
                *(float2*)(out + ro + j * 8 + qc * 2) = v;
            }
        }
    }
}

// ---------------- launch -----------------------------------------------------
extern "C" void kernel_launch(void* const* d_in, const int* in_sizes, int n_in,
                              void* d_out, int out_size) {
    const float* X  = (const float*)d_in[0];
    const float* Wr = (const float*)d_in[1];
    const float* Wg = (const float*)d_in[2];
    const float* Wu = (const float*)d_in[3];
    const float* Wd = (const float*)d_in[4];
    const float* Wc = (const float*)d_in[5];
    float* out = (float*)d_out;
    float* logits = out + (size_t)T_TOK * H_DIM;

    // Resolve REAL device addresses (symbol-as-arg = host shadow addr = silent
    // ATS write to host memory on GB300; the R4/R9 bug).
    void *pG, *pU, *pD, *pC;
    cudaGetSymbolAddress(&pG, g_WgT);
    cudaGetSymbolAddress(&pU, g_WuT);
    cudaGetSymbolAddress(&pD, g_WdT);
    cudaGetSymbolAddress(&pC, g_WcT);

    cudaFuncSetAttribute(gemm1_kernel, cudaFuncAttributeMaxDynamicSharedMemorySize, G1_SMEM);
    cudaFuncSetAttribute(gemm2_kernel, cudaFuncAttributeMaxDynamicSharedMemorySize, G2_SMEM);
    cudaFuncSetAttribute(gemm3_kernel, cudaFuncAttributeMaxDynamicSharedMemorySize, G3_SMEM);

    convert_x<<<T_TOK * H_DIM / 1024, 256>>>(X);

    tsplit_all<<<NG + NU + ND + NC, dim3(32, 8)>>>(
        Wg, Wu, Wd, Wc, (__half*)pG, (__half*)pU, (__half*)pD, (__half*)pC);

    router_gemm<<<T_TOK / 8, 256>>>(X, Wr, logits);
    route_kernel<<<T_TOK / 256, 256>>>(logits);

    gemm1_kernel<<<dim3(I_DIM / 64, CAP / 128, E_NUM), 256, G1_SMEM>>>();
    gemm2_kernel<<<dim3(O_DIM / 64, CAP / 128, E_NUM), 256, G2_SMEM>>>();

    combine_kernel<<<T_TOK, 256>>>();
    gemm3_kernel<<<dim3(H_DIM / 64, T_TOK / 128), 256, G3_SMEM>>>(out);
}

// round 16
// speedup vs baseline: 3.0926x; 1.0270x over previous
#include <cuda_runtime.h>
#include <cuda_fp16.h>
#include <math.h>
#include <stdint.h>

// Problem constants
#define T_TOK 2048
#define H_DIM 1024
#define E_NUM 32
#define I_DIM 256
#define O_DIM 512
#define TOPK  4
#define CAP   2048
#define EROWS (E_NUM*CAP)

#define RS 40   // smem row stride (fp16 elems) -> 80B, ldmatrix conflict-free

// dynamic smem stage sizes (bytes)
#define G1_STG 20480            // Ahi 10240 | Gh 5120 | Uh 5120
#define G1_SMEM (2*G1_STG + 512)
#define G2_STG 15360            // Ahi 10240 | Bh 5120
#define G2_SMEM (2*G2_STG)
#define G3_STG 15360
#define G3_SMEM (2*G3_STG)

// ---------------- scratch (device globals; no allocation) --------------------
__device__ int   g_cnt[E_NUM];
__device__ int   g_slot_e[T_TOK * TOPK];
__device__ int   g_slot_r[T_TOK * TOPK];
__device__ float g_slot_w[T_TOK * TOPK];
__device__ int   g_bucket[E_NUM * CAP];
__device__ float g_Y[(size_t)EROWS * O_DIM];

__device__ __align__(256) __half g_Xhi[T_TOK * H_DIM];
__device__ __align__(256) __half g_Hhi[(size_t)EROWS * I_DIM];
__device__ __align__(256) __half g_phi[T_TOK * H_DIM];
__device__ __align__(256) __half g_WcT[H_DIM * H_DIM];
__device__ __align__(256) __half g_WgT[E_NUM * I_DIM * H_DIM];
__device__ __align__(256) __half g_WuT[E_NUM * I_DIM * H_DIM];
__device__ __align__(256) __half g_WdT[E_NUM * O_DIM * I_DIM];

// ---------------- helpers ----------------------------------------------------
__device__ __forceinline__ void mma16816(float* c, const uint32_t* a, const uint32_t* b) {
    asm volatile(
        "mma.sync.aligned.m16n8k16.row.col.f32.f16.f16.f32 "
        "{%0,%1,%2,%3}, {%4,%5,%6,%7}, {%8,%9}, {%0,%1,%2,%3};"
        : "+f"(c[0]), "+f"(c[1]), "+f"(c[2]), "+f"(c[3])
        : "r"(a[0]), "r"(a[1]), "r"(a[2]), "r"(a[3]), "r"(b[0]), "r"(b[1]));
}

__device__ __forceinline__ void ldsm4(uint32_t* r, uint32_t addr) {
    asm volatile("ldmatrix.sync.aligned.m8n8.x4.shared.b16 {%0,%1,%2,%3}, [%4];"
                 : "=r"(r[0]), "=r"(r[1]), "=r"(r[2]), "=r"(r[3]) : "r"(addr));
}

__device__ __forceinline__ void cpa16(uint32_t s, const void* g) {
    asm volatile("cp.async.ca.shared.global [%0], [%1], 16;" :: "r"(s), "l"(g));
}
#define CP_COMMIT() asm volatile("cp.async.commit_group;")
#define CP_WAIT1()  asm volatile("cp.async.wait_group 1;")
#define CP_WAIT0()  asm volatile("cp.async.wait_group 0;")

// ---------------- init -------------------------------------------------------
__global__ void init_kernel() {
    if (threadIdx.x < E_NUM) g_cnt[threadIdx.x] = 0;
}

// ---------------- fused: router logits (fp32 exact) + X convert + routing ----
__global__ __launch_bounds__(256) void router_fused(const float* __restrict__ X,
                                                    const float* __restrict__ Wr,
                                                    float* __restrict__ logits) {
    __shared__ float xs[8][H_DIM];
    __shared__ float lg[8][E_NUM];
    int t0 = blockIdx.x * 8;
    for (int i = threadIdx.x; i < 8 * H_DIM; i += 256)
        xs[i >> 10][i & 1023] = X[(size_t)t0 * H_DIM + i];
    __syncthreads();

    // fp16 convert of these 8 rows (coalesced half2 stores)
    const float2* xsf2 = (const float2*)&xs[0][0];
    for (int i = threadIdx.x; i < 4 * H_DIM; i += 256) {   // 4096 half2
        float2 v = xsf2[i];
        __half2 h;
        h.x = __float2half_rn(v.x); h.y = __float2half_rn(v.y);
        *(__half2*)(g_Xhi + (size_t)t0 * H_DIM + 2 * i) = h;
    }

    // logits: warp = token, lane = expert (fp32, identical math to verified)
    int tl = threadIdx.x >> 5;
    int e  = threadIdx.x & 31;
    const float* xr = xs[tl];
    float acc = 0.f;
#pragma unroll 8
    for (int k = 0; k < H_DIM; k++)
        acc += xr[k] * Wr[k * E_NUM + e];
    logits[(t0 + tl) * E_NUM + e] = acc;
    lg[tl][e] = acc;
    __syncwarp();

    // routing: lane 0 per warp runs the verified scalar routine
    if (e == 0) {
        int t = t0 + tl;
        float s[E_NUM];
#pragma unroll
        for (int j = 0; j < E_NUM; j++) s[j] = lg[tl][j];
        float ssum[4]; int top1[4], top2[4]; float v1a[4], v2a[4];
#pragma unroll
        for (int sh = 0; sh < 4; sh++) {
            float sum = 0.f;
#pragma unroll
            for (int j = 0; j < 8; j++) sum += s[sh * 8 + j];
            ssum[sh] = sum;
            int i1 = 0; float v1 = s[sh * 8];
#pragma unroll
            for (int j = 1; j < 8; j++) { float v = s[sh * 8 + j]; if (v > v1) { v1 = v; i1 = j; } }
            int i2 = -1; float v2 = -1e30f;
#pragma unroll
            for (int j = 0; j < 8; j++) {
                if (j == i1) continue;
                float v = s[sh * 8 + j];
                if (v > v2) { v2 = v; i2 = j; }
            }
            top1[sh] = i1; top2[sh] = i2; v1a[sh] = v1; v2a[sh] = v2;
        }
        int ch0 = (ssum[1] > ssum[0]) ? 1 : 0;
        int ch1 = (ssum[3] > ssum[2]) ? 3 : 2;
        int ce[4]; float cv[4];
        ce[0] = ch0 * 8 + top1[ch0]; cv[0] = v1a[ch0];
        ce[1] = ch0 * 8 + top2[ch0]; cv[1] = v2a[ch0];
        ce[2] = ch1 * 8 + top1[ch1]; cv[2] = v1a[ch1];
        ce[3] = ch1 * 8 + top2[ch1]; cv[3] = v2a[ch1];
        float m = cv[0];
#pragma unroll
        for (int k = 1; k < 4; k++) m = fmaxf(m, cv[k]);
        float w[4]; float wsum = 0.f;
#pragma unroll
        for (int k = 0; k < 4; k++) { w[k] = expf(cv[k] - m); wsum += w[k]; }
        float inv = 1.f / wsum;
#pragma unroll
        for (int k = 0; k < 4; k++) {
            int ex = ce[k];
            int r = atomicAdd(&g_cnt[ex], 1);
            g_bucket[ex * CAP + r] = t;
            g_slot_e[t * TOPK + k] = ex;
            g_slot_r[t * TOPK + k] = r;
            g_slot_w[t * TOPK + k] = w[k] * inv;
        }
    }
}

// ---------------- fused transpose of all 4 weight tensors --------------------
// 32c x 64r tiles; half2 stores (full 128B write transactions)
__device__ __forceinline__ void tile_transpose(const float* src, __half* dst,
                                               int R, int C, int bx, int by, int bz) {
    size_t eoff = (size_t)bz * R * C;
    __shared__ float t[64][33];
    int c0 = bx * 32, r0 = by * 64;
    int tx = threadIdx.x, ty = threadIdx.y;
#pragma unroll
    for (int i = 0; i < 8; i++) {
        int rl = ty + i * 8;
        t[rl][tx] = src[eoff + (size_t)(r0 + rl) * C + c0 + tx];
    }
    __syncthreads();
#pragma unroll
    for (int i = 0; i < 4; i++) {
        int cl = ty + i * 8;
        float v0 = t[2 * tx][cl];
        float v1 = t[2 * tx + 1][cl];
        __half2 h;
        h.x = __float2half_rn(v0); h.y = __float2half_rn(v1);
        *(__half2*)(dst + eoff + (size_t)(c0 + cl) * R + r0 + 2 * tx) = h;
    }
}

#define NG 4096   // 8 * 16 * 32
#define NU 4096
#define ND 2048   // 16 * 4 * 32
#define NC 512    // 32 * 16

__global__ void tsplit_all(const float* __restrict__ Wg, const float* __restrict__ Wu,
                           const float* __restrict__ Wd, const float* __restrict__ Wc,
                           __half* dG, __half* dU, __half* dD, __half* dC) {
    int id = blockIdx.x;
    if (id < NG) {
        int bx = id & 7, by = (id >> 3) & 15, bz = id >> 7;
        tile_transpose(Wg, dG, H_DIM, I_DIM, bx, by, bz);
    } else if (id < NG + NU) {
        id -= NG;
        int bx = id & 7, by = (id >> 3) & 15, bz = id >> 7;
        tile_transpose(Wu, dU, H_DIM, I_DIM, bx, by, bz);
    } else if (id < NG + NU + ND) {
        id -= NG + NU;
        int bx = id & 15, by = (id >> 4) & 3, bz = id >> 6;
        tile_transpose(Wd, dD, I_DIM, O_DIM, bx, by, bz);
    } else {
        id -= NG + NU + ND;
        int bx = id & 31, by = id >> 5;
        tile_transpose(Wc, dC, H_DIM, H_DIM, bx, by, 0);
    }
}

// ---------------- GEMM1: gate+up (fp16 1-term, ldmatrix, pipelined) ----------
__global__ __launch_bounds__(256) void gemm1_kernel() {
    int e    = blockIdx.z;
    int rows = g_cnt[e];
    int row0 = blockIdx.y * 128;
    if (row0 >= rows) return;
    int base = e * CAP;
    int i0   = blockIdx.x * 64;

    extern __shared__ __align__(16) char sm[];
    int* toks = (int*)(sm + 2 * G1_STG);
    uint32_t sb = (uint32_t)__cvta_generic_to_shared(sm);

    int tid = threadIdx.x;
    int wid = tid >> 5, lane = tid & 31;
    int qr = lane >> 2, qc = lane & 3;
    int wm = wid & 3, wn = wid >> 2;

    int la = (lane & 15) * RS + (lane >> 4) * 8;
    int lb = (((lane >> 4) << 3) + (lane & 7)) * RS + ((lane >> 3) & 1) * 8;

    for (int r = tid; r < 128; r += 256) {
        int rr = row0 + r;
        toks[r] = g_bucket[e * CAP + (rr < rows ? rr : row0)];
    }
    __syncthreads();

    const __half* GHp = g_WgT + (size_t)e * I_DIM * H_DIM + (size_t)i0 * H_DIM;
    const __half* UHp = g_WuT + (size_t)e * I_DIM * H_DIM + (size_t)i0 * H_DIM;

    int r0a = tid >> 2, sga = tid & 3;
    int rb = tid >> 2, sgb = tid & 3;

    auto issue = [&](int ch, int st) {
        int k0 = ch * 32;
        uint32_t s = sb + st * G1_STG;
#pragma unroll
        for (int h = 0; h < 2; h++) {
            int r = r0a + h * 64;
            size_t so = (size_t)toks[r] * H_DIM + k0 + sga * 8;
            cpa16(s + (uint32_t)(r * RS + sga * 8) * 2, g_Xhi + so);
        }
        {
            size_t so = (size_t)rb * H_DIM + k0 + sgb * 8;
            uint32_t d = (uint32_t)(rb * RS + sgb * 8) * 2;
            cpa16(s + 10240 + d, GHp + so);
            cpa16(s + 15360 + d, UHp + so);
        }
        CP_COMMIT();
    };

    float accG[2][4][4] = {}, accU[2][4][4] = {};

    issue(0, 0);
    for (int ch = 0; ch < 32; ch++) {
        int st = ch & 1;
        if (ch + 1 < 32) { issue(ch + 1, st ^ 1); CP_WAIT1(); }
        else             { CP_WAIT0(); }
        __syncthreads();

        uint32_t sA = sb + st * G1_STG;
        uint32_t sG = sA + 10240;
        uint32_t sU = sA + 15360;

#pragma unroll
        for (int kk = 0; kk < 32; kk += 16) {
            uint32_t ah[2][4];
#pragma unroll
            for (int i = 0; i < 2; i++)
                ldsm4(ah[i], sA + 2u * ((wm * 32 + i * 16) * RS + kk + la));
            uint32_t bg[2][4];
#pragma unroll
            for (int jp = 0; jp < 2; jp++)
                ldsm4(bg[jp], sG + 2u * ((wn * 32 + jp * 16) * RS + kk + lb));
#pragma unroll
            for (int i = 0; i < 2; i++)
#pragma unroll
                for (int j = 0; j < 4; j++)
                    mma16816(accG[i][j], ah[i], &bg[j >> 1][(j & 1) * 2]);
#pragma unroll
            for (int jp = 0; jp < 2; jp++)
                ldsm4(bg[jp], sU + 2u * ((wn * 32 + jp * 16) * RS + kk + lb));
#pragma unroll
            for (int i = 0; i < 2; i++)
#pragma unroll
                for (int j = 0; j < 4; j++)
                    mma16816(accU[i][j], ah[i], &bg[j >> 1][(j & 1) * 2]);
        }
        __syncthreads();
    }

#pragma unroll
    for (int i = 0; i < 2; i++) {
#pragma unroll
        for (int half = 0; half < 2; half++) {
            int rr = row0 + wm * 32 + i * 16 + qr + half * 8;
            if (rr >= rows) continue;
            size_t ro = (size_t)(base + rr) * I_DIM + i0 + wn * 32;
#pragma unroll
            for (int j = 0; j < 4; j++) {
                float g0 = accG[i][j][half * 2 + 0], g1 = accG[i][j][half * 2 + 1];
                float u0 = accU[i][j][half * 2 + 0], u1 = accU[i][j][half * 2 + 1];
                float h0 = g0 / (1.f + expf(-g0)) * u0;
                float h1 = g1 / (1.f + expf(-g1)) * u1;
                __half2 ph;
                ph.x = __float2half_rn(h0); ph.y = __float2half_rn(h1);
                *(__half2*)(g_Hhi + ro + j * 8 + qc * 2) = ph;
            }
        }
    }
}

// ---------------- GEMM2: down proj (fp16 1-term, ldmatrix, pipelined) --------
__global__ __launch_bounds__(256) void gemm2_kernel() {
    int e    = blockIdx.z;
    int rows = g_cnt[e];
    int row0 = blockIdx.y * 128;
    if (row0 >= rows) return;
    int base = e * CAP;
    int o0   = blockIdx.x * 64;

    extern __shared__ __align__(16) char sm[];
    uint32_t sb = (uint32_t)__cvta_generic_to_shared(sm);

    int tid = threadIdx.x;
    int wid = tid >> 5, lane = tid & 31;
    int qr = lane >> 2, qc = lane & 3;
    int wm = wid & 3, wn = wid >> 2;

    int la = (lane & 15) * RS + (lane >> 4) * 8;
    int lb = (((lane >> 4) << 3) + (lane & 7)) * RS + ((lane >> 3) & 1) * 8;

    const __half* BHp = g_WdT + (size_t)e * O_DIM * I_DIM + (size_t)o0 * I_DIM;

    int r0a = tid >> 2, sga = tid & 3;
    int rb = tid >> 2, sgb = tid & 3;
    int arow0 = row0 + r0a;      if (arow0 >= rows) arow0 = rows - 1;
    int arow1 = row0 + r0a + 64; if (arow1 >= rows) arow1 = rows - 1;

    auto issue = [&](int ch, int st) {
        int k0 = ch * 32;
        uint32_t s = sb + st * G2_STG;
        {
            size_t so = (size_t)(base + arow0) * I_DIM + k0 + sga * 8;
            cpa16(s + (uint32_t)(r0a * RS + sga * 8) * 2, g_Hhi + so);
            so = (size_t)(base + arow1) * I_DIM + k0 + sga * 8;
            cpa16(s + (uint32_t)((r0a + 64) * RS + sga * 8) * 2, g_Hhi + so);
        }
        {
            size_t so = (size_t)rb * I_DIM + k0 + sgb * 8;
            cpa16(s + 10240 + (uint32_t)(rb * RS + sgb * 8) * 2, BHp + so);
        }
        CP_COMMIT();
    };

    float acc[2][4][4] = {};

    issue(0, 0);
    for (int ch = 0; ch < 8; ch++) {
        int st = ch & 1;
        if (ch + 1 < 8) { issue(ch + 1, st ^ 1); CP_WAIT1(); }
        else            { CP_WAIT0(); }
        __syncthreads();

        uint32_t sA = sb + st * G2_STG;
        uint32_t sB = sA + 10240;

#pragma unroll
        for (int kk = 0; kk < 32; kk += 16) {
            uint32_t ah[2][4];
#pragma unroll
            for (int i = 0; i < 2; i++)
                ldsm4(ah[i], sA + 2u * ((wm * 32 + i * 16) * RS + kk + la));
            uint32_t bg[2][4];
#pragma unroll
            for (int jp = 0; jp < 2; jp++)
                ldsm4(bg[jp], sB + 2u * ((wn * 32 + jp * 16) * RS + kk + lb));
#pragma unroll
            for (int i = 0; i < 2; i++)
#pragma unroll
                for (int j = 0; j < 4; j++)
                    mma16816(acc[i][j], ah[i], &bg[j >> 1][(j & 1) * 2]);
        }
        __syncthreads();
    }

#pragma unroll
    for (int i = 0; i < 2; i++) {
#pragma unroll
        for (int half = 0; half < 2; half++) {
            int rr = row0 + wm * 32 + i * 16 + qr + half * 8;
            if (rr >= rows) continue;
            size_t ro = (size_t)(base + rr) * O_DIM + o0 + wn * 32;
#pragma unroll
            for (int j = 0; j < 4; j++) {
                float2 v;
                v.x = acc[i][j][half * 2 + 0];
                v.y = acc[i][j][half * 2 + 1];
                *(float2*)(g_Y + ro + j * 8 + qc * 2) = v;
            }
        }
    }
}

// ---------------- combine (gather, fused fp16 store) --------------------------
__global__ void combine_kernel() {
    int t = blockIdx.x;
    __shared__ int   se[TOPK];
    __shared__ int   sr[TOPK];
    __shared__ float sw[TOPK];
    if (threadIdx.x < TOPK) {
        int e = g_slot_e[t * TOPK + threadIdx.x];
        se[threadIdx.x] = e;
        sr[threadIdx.x] = e * CAP + g_slot_r[t * TOPK + threadIdx.x];
        sw[threadIdx.x] = g_slot_w[t * TOPK + threadIdx.x];
    }
    __syncthreads();
    for (int c = threadIdx.x; c < H_DIM; c += blockDim.x) {
        int g = c >> 9;
        int o = c & 511;
        float acc = 0.f;
#pragma unroll
        for (int s = 0; s < TOPK; s++)
            if ((se[s] >> 4) == g)
                acc += sw[s] * g_Y[(size_t)sr[s] * O_DIM + o];
        g_phi[(size_t)t * H_DIM + c] = __float2half_rn(acc);
    }
}

// ---------------- GEMM3 (fp16 1-term, ldmatrix, pipelined) -------------------
__global__ __launch_bounds__(256) void gemm3_kernel(float* __restrict__ out) {
    int row0 = blockIdx.y * 128;
    int j0   = blockIdx.x * 64;

    extern __shared__ __align__(16) char sm[];
    uint32_t sb = (uint32_t)__cvta_generic_to_shared(sm);

    int tid = threadIdx.x;
    int wid = tid >> 5, lane = tid & 31;
    int qr = lane >> 2, qc = lane & 3;
    int wm = wid & 3, wn = wid >> 2;

    int la = (lane & 15) * RS + (lane >> 4) * 8;
    int lb = (((lane >> 4) << 3) + (lane & 7)) * RS + ((lane >> 3) & 1) * 8;

    const __half* BHp = g_WcT + (size_t)j0 * H_DIM;

    int r0a = tid >> 2, sga = tid & 3;
    int rb = tid >> 2, sgb = tid & 3;

    auto issue = [&](int ch, int st) {
        int k0 = ch * 32;
        uint32_t s = sb + st * G3_STG;
#pragma unroll
        for (int h = 0; h < 2; h++) {
            int r = r0a + h * 64;
            size_t so = (size_t)(row0 + r) * H_DIM + k0 + sga * 8;
            cpa16(s + (uint32_t)(r * RS + sga * 8) * 2, g_phi + so);
        }
        {
            size_t so = (size_t)rb * H_DIM + k0 + sgb * 8;
            cpa16(s + 10240 + (uint32_t)(rb * RS + sgb * 8) * 2, BHp + so);
        }
        CP_COMMIT();
    };

    float acc[2][4][4] = {};

    issue(0, 0);
    for (int ch = 0; ch < 32; ch++) {
        int st = ch & 1;
        if (ch + 1 < 32) { issue(ch + 1, st ^ 1); CP_WAIT1(); }
        else             { CP_WAIT0(); }
        __syncthreads();

        uint32_t sA = sb + st * G3_STG;
        uint32_t sB = sA + 10240;

#pragma unroll
        for (int kk = 0; kk < 32; kk += 16) {
            uint32_t ah[2][4];
#pragma unroll
            for (int i = 0; i < 2; i++)
                ldsm4(ah[i], sA + 2u * ((wm * 32 + i * 16) * RS + kk + la));
            uint32_t bg[2][4];
#pragma unroll
            for (int jp = 0; jp < 2; jp++)
                ldsm4(bg[jp], sB + 2u * ((wn * 32 + jp * 16) * RS + kk + lb));
#pragma unroll
            for (int i = 0; i < 2; i++)
#pragma unroll
                for (int j = 0; j < 4; j++)
                    mma16816(acc[i][j], ah[i], &bg[j >> 1][(j & 1) * 2]);
        }
        __syncthreads();
    }

#pragma unroll
    for (int i = 0; i < 2; i++) {
#pragma unroll
        for (int half = 0; half < 2; half++) {
            int rr = row0 + wm * 32 + i * 16 + qr + half * 8;
            size_t ro = (size_t)rr * H_DIM + j0 + wn * 32;
#pragma unroll
            for (int j = 0; j < 4; j++) {
                float2 v;
                v.x = acc[i][j][half * 2 + 0];
                v.y = acc[i][j][half * 2 + 1];
                *(float2*)(out + ro + j * 8 + qc * 2) = v;
            }
        }
    }
}

// ---------------- launch -----------------------------------------------------
extern "C" void kernel_launch(void* const* d_in, const int* in_sizes, int n_in,
                              void* d_out, int out_size) {
    const float* X  = (const float*)d_in[0];
    const float* Wr = (const float*)d_in[1];
    const float* Wg = (const float*)d_in[2];
    const float* Wu = (const float*)d_in[3];
    const float* Wd = (const float*)d_in[4];
    const float* Wc = (const float*)d_in[5];
    float* out = (float*)d_out;
    float* logits = out + (size_t)T_TOK * H_DIM;

    // Resolve REAL device addresses (symbol-as-arg = host shadow addr = silent
    // ATS write to host memory on GB300; the R4/R9 bug).
    void *pG, *pU, *pD, *pC;
    cudaGetSymbolAddress(&pG, g_WgT);
    cudaGetSymbolAddress(&pU, g_WuT);
    cudaGetSymbolAddress(&pD, g_WdT);
    cudaGetSymbolAddress(&pC, g_WcT);

    cudaFuncSetAttribute(gemm1_kernel, cudaFuncAttributeMaxDynamicSharedMemorySize, G1_SMEM);
    cudaFuncSetAttribute(gemm2_kernel, cudaFuncAttributeMaxDynamicSharedMemorySize, G2_SMEM);
    cudaFuncSetAttribute(gemm3_kernel, cudaFuncAttributeMaxDynamicSharedMemorySize, G3_SMEM);

    // One-time stream/event setup (created outside capture on the first,
    // non-captured correctness call; reused thereafter — graph fork/join).
    static cudaStream_t s2 = nullptr;
    static cudaEvent_t evA = nullptr, evB = nullptr;
    if (!s2) {
        cudaStreamCreateWithFlags(&s2, cudaStreamNonBlocking);
        cudaEventCreateWithFlags(&evA, cudaEventDisableTiming);
        cudaEventCreateWithFlags(&evB, cudaEventDisableTiming);
    }

    // fork: weight transposes run concurrently with the router chain
    cudaEventRecord(evA, 0);
    cudaStreamWaitEvent(s2, evA, 0);
    tsplit_all<<<NG + NU + ND + NC, dim3(32, 8), 0, s2>>>(
        Wg, Wu, Wd, Wc, (__half*)pG, (__half*)pU, (__half*)pD, (__half*)pC);
    cudaEventRecord(evB, s2);

    init_kernel<<<1, 32>>>();
    router_fused<<<T_TOK / 8, 256>>>(X, Wr, logits);

    // join: GEMMs need both branches
    cudaStreamWaitEvent(0, evB, 0);

    gemm1_kernel<<<dim3(I_DIM / 64, CAP / 128, E_NUM), 256, G1_SMEM>>>();
    gemm2_kernel<<<dim3(O_DIM / 64, CAP / 128, E_NUM), 256, G2_SMEM>>>();

    combine_kernel<<<T_TOK, 256>>>();
    gemm3_kernel<<<dim3(H_DIM / 64, T_TOK / 128), 256, G3_SMEM>>>(out);
}

// round 17
// speedup vs baseline: 3.1721x; 1.0257x over previous
#include <cuda_runtime.h>
#include <cuda_fp16.h>
#include <math.h>
#include <stdint.h>

// Problem constants
#define T_TOK 2048
#define H_DIM 1024
#define E_NUM 32
#define I_DIM 256
#define O_DIM 512
#define TOPK  4
#define CAP   2048
#define EROWS (E_NUM*CAP)

#define RS 40   // smem row stride (fp16 elems) -> 80B, ldmatrix conflict-free

// dynamic smem stage sizes (bytes) — M=64 tiles
#define TILE_B 5120             // 64 rows * RS * 2
#define G1_STG (3*TILE_B)       // A | G | U
#define G1_SMEM (2*G1_STG + 256)
#define G2_STG (2*TILE_B)       // A | B
#define G2_SMEM (2*G2_STG)
#define G3_STG (2*TILE_B)
#define G3_SMEM (2*G3_STG)

// ---------------- scratch (device globals; no allocation) --------------------
__device__ int   g_cnt[E_NUM];
__device__ int   g_slot_e[T_TOK * TOPK];
__device__ int   g_slot_r[T_TOK * TOPK];
__device__ float g_slot_w[T_TOK * TOPK];
__device__ int   g_bucket[E_NUM * CAP];
__device__ float g_Y[(size_t)EROWS * O_DIM];

__device__ __align__(256) __half g_Xhi[T_TOK * H_DIM];
__device__ __align__(256) __half g_Hhi[(size_t)EROWS * I_DIM];
__device__ __align__(256) __half g_phi[T_TOK * H_DIM];
__device__ __align__(256) __half g_WcT[H_DIM * H_DIM];
__device__ __align__(256) __half g_WgT[E_NUM * I_DIM * H_DIM];
__device__ __align__(256) __half g_WuT[E_NUM * I_DIM * H_DIM];
__device__ __align__(256) __half g_WdT[E_NUM * O_DIM * I_DIM];

// ---------------- helpers ----------------------------------------------------
__device__ __forceinline__ void mma16816(float* c, const uint32_t* a, const uint32_t* b) {
    asm volatile(
        "mma.sync.aligned.m16n8k16.row.col.f32.f16.f16.f32 "
        "{%0,%1,%2,%3}, {%4,%5,%6,%7}, {%8,%9}, {%0,%1,%2,%3};"
        : "+f"(c[0]), "+f"(c[1]), "+f"(c[2]), "+f"(c[3])
        : "r"(a[0]), "r"(a[1]), "r"(a[2]), "r"(a[3]), "r"(b[0]), "r"(b[1]));
}

__device__ __forceinline__ void ldsm4(uint32_t* r, uint32_t addr) {
    asm volatile("ldmatrix.sync.aligned.m8n8.x4.shared.b16 {%0,%1,%2,%3}, [%4];"
                 : "=r"(r[0]), "=r"(r[1]), "=r"(r[2]), "=r"(r[3]) : "r"(addr));
}

__device__ __forceinline__ void cpa16(uint32_t s, const void* g) {
    asm volatile("cp.async.ca.shared.global [%0], [%1], 16;" :: "r"(s), "l"(g));
}
#define CP_COMMIT() asm volatile("cp.async.commit_group;")
#define CP_WAIT1()  asm volatile("cp.async.wait_group 1;")
#define CP_WAIT0()  asm volatile("cp.async.wait_group 0;")

// ---------------- init -------------------------------------------------------
__global__ void init_kernel() {
    if (threadIdx.x < E_NUM) g_cnt[threadIdx.x] = 0;
}

// ---------------- fused: router logits (fp32 exact) + X convert + routing ----
__global__ __launch_bounds__(256) void router_fused(const float* __restrict__ X,
                                                    const float* __restrict__ Wr,
                                                    float* __restrict__ logits) {
    __shared__ float xs[8][H_DIM];
    __shared__ float lg[8][E_NUM];
    int t0 = blockIdx.x * 8;
    for (int i = threadIdx.x; i < 8 * H_DIM; i += 256)
        xs[i >> 10][i & 1023] = X[(size_t)t0 * H_DIM + i];
    __syncthreads();

    const float2* xsf2 = (const float2*)&xs[0][0];
    for (int i = threadIdx.x; i < 4 * H_DIM; i += 256) {
        float2 v = xsf2[i];
        __half2 h;
        h.x = __float2half_rn(v.x); h.y = __float2half_rn(v.y);
        *(__half2*)(g_Xhi + (size_t)t0 * H_DIM + 2 * i) = h;
    }

    int tl = threadIdx.x >> 5;
    int e  = threadIdx.x & 31;
    const float* xr = xs[tl];
    float acc = 0.f;
#pragma unroll 8
    for (int k = 0; k < H_DIM; k++)
        acc += xr[k] * Wr[k * E_NUM + e];
    logits[(t0 + tl) * E_NUM + e] = acc;
    lg[tl][e] = acc;
    __syncwarp();

    if (e == 0) {
        int t = t0 + tl;
        float s[E_NUM];
#pragma unroll
        for (int j = 0; j < E_NUM; j++) s[j] = lg[tl][j];
        float ssum[4]; int top1[4], top2[4]; float v1a[4], v2a[4];
#pragma unroll
        for (int sh = 0; sh < 4; sh++) {
            float sum = 0.f;
#pragma unroll
            for (int j = 0; j < 8; j++) sum += s[sh * 8 + j];
            ssum[sh] = sum;
            int i1 = 0; float v1 = s[sh * 8];
#pragma unroll
            for (int j = 1; j < 8; j++) { float v = s[sh * 8 + j]; if (v > v1) { v1 = v; i1 = j; } }
            int i2 = -1; float v2 = -1e30f;
#pragma unroll
            for (int j = 0; j < 8; j++) {
                if (j == i1) continue;
                float v = s[sh * 8 + j];
                if (v > v2) { v2 = v; i2 = j; }
            }
            top1[sh] = i1; top2[sh] = i2; v1a[sh] = v1; v2a[sh] = v2;
        }
        int ch0 = (ssum[1] > ssum[0]) ? 1 : 0;
        int ch1 = (ssum[3] > ssum[2]) ? 3 : 2;
        int ce[4]; float cv[4];
        ce[0] = ch0 * 8 + top1[ch0]; cv[0] = v1a[ch0];
        ce[1] = ch0 * 8 + top2[ch0]; cv[1] = v2a[ch0];
        ce[2] = ch1 * 8 + top1[ch1]; cv[2] = v1a[ch1];
        ce[3] = ch1 * 8 + top2[ch1]; cv[3] = v2a[ch1];
        float m = cv[0];
#pragma unroll
        for (int k = 1; k < 4; k++) m = fmaxf(m, cv[k]);
        float w[4]; float wsum = 0.f;
#pragma unroll
        for (int k = 0; k < 4; k++) { w[k] = expf(cv[k] - m); wsum += w[k]; }
        float inv = 1.f / wsum;
#pragma unroll
        for (int k = 0; k < 4; k++) {
            int ex = ce[k];
            int r = atomicAdd(&g_cnt[ex], 1);
            g_bucket[ex * CAP + r] = t;
            g_slot_e[t * TOPK + k] = ex;
            g_slot_r[t * TOPK + k] = r;
            g_slot_w[t * TOPK + k] = w[k] * inv;
        }
    }
}

// ---------------- fused transpose of all 4 weight tensors --------------------
__device__ __forceinline__ void tile_transpose(const float* src, __half* dst,
                                               int R, int C, int bx, int by, int bz) {
    size_t eoff = (size_t)bz * R * C;
    __shared__ float t[64][33];
    int c0 = bx * 32, r0 = by * 64;
    int tx = threadIdx.x, ty = threadIdx.y;
#pragma unroll
    for (int i = 0; i < 8; i++) {
        int rl = ty + i * 8;
        t[rl][tx] = src[eoff + (size_t)(r0 + rl) * C + c0 + tx];
    }
    __syncthreads();
#pragma unroll
    for (int i = 0; i < 4; i++) {
        int cl = ty + i * 8;
        float v0 = t[2 * tx][cl];
        float v1 = t[2 * tx + 1][cl];
        __half2 h;
        h.x = __float2half_rn(v0); h.y = __float2half_rn(v1);
        *(__half2*)(dst + eoff + (size_t)(c0 + cl) * R + r0 + 2 * tx) = h;
    }
}

#define NG 4096
#define NU 4096
#define ND 2048
#define NC 512

__global__ void tsplit_all(const float* __restrict__ Wg, const float* __restrict__ Wu,
                           const float* __restrict__ Wd, const float* __restrict__ Wc,
                           __half* dG, __half* dU, __half* dD, __half* dC) {
    int id = blockIdx.x;
    if (id < NG) {
        int bx = id & 7, by = (id >> 3) & 15, bz = id >> 7;
        tile_transpose(Wg, dG, H_DIM, I_DIM, bx, by, bz);
    } else if (id < NG + NU) {
        id -= NG;
        int bx = id & 7, by = (id >> 3) & 15, bz = id >> 7;
        tile_transpose(Wu, dU, H_DIM, I_DIM, bx, by, bz);
    } else if (id < NG + NU + ND) {
        id -= NG + NU;
        int bx = id & 15, by = (id >> 4) & 3, bz = id >> 6;
        tile_transpose(Wd, dD, I_DIM, O_DIM, bx, by, bz);
    } else {
        id -= NG + NU + ND;
        int bx = id & 31, by = id >> 5;
        tile_transpose(Wc, dC, H_DIM, H_DIM, bx, by, 0);
    }
}

// ---------------- GEMM1: gate+up (M=64 tile, 2m x 4n warps) ------------------
__global__ __launch_bounds__(256) void gemm1_kernel() {
    int e    = blockIdx.z;
    int rows = g_cnt[e];
    int row0 = blockIdx.y * 64;
    if (row0 >= rows) return;
    int base = e * CAP;
    int i0   = blockIdx.x * 64;

    extern __shared__ __align__(16) char sm[];
    int* toks = (int*)(sm + 2 * G1_STG);
    uint32_t sb = (uint32_t)__cvta_generic_to_shared(sm);

    int tid = threadIdx.x;
    int wid = tid >> 5, lane = tid & 31;
    int qr = lane >> 2, qc = lane & 3;
    int wm = wid & 1, wn = wid >> 1;       // 2 m-tiles(32r) x 4 n-tiles(16c)

    int la = (lane & 15) * RS + (lane >> 4) * 8;
    int lb = (((lane >> 4) << 3) + (lane & 7)) * RS + ((lane >> 3) & 1) * 8;

    for (int r = tid; r < 64; r += 256) {
        int rr = row0 + r;
        toks[r] = g_bucket[e * CAP + (rr < rows ? rr : row0)];
    }
    __syncthreads();

    const __half* GHp = g_WgT + (size_t)e * I_DIM * H_DIM + (size_t)i0 * H_DIM;
    const __half* UHp = g_WuT + (size_t)e * I_DIM * H_DIM + (size_t)i0 * H_DIM;

    int r0a = tid >> 2, sga = tid & 3;     // 64 rows x 4 segs

    auto issue = [&](int ch, int st) {
        int k0 = ch * 32;
        uint32_t s = sb + st * G1_STG;
        {
            size_t so = (size_t)toks[r0a] * H_DIM + k0 + sga * 8;
            cpa16(s + (uint32_t)(r0a * RS + sga * 8) * 2, g_Xhi + so);
        }
        {
            size_t so = (size_t)r0a * H_DIM + k0 + sga * 8;
            uint32_t d = (uint32_t)(r0a * RS + sga * 8) * 2;
            cpa16(s + TILE_B + d, GHp + so);
            cpa16(s + 2 * TILE_B + d, UHp + so);
        }
        CP_COMMIT();
    };

    float accG[2][2][4] = {}, accU[2][2][4] = {};

    issue(0, 0);
    for (int ch = 0; ch < 32; ch++) {
        int st = ch & 1;
        if (ch + 1 < 32) { issue(ch + 1, st ^ 1); CP_WAIT1(); }
        else             { CP_WAIT0(); }
        __syncthreads();

        uint32_t sA = sb + st * G1_STG;
        uint32_t sG = sA + TILE_B;
        uint32_t sU = sA + 2 * TILE_B;

#pragma unroll
        for (int kk = 0; kk < 32; kk += 16) {
            uint32_t ah[2][4];
#pragma unroll
            for (int i = 0; i < 2; i++)
                ldsm4(ah[i], sA + 2u * ((wm * 32 + i * 16) * RS + kk + la));
            uint32_t bg[4];
            ldsm4(bg, sG + 2u * ((wn * 16) * RS + kk + lb));
#pragma unroll
            for (int i = 0; i < 2; i++)
#pragma unroll
                for (int j = 0; j < 2; j++)
                    mma16816(accG[i][j], ah[i], &bg[j * 2]);
            ldsm4(bg, sU + 2u * ((wn * 16) * RS + kk + lb));
#pragma unroll
            for (int i = 0; i < 2; i++)
#pragma unroll
                for (int j = 0; j < 2; j++)
                    mma16816(accU[i][j], ah[i], &bg[j * 2]);
        }
        __syncthreads();
    }

    // epilogue: silu(gate)*up -> fp16
#pragma unroll
    for (int i = 0; i < 2; i++) {
#pragma unroll
        for (int half = 0; half < 2; half++) {
            int rr = row0 + wm * 32 + i * 16 + qr + half * 8;
            if (rr >= rows) continue;
            size_t ro = (size_t)(base + rr) * I_DIM + i0 + wn * 16;
#pragma unroll
            for (int j = 0; j < 2; j++) {
                float g0 = accG[i][j][half * 2 + 0], g1 = accG[i][j][half * 2 + 1];
                float u0 = accU[i][j][half * 2 + 0], u1 = accU[i][j][half * 2 + 1];
                float h0 = g0 / (1.f + expf(-g0)) * u0;
                float h1 = g1 / (1.f + expf(-g1)) * u1;
                __half2 ph;
                ph.x = __float2half_rn(h0); ph.y = __float2half_rn(h1);
                *(__half2*)(g_Hhi + ro + j * 8 + qc * 2) = ph;
            }
        }
    }
}

// ---------------- GEMM2: down proj (M=64 tile) -------------------------------
__global__ __launch_bounds__(256) void gemm2_kernel() {
    int e    = blockIdx.z;
    int rows = g_cnt[e];
    int row0 = blockIdx.y * 64;
    if (row0 >= rows) return;
    int base = e * CAP;
    int o0   = blockIdx.x * 64;

    extern __shared__ __align__(16) char sm[];
    uint32_t sb = (uint32_t)__cvta_generic_to_shared(sm);

    int tid = threadIdx.x;
    int wid = tid >> 5, lane = tid & 31;
    int qr = lane >> 2, qc = lane & 3;
    int wm = wid & 1, wn = wid >> 1;

    int la = (lane & 15) * RS + (lane >> 4) * 8;
    int lb = (((lane >> 4) << 3) + (lane & 7)) * RS + ((lane >> 3) & 1) * 8;

    const __half* BHp = g_WdT + (size_t)e * O_DIM * I_DIM + (size_t)o0 * I_DIM;

    int r0a = tid >> 2, sga = tid & 3;
    int arow = row0 + r0a; if (arow >= rows) arow = rows - 1;

    auto issue = [&](int ch, int st) {
        int k0 = ch * 32;
        uint32_t s = sb + st * G2_STG;
        {
            size_t so = (size_t)(base + arow) * I_DIM + k0 + sga * 8;
            cpa16(s + (uint32_t)(r0a * RS + sga * 8) * 2, g_Hhi + so);
        }
        {
            size_t so = (size_t)r0a * I_DIM + k0 + sga * 8;
            cpa16(s + TILE_B + (uint32_t)(r0a * RS + sga * 8) * 2, BHp + so);
        }
        CP_COMMIT();
    };

    float acc[2][2][4] = {};

    issue(0, 0);
    for (int ch = 0; ch < 8; ch++) {
        int st = ch & 1;
        if (ch + 1 < 8) { issue(ch + 1, st ^ 1); CP_WAIT1(); }
        else            { CP_WAIT0(); }
        __syncthreads();

        uint32_t sA = sb + st * G2_STG;
        uint32_t sB = sA + TILE_B;

#pragma unroll
        for (int kk = 0; kk < 32; kk += 16) {
            uint32_t ah[2][4];
#pragma unroll
            for (int i = 0; i < 2; i++)
                ldsm4(ah[i], sA + 2u * ((wm * 32 + i * 16) * RS + kk + la));
            uint32_t bg[4];
            ldsm4(bg, sB + 2u * ((wn * 16) * RS + kk + lb));
#pragma unroll
            for (int i = 0; i < 2; i++)
#pragma unroll
                for (int j = 0; j < 2; j++)
                    mma16816(acc[i][j], ah[i], &bg[j * 2]);
        }
        __syncthreads();
    }

#pragma unroll
    for (int i = 0; i < 2; i++) {
#pragma unroll
        for (int half = 0; half < 2; half++) {
            int rr = row0 + wm * 32 + i * 16 + qr + half * 8;
            if (rr >= rows) continue;
            size_t ro = (size_t)(base + rr) * O_DIM + o0 + wn * 16;
#pragma unroll
            for (int j = 0; j < 2; j++) {
                float2 v;
                v.x = acc[i][j][half * 2 + 0];
                v.y = acc[i][j][half * 2 + 1];
                *(float2*)(g_Y + ro + j * 8 + qc * 2) = v;
            }
        }
    }
}

// ---------------- combine (gather, fused fp16 store) --------------------------
__global__ void combine_kernel() {
    int t = blockIdx.x;
    __shared__ int   se[TOPK];
    __shared__ int   sr[TOPK];
    __shared__ float sw[TOPK];
    if (threadIdx.x < TOPK) {
        int e = g_slot_e[t * TOPK + threadIdx.x];
        se[threadIdx.x] = e;
        sr[threadIdx.x] = e * CAP + g_slot_r[t * TOPK + threadIdx.x];
        sw[threadIdx.x] = g_slot_w[t * TOPK + threadIdx.x];
    }
    __syncthreads();
    for (int c = threadIdx.x; c < H_DIM; c += blockDim.x) {
        int g = c >> 9;
        int o = c & 511;
        float acc = 0.f;
#pragma unroll
        for (int s = 0; s < TOPK; s++)
            if ((se[s] >> 4) == g)
                acc += sw[s] * g_Y[(size_t)sr[s] * O_DIM + o];
        g_phi[(size_t)t * H_DIM + c] = __float2half_rn(acc);
    }
}

// ---------------- GEMM3 (M=64 tile) ------------------------------------------
__global__ __launch_bounds__(256) void gemm3_kernel(float* __restrict__ out) {
    int row0 = blockIdx.y * 64;
    int j0   = blockIdx.x * 64;

    extern __shared__ __align__(16) char sm[];
    uint32_t sb = (uint32_t)__cvta_generic_to_shared(sm);

    int tid = threadIdx.x;
    int wid = tid >> 5, lane = tid & 31;
    int qr = lane >> 2, qc = lane & 3;
    int wm = wid & 1, wn = wid >> 1;

    int la = (lane & 15) * RS + (lane >> 4) * 8;
    int lb = (((lane >> 4) << 3) + (lane & 7)) * RS + ((lane >> 3) & 1) * 8;

    const __half* BHp = g_WcT + (size_t)j0 * H_DIM;

    int r0a = tid >> 2, sga = tid & 3;

    auto issue = [&](int ch, int st) {
        int k0 = ch * 32;
        uint32_t s = sb + st * G3_STG;
        {
            size_t so = (size_t)(row0 + r0a) * H_DIM + k0 + sga * 8;
            cpa16(s + (uint32_t)(r0a * RS + sga * 8) * 2, g_phi + so);
        }
        {
            size_t so = (size_t)r0a * H_DIM + k0 + sga * 8;
            cpa16(s + TILE_B + (uint32_t)(r0a * RS + sga * 8) * 2, BHp + so);
        }
        CP_COMMIT();
    };

    float acc[2][2][4] = {};

    issue(0, 0);
    for (int ch = 0; ch < 32; ch++) {
        int st = ch & 1;
        if (ch + 1 < 32) { issue(ch + 1, st ^ 1); CP_WAIT1(); }
        else             { CP_WAIT0(); }
        __syncthreads();

        uint32_t sA = sb + st * G3_STG;
        uint32_t sB = sA + TILE_B;

#pragma unroll
        for (int kk = 0; kk < 32; kk += 16) {
            uint32_t ah[2][4];
#pragma unroll
            for (int i = 0; i < 2; i++)
                ldsm4(ah[i], sA + 2u * ((wm * 32 + i * 16) * RS + kk + la));
            uint32_t bg[4];
            ldsm4(bg, sB + 2u * ((wn * 16) * RS + kk + lb));
#pragma unroll
            for (int i = 0; i < 2; i++)
#pragma unroll
                for (int j = 0; j < 2; j++)
                    mma16816(acc[i][j], ah[i], &bg[j * 2]);
        }
        __syncthreads();
    }

#pragma unroll
    for (int i = 0; i < 2; i++) {
#pragma unroll
        for (int half = 0; half < 2; half++) {
            int rr = row0 + wm * 32 + i * 16 + qr + half * 8;
            size_t ro = (size_t)rr * H_DIM + j0 + wn * 16;
#pragma unroll
            for (int j = 0; j < 2; j++) {
                float2 v;
                v.x = acc[i][j][half * 2 + 0];
                v.y = acc[i][j][half * 2 + 1];
                *(float2*)(out + ro + j * 8 + qc * 2) = v;
            }
        }
    }
}

// ---------------- launch -----------------------------------------------------
extern "C" void kernel_launch(void* const* d_in, const int* in_sizes, int n_in,
                              void* d_out, int out_size) {
    const float* X  = (const float*)d_in[0];
    const float* Wr = (const float*)d_in[1];
    const float* Wg = (const float*)d_in[2];
    const float* Wu = (const float*)d_in[3];
    const float* Wd = (const float*)d_in[4];
    const float* Wc = (const float*)d_in[5];
    float* out = (float*)d_out;
    float* logits = out + (size_t)T_TOK * H_DIM;

    // Resolve REAL device addresses (symbol-as-arg = host shadow addr = silent
    // ATS write to host memory on GB300; the R4/R9 bug).
    void *pG, *pU, *pD, *pC;
    cudaGetSymbolAddress(&pG, g_WgT);
    cudaGetSymbolAddress(&pU, g_WuT);
    cudaGetSymbolAddress(&pD, g_WdT);
    cudaGetSymbolAddress(&pC, g_WcT);

    cudaFuncSetAttribute(gemm1_kernel, cudaFuncAttributeMaxDynamicSharedMemorySize, G1_SMEM);
    cudaFuncSetAttribute(gemm2_kernel, cudaFuncAttributeMaxDynamicSharedMemorySize, G2_SMEM);
    cudaFuncSetAttribute(gemm3_kernel, cudaFuncAttributeMaxDynamicSharedMemorySize, G3_SMEM);

    static cudaStream_t s2 = nullptr;
    static cudaEvent_t evA = nullptr, evB = nullptr;
    if (!s2) {
        cudaStreamCreateWithFlags(&s2, cudaStreamNonBlocking);
        cudaEventCreateWithFlags(&evA, cudaEventDisableTiming);
        cudaEventCreateWithFlags(&evB, cudaEventDisableTiming);
    }

    // fork: weight transposes concurrent with router chain
    cudaEventRecord(evA, 0);
    cudaStreamWaitEvent(s2, evA, 0);
    tsplit_all<<<NG + NU + ND + NC, dim3(32, 8), 0, s2>>>(
        Wg, Wu, Wd, Wc, (__half*)pG, (__half*)pU, (__half*)pD, (__half*)pC);
    cudaEventRecord(evB, s2);

    init_kernel<<<1, 32>>>();
    router_fused<<<T_TOK / 8, 256>>>(X, Wr, logits);

    cudaStreamWaitEvent(0, evB, 0);

    gemm1_kernel<<<dim3(I_DIM / 64, CAP / 64, E_NUM), 256, G1_SMEM>>>();
    gemm2_kernel<<<dim3(O_DIM / 64, CAP / 64, E_NUM), 256, G2_SMEM>>>();

    combine_kernel<<<T_TOK, 256>>>();
    gemm3_kernel<<<dim3(H_DIM / 64, T_TOK / 64), 256, G3_SMEM>>>(out);
}